// round 7
// baseline (speedup 1.0000x reference)
#include <cuda_runtime.h>
#include <cuda_bf16.h>
#include <math.h>
#include <stdint.h>

#define BB 2
#define SS 2048
#define DIN 4096
#define NH 32
#define NKV 8
#define HD 64
#define QDIM 2048
#define KVDIM 512
#define QKVN 3072
#define DOUT 2048
#define MTOT 4096

// ---------------- scratch (__device__ globals) ------------------------------
__device__ __nv_bfloat16 g_hs_hi[MTOT*DIN];
__device__ __nv_bfloat16 g_hs_lo[MTOT*DIN];
__device__ __nv_bfloat16 g_qh[MTOT*QDIM];
__device__ __nv_bfloat16 g_ql[MTOT*QDIM];
__device__ __nv_bfloat16 g_kh[MTOT*KVDIM];
__device__ __nv_bfloat16 g_kl[MTOT*KVDIM];
__device__ __nv_bfloat16 g_vh[MTOT*KVDIM];
__device__ __nv_bfloat16 g_vl[MTOT*KVDIM];
__device__ __nv_bfloat16 g_aoh[MTOT*QDIM];
__device__ __nv_bfloat16 g_aol[MTOT*QDIM];
__device__ __nv_bfloat16 g_wqkvT_hi[QKVN*DIN];
__device__ __nv_bfloat16 g_wqkvT_lo[QKVN*DIN];
__device__ __nv_bfloat16 g_woT_hi[DOUT*QDIM];
__device__ __nv_bfloat16 g_woT_lo[DOUT*QDIM];

// ---------------- helpers ----------------------------------------------------
__device__ __forceinline__ uint32_t smem_u32(const void* p) {
    uint32_t a;
    asm("{ .reg .u64 t; cvta.to.shared.u64 t, %1; cvt.u32.u64 %0, t; }" : "=r"(a) : "l"(p));
    return a;
}

#define LDSM4(r, addr)                                                           \
    asm volatile("ldmatrix.sync.aligned.m8n8.x4.shared.b16 {%0,%1,%2,%3}, [%4];" \
        : "=r"((r)[0]), "=r"((r)[1]), "=r"((r)[2]), "=r"((r)[3]) : "r"(addr))

#define LDSM4T(r, addr)                                                          \
    asm volatile("ldmatrix.sync.aligned.m8n8.x4.trans.shared.b16 {%0,%1,%2,%3}, [%4];" \
        : "=r"((r)[0]), "=r"((r)[1]), "=r"((r)[2]), "=r"((r)[3]) : "r"(addr))

#define MMA_BF16(d, a, b0, b1)                                                   \
    asm volatile("mma.sync.aligned.m16n8k16.row.col.f32.bf16.bf16.f32 "          \
        "{%0,%1,%2,%3}, {%4,%5,%6,%7}, {%8,%9}, {%0,%1,%2,%3};"                  \
        : "+f"((d)[0]), "+f"((d)[1]), "+f"((d)[2]), "+f"((d)[3])                 \
        : "r"((a)[0]), "r"((a)[1]), "r"((a)[2]), "r"((a)[3]), "r"(b0), "r"(b1))

#define CP_ASYNC16(dst, src)                                                     \
    asm volatile("cp.async.cg.shared.global [%0], [%1], 16;" :: "r"(dst), "l"(src) : "memory")
#define CP_COMMIT()  asm volatile("cp.async.commit_group;" ::: "memory")
#define CP_WAIT1()   asm volatile("cp.async.wait_group 1;" ::: "memory")
#define CP_WAIT0()   asm volatile("cp.async.wait_group 0;" ::: "memory")

__device__ __forceinline__ uint32_t pack_bf16(float lo, float hi) {
    uint32_t r;
    asm("cvt.rn.bf16x2.f32 %0, %1, %2;" : "=r"(r) : "f"(hi), "f"(lo));
    return r;
}
__device__ __forceinline__ float bfr(float x) {
    return __bfloat162float(__float2bfloat16(x));
}

__device__ __forceinline__ float fast_exp(float x) {
    float t = fmaxf(x * 1.4426950408889634f, -126.0f);
    float fi = floorf(t);
    float f = t - fi;
    float p = 1.54035304e-4f;
    p = fmaf(p, f, 1.33335581e-3f);
    p = fmaf(p, f, 9.61812911e-3f);
    p = fmaf(p, f, 5.55041087e-2f);
    p = fmaf(p, f, 2.40226507e-1f);
    p = fmaf(p, f, 6.93147181e-1f);
    p = fmaf(p, f, 1.0f);
    return p * __uint_as_float(((uint32_t)((int)fi + 127)) << 23);
}

// ---------------- prep kernels ------------------------------------------------
__global__ void split_kernel(const float* __restrict__ x, __nv_bfloat16* __restrict__ hi,
                             __nv_bfloat16* __restrict__ lo, int n4) {
    int i = blockIdx.x * blockDim.x + threadIdx.x;
    if (i >= n4) return;
    float4 v = ((const float4*)x)[i];
    __nv_bfloat16 h[4], l[4];
    float vv[4] = {v.x, v.y, v.z, v.w};
    #pragma unroll
    for (int j = 0; j < 4; j++) {
        h[j] = __float2bfloat16(vv[j]);
        l[j] = __float2bfloat16(vv[j] - __bfloat162float(h[j]));
    }
    ((uint2*)hi)[i] = *(uint2*)h;
    ((uint2*)lo)[i] = *(uint2*)l;
}

__global__ void transpose_split_qkv(const float* __restrict__ Wq, const float* __restrict__ Wk,
                                    const float* __restrict__ Wv,
                                    __nv_bfloat16* __restrict__ Th, __nv_bfloat16* __restrict__ Tl) {
    __shared__ float t[32][33];
    int n0 = blockIdx.x * 32;
    int k0 = blockIdx.y * 32;
    const float* W; int srcN, sn0;
    if (n0 < QDIM)              { W = Wq; srcN = QDIM;  sn0 = n0; }
    else if (n0 < QDIM + KVDIM) { W = Wk; srcN = KVDIM; sn0 = n0 - QDIM; }
    else                        { W = Wv; srcN = KVDIM; sn0 = n0 - QDIM - KVDIM; }
    int x = threadIdx.x, y = threadIdx.y;
    #pragma unroll
    for (int i = 0; i < 32; i += 8)
        t[y + i][x] = W[(size_t)(k0 + y + i) * srcN + sn0 + x];
    __syncthreads();
    #pragma unroll
    for (int i = 0; i < 32; i += 8) {
        float v = t[x][y + i];
        float h = bfr(v);
        size_t idx = (size_t)(n0 + y + i) * DIN + k0 + x;
        Th[idx] = __float2bfloat16(h);
        Tl[idx] = __float2bfloat16(v - h);
    }
}

__global__ void transpose_split_kernel(const float* __restrict__ W,
                                       __nv_bfloat16* __restrict__ Th,
                                       __nv_bfloat16* __restrict__ Tl, int K, int N) {
    __shared__ float t[32][33];
    int k0 = blockIdx.y * 32, n0 = blockIdx.x * 32;
    int x = threadIdx.x, y = threadIdx.y;
    #pragma unroll
    for (int i = 0; i < 32; i += 8)
        t[y + i][x] = W[(size_t)(k0 + y + i) * N + n0 + x];
    __syncthreads();
    #pragma unroll
    for (int i = 0; i < 32; i += 8) {
        float v = t[x][y + i];
        float h = bfr(v);
        size_t idx = (size_t)(n0 + y + i) * K + k0 + x;
        Th[idx] = __float2bfloat16(h);
        Tl[idx] = __float2bfloat16(v - h);
    }
}

// ---------------- split-bf16 HMMA GEMM core (512 threads, 2-stage) --------------
#define AST 40
#define TILE_E (128*AST)
#define STAGE_E (4*TILE_E)
#define NSTAGE 2
#define GEMM_SMEM (NSTAGE * STAGE_E * 2)   // 163840 B

__device__ __forceinline__ void load_stage(
    uint32_t sbase_bytes, int tid, int bm, int bn, int k0, int K,
    const __nv_bfloat16* __restrict__ Ah, const __nv_bfloat16* __restrict__ Al,
    const __nv_bfloat16* __restrict__ Bh, const __nv_bfloat16* __restrict__ Bl)
{
    #pragma unroll
    for (int i = 0; i < 4; i++) {
        int cid = tid + i * 512;
        int arr = cid >> 9;
        int rem = cid & 511;
        int row = rem >> 2;
        int c16 = rem & 3;
        const __nv_bfloat16* g;
        if (arr == 0)      g = Ah + (size_t)(bm + row) * K + k0 + c16 * 8;
        else if (arr == 1) g = Al + (size_t)(bm + row) * K + k0 + c16 * 8;
        else if (arr == 2) g = Bh + (size_t)(bn + row) * K + k0 + c16 * 8;
        else               g = Bl + (size_t)(bn + row) * K + k0 + c16 * 8;
        uint32_t d = sbase_bytes + (uint32_t)(arr * TILE_E + row * AST + c16 * 8) * 2;
        CP_ASYNC16(d, g);
    }
    CP_COMMIT();
}

__device__ __forceinline__ void gemm_mainloop(
    float acc[8][4], uint32_t smb, int tid, int bm, int bn, int K,
    const __nv_bfloat16* __restrict__ Ah, const __nv_bfloat16* __restrict__ Al,
    const __nv_bfloat16* __restrict__ Bh, const __nv_bfloat16* __restrict__ Bl)
{
    const int wid = tid >> 5;
    const int lane = tid & 31;
    const int wm = (wid & 7) * 16;      // 8 warps in M
    const int wn = (wid >> 3) * 64;     // 2 warps in N
    const int nch = K >> 5;

    load_stage(smb, tid, bm, bn, 0, K, Ah, Al, Bh, Bl);

    for (int c = 0; c < nch; c++) {
        int buf = c & 1;
        if (c + 1 < nch) {
            load_stage(smb + (uint32_t)(buf ^ 1) * STAGE_E * 2, tid, bm, bn,
                       (c + 1) << 5, K, Ah, Al, Bh, Bl);
            CP_WAIT1();
        } else {
            CP_WAIT0();
        }
        __syncthreads();

        uint32_t Ab  = smb + (uint32_t)buf * STAGE_E * 2;
        uint32_t Alb = Ab + TILE_E * 2;
        uint32_t Bb  = Ab + 2 * TILE_E * 2;
        uint32_t Blb = Ab + 3 * TILE_E * 2;

        #pragma unroll
        for (int ks = 0; ks < 2; ks++) {
            uint32_t ah[4], al[4], bh[4][4], bl[4][4];
            {
                int row = wm + (lane & 15);
                int col = ks * 16 + ((lane >> 4) << 3);
                uint32_t off = (uint32_t)(row * AST + col) * 2;
                LDSM4(ah, Ab + off);
                LDSM4(al, Alb + off);
            }
            #pragma unroll
            for (int p = 0; p < 4; p++) {
                int row = wn + p * 16 + (lane & 7) + ((lane >> 4) << 3);
                int col = ks * 16 + (((lane >> 3) & 1) << 3);
                uint32_t off = (uint32_t)(row * AST + col) * 2;
                LDSM4(bh[p], Bb + off);
                LDSM4(bl[p], Blb + off);
            }
            #pragma unroll
            for (int nt = 0; nt < 8; nt++) {
                uint32_t b0h = bh[nt >> 1][(nt & 1) * 2];
                uint32_t b1h = bh[nt >> 1][(nt & 1) * 2 + 1];
                uint32_t b0l = bl[nt >> 1][(nt & 1) * 2];
                uint32_t b1l = bl[nt >> 1][(nt & 1) * 2 + 1];
                MMA_BF16(acc[nt], ah, b0h, b1h);
                MMA_BF16(acc[nt], ah, b0l, b1l);
                MMA_BF16(acc[nt], al, b0h, b1h);
            }
        }
        __syncthreads();
    }
}

// O projection: fp32 C output
__global__ __launch_bounds__(512, 1)
void hmma_gemm_c(const __nv_bfloat16* __restrict__ Ah, const __nv_bfloat16* __restrict__ Al,
                 const __nv_bfloat16* __restrict__ Bh, const __nv_bfloat16* __restrict__ Bl,
                 float* __restrict__ C, int M, int N, int K)
{
    extern __shared__ __nv_bfloat16 sm[];
    const int tid = threadIdx.x;
    const int wid = tid >> 5, lane = tid & 31;
    const int bm = blockIdx.y * 128, bn = blockIdx.x * 128;
    const int wm = (wid & 7) * 16, wn = (wid >> 3) * 64;

    float acc[8][4];
    #pragma unroll
    for (int nt = 0; nt < 8; nt++)
        #pragma unroll
        for (int j = 0; j < 4; j++) acc[nt][j] = 0.f;

    gemm_mainloop(acc, smem_u32(sm), tid, bm, bn, K, Ah, Al, Bh, Bl);

    #pragma unroll
    for (int nt = 0; nt < 8; nt++) {
        int r0  = bm + wm + (lane >> 2);
        int col = bn + wn + nt * 8 + (lane & 3) * 2;
        *(float2*)&C[(size_t)r0 * N + col] = make_float2(acc[nt][0], acc[nt][1]);
        *(float2*)&C[(size_t)(r0 + 8) * N + col] = make_float2(acc[nt][2], acc[nt][3]);
    }
}

// QKV GEMM with fused RoPE + hi/lo split epilogue
__global__ __launch_bounds__(512, 1)
void hmma_gemm_qkv(const __nv_bfloat16* __restrict__ Ah, const __nv_bfloat16* __restrict__ Al,
                   const __nv_bfloat16* __restrict__ Bh, const __nv_bfloat16* __restrict__ Bl,
                   const int* __restrict__ pos,
                   __nv_bfloat16* __restrict__ qh, __nv_bfloat16* __restrict__ ql,
                   __nv_bfloat16* __restrict__ kh, __nv_bfloat16* __restrict__ kl,
                   __nv_bfloat16* __restrict__ vh, __nv_bfloat16* __restrict__ vl)
{
    extern __shared__ __nv_bfloat16 sm[];
    const int tid = threadIdx.x;
    const int wid = tid >> 5, lane = tid & 31;
    const int bm = blockIdx.y * 128, bn = blockIdx.x * 128;
    const int wm = (wid & 7) * 16, wn = (wid >> 3) * 64;

    float acc[8][4];
    #pragma unroll
    for (int nt = 0; nt < 8; nt++)
        #pragma unroll
        for (int j = 0; j < 4; j++) acc[nt][j] = 0.f;

    gemm_mainloop(acc, smem_u32(sm), tid, bm, bn, DIN, Ah, Al, Bh, Bl);

    const int ncol0 = bn + wn;   // 64-aligned: one head per warp
    if (ncol0 >= QDIM + KVDIM) {
        int colb = ncol0 - (QDIM + KVDIM) + (lane & 3) * 2;
        #pragma unroll
        for (int nt = 0; nt < 8; nt++)
            #pragma unroll
            for (int rs = 0; rs < 2; rs++) {
                int m = bm + wm + (lane >> 2) + rs * 8;
                float v0 = acc[nt][rs * 2], v1 = acc[nt][rs * 2 + 1];
                float h0 = bfr(v0), h1 = bfr(v1);
                size_t o = (size_t)m * KVDIM + colb + nt * 8;
                *(uint32_t*)&vh[o] = pack_bf16(h0, h1);
                *(uint32_t*)&vl[o] = pack_bf16(v0 - h0, v1 - h1);
            }
    } else {
        const int isQ = ncol0 < QDIM;
        const float scale = isQ ? 0.125f : 1.0f;
        __nv_bfloat16* oh = isQ ? qh : kh;
        __nv_bfloat16* ol = isQ ? ql : kl;
        const int stride = isQ ? QDIM : KVDIM;
        const int colbase = isQ ? ncol0 : ncol0 - QDIM;
        #pragma unroll
        for (int rs = 0; rs < 2; rs++) {
            int m = bm + wm + (lane >> 2) + rs * 8;
            float pf = (float)pos[m];
            #pragma unroll
            for (int nt = 0; nt < 4; nt++) {
                int jp0 = nt * 8 + (lane & 3) * 2;
                float y1[2], y2[2];
                #pragma unroll
                for (int c = 0; c < 2; c++) {
                    float inv = exp2f(-(float)(jp0 + c) * (13.287712379549449f / 32.0f));
                    float ang = pf * inv;
                    float s, cs;
                    sincosf(ang, &s, &cs);
                    float v1 = acc[nt][rs * 2 + c];
                    float v2 = acc[nt + 4][rs * 2 + c];
                    y1[c] = (v1 * cs - v2 * s) * scale;
                    y2[c] = (v2 * cs + v1 * s) * scale;
                }
                size_t o = (size_t)m * stride + colbase + jp0;
                float h10 = bfr(y1[0]), h11 = bfr(y1[1]);
                float h20 = bfr(y2[0]), h21 = bfr(y2[1]);
                *(uint32_t*)&oh[o]      = pack_bf16(h10, h11);
                *(uint32_t*)&ol[o]      = pack_bf16(y1[0] - h10, y1[1] - h11);
                *(uint32_t*)&oh[o + 32] = pack_bf16(h20, h21);
                *(uint32_t*)&ol[o + 32] = pack_bf16(y2[0] - h20, y2[1] - h21);
            }
        }
    }
}

// ---------------- HMMA flash attention (512 threads, triple-buffered K/V) ------
#define QST 72
#define ATT_Q_E  (256*QST)
#define ATT_KV_E (64*QST)
#define ATT_KV_STAGE (4*ATT_KV_E*2)
#define ATT_QBYTES (2*ATT_Q_E*2)
#define ATT_SMEM (ATT_QBYTES + 3*ATT_KV_STAGE)   // 184320 B

__device__ __forceinline__ void attn_load_kv(
    uint32_t stage_base, int tid, int b, int kvh, int kt,
    const __nv_bfloat16* __restrict__ kh, const __nv_bfloat16* __restrict__ kl,
    const __nv_bfloat16* __restrict__ vh, const __nv_bfloat16* __restrict__ vl)
{
    #pragma unroll
    for (int it = 0; it < 4; it++) {
        int cid = tid + it * 512;
        int arr = cid >> 9;
        int rem = cid & 511;
        int row = rem >> 3;
        int c   = rem & 7;
        const __nv_bfloat16* base = (arr == 0) ? kh : (arr == 1) ? kl : (arr == 2) ? vh : vl;
        const __nv_bfloat16* src = base + (size_t)(b * SS + kt * 64 + row) * KVDIM + kvh * 64 + c * 8;
        CP_ASYNC16(stage_base + (uint32_t)arr * ATT_KV_E * 2 + (uint32_t)(row * QST + c * 8) * 2, src);
    }
    CP_COMMIT();
}

__global__ __launch_bounds__(512, 1)
void attn_hmma(const __nv_bfloat16* __restrict__ qh, const __nv_bfloat16* __restrict__ ql,
               const __nv_bfloat16* __restrict__ kh, const __nv_bfloat16* __restrict__ kl,
               const __nv_bfloat16* __restrict__ vh, const __nv_bfloat16* __restrict__ vl,
               __nv_bfloat16* __restrict__ aoh, __nv_bfloat16* __restrict__ aol)
{
    extern __shared__ __nv_bfloat16 smatt[];
    const int qt  = gridDim.x - 1 - blockIdx.x;
    const int kvh = blockIdx.y;
    const int b   = blockIdx.z;
    const int tid = threadIdx.x, wid = tid >> 5, lane = tid & 31;

    const uint32_t smb  = smem_u32(smatt);
    const uint32_t Qh_o = smb;
    const uint32_t Ql_o = smb + ATT_Q_E * 2;

    // Q tile load
    #pragma unroll
    for (int it = 0; it < 8; it++) {
        int cid = tid + it * 512;
        int arr = cid >> 11;
        int rem = cid & 2047;
        int row = rem >> 3;
        int c   = rem & 7;
        const __nv_bfloat16* src = (arr ? ql : qh)
            + (size_t)(b * SS + qt * 64 + (row & 63)) * QDIM
            + (kvh * 4 + (row >> 6)) * 64 + c * 8;
        CP_ASYNC16((arr ? Ql_o : Qh_o) + (uint32_t)(row * QST + c * 8) * 2, src);
    }
    CP_COMMIT();

    attn_load_kv(smb + ATT_QBYTES, tid, b, kvh, 0, kh, kl, vh, vl);
    if (qt >= 1)
        attn_load_kv(smb + ATT_QBYTES + ATT_KV_STAGE, tid, b, kvh, 1, kh, kl, vh, vl);

    float m_r[2], l_r[2], oacc[8][4];
    m_r[0] = -1e30f; m_r[1] = -1e30f;
    l_r[0] = 0.f;    l_r[1] = 0.f;
    #pragma unroll
    for (int nt = 0; nt < 8; nt++)
        #pragma unroll
        for (int j = 0; j < 4; j++) oacc[nt][j] = 0.f;

    const int wrow  = wid * 16;        // 16 warps x 16 rows = 256
    const int hloc  = wid >> 2;        // q head within group
    const int rtile = (wid & 3) * 16;  // token row base in 64-tile

    int st = 0;
    for (int kt = 0; kt <= qt; kt++) {
        if (kt < qt) CP_WAIT1(); else CP_WAIT0();
        __syncthreads();

        if (kt + 2 <= qt)
            attn_load_kv(smb + ATT_QBYTES + (uint32_t)((kt + 2) % 3) * ATT_KV_STAGE,
                         tid, b, kvh, kt + 2, kh, kl, vh, vl);

        const uint32_t stg  = smb + ATT_QBYTES + (uint32_t)st * ATT_KV_STAGE;
        const uint32_t Kh_o = stg;
        const uint32_t Kl_o = stg + ATT_KV_E * 2;
        const uint32_t Vh_o = stg + 2 * ATT_KV_E * 2;
        const uint32_t Vl_o = stg + 3 * ATT_KV_E * 2;

        // ---- S = Q K^T
        float sacc[8][4];
        #pragma unroll
        for (int nt = 0; nt < 8; nt++)
            #pragma unroll
            for (int j = 0; j < 4; j++) sacc[nt][j] = 0.f;

        #pragma unroll
        for (int ks = 0; ks < 4; ks++) {
            uint32_t qa_h[4], qa_l[4], kb_h[4][4], kb_l[4][4];
            {
                int row = wrow + (lane & 15);
                int col = ks * 16 + ((lane >> 4) << 3);
                uint32_t off = (uint32_t)(row * QST + col) * 2;
                LDSM4(qa_h, Qh_o + off);
                LDSM4(qa_l, Ql_o + off);
            }
            #pragma unroll
            for (int p = 0; p < 4; p++) {
                int row = p * 16 + (lane & 7) + ((lane >> 4) << 3);
                int col = ks * 16 + (((lane >> 3) & 1) << 3);
                uint32_t off = (uint32_t)(row * QST + col) * 2;
                LDSM4(kb_h[p], Kh_o + off);
                LDSM4(kb_l[p], Kl_o + off);
            }
            #pragma unroll
            for (int nt = 0; nt < 8; nt++) {
                uint32_t b0h = kb_h[nt >> 1][(nt & 1) * 2];
                uint32_t b1h = kb_h[nt >> 1][(nt & 1) * 2 + 1];
                uint32_t b0l = kb_l[nt >> 1][(nt & 1) * 2];
                uint32_t b1l = kb_l[nt >> 1][(nt & 1) * 2 + 1];
                MMA_BF16(sacc[nt], qa_h, b0h, b1h);
                MMA_BF16(sacc[nt], qa_h, b0l, b1l);
                MMA_BF16(sacc[nt], qa_l, b0h, b1h);
            }
        }

        if (kt == qt) {
            #pragma unroll
            for (int nt = 0; nt < 8; nt++)
                #pragma unroll
                for (int cc = 0; cc < 4; cc++) {
                    int rloc = rtile + (lane >> 2) + ((cc >= 2) ? 8 : 0);
                    int cloc = nt * 8 + (lane & 3) * 2 + (cc & 1);
                    if (cloc > rloc) sacc[nt][cc] = -1e30f;
                }
        }

        // ---- online softmax
        {
            float mx0 = -1e30f, mx1 = -1e30f;
            #pragma unroll
            for (int nt = 0; nt < 8; nt++) {
                mx0 = fmaxf(mx0, fmaxf(sacc[nt][0], sacc[nt][1]));
                mx1 = fmaxf(mx1, fmaxf(sacc[nt][2], sacc[nt][3]));
            }
            mx0 = fmaxf(mx0, __shfl_xor_sync(0xffffffffu, mx0, 1));
            mx0 = fmaxf(mx0, __shfl_xor_sync(0xffffffffu, mx0, 2));
            mx1 = fmaxf(mx1, __shfl_xor_sync(0xffffffffu, mx1, 1));
            mx1 = fmaxf(mx1, __shfl_xor_sync(0xffffffffu, mx1, 2));
            float mn0 = fmaxf(m_r[0], mx0);
            float mn1 = fmaxf(m_r[1], mx1);
            float sc0 = fast_exp(m_r[0] - mn0);
            float sc1 = fast_exp(m_r[1] - mn1);
            m_r[0] = mn0; m_r[1] = mn1;
            float sum0 = 0.f, sum1 = 0.f;
            #pragma unroll
            for (int nt = 0; nt < 8; nt++) {
                float p0 = fast_exp(sacc[nt][0] - mn0);
                float p1 = fast_exp(sacc[nt][1] - mn0);
                float p2 = fast_exp(sacc[nt][2] - mn1);
                float p3 = fast_exp(sacc[nt][3] - mn1);
                sacc[nt][0] = p0; sacc[nt][1] = p1;
                sacc[nt][2] = p2; sacc[nt][3] = p3;
                sum0 += p0 + p1; sum1 += p2 + p3;
                oacc[nt][0] *= sc0; oacc[nt][1] *= sc0;
                oacc[nt][2] *= sc1; oacc[nt][3] *= sc1;
            }
            l_r[0] = l_r[0] * sc0 + sum0;
            l_r[1] = l_r[1] * sc1 + sum1;
        }

        // ---- O += P V
        #pragma unroll
        for (int j = 0; j < 4; j++) {
            uint32_t vb_h[4][4], vb_l[4][4];
            int tok_off = (lane & 7) + (((lane >> 3) & 1) << 3);
            int d_off   = ((lane >> 4) & 1) << 3;
            #pragma unroll
            for (int p = 0; p < 4; p++) {
                uint32_t off = (uint32_t)((j * 16 + tok_off) * QST + p * 16 + d_off) * 2;
                LDSM4T(vb_h[p], Vh_o + off);
                LDSM4T(vb_l[p], Vl_o + off);
            }
            uint32_t ah[4], al[4];
            #pragma unroll
            for (int q = 0; q < 4; q++) {
                int nt = 2 * j + (q >> 1);
                float v0 = sacc[nt][(q & 1) * 2];
                float v1 = sacc[nt][(q & 1) * 2 + 1];
                uint32_t ph = pack_bf16(v0, v1);
                float r0 = v0 - __uint_as_float(ph << 16);
                float r1 = v1 - __uint_as_float(ph & 0xFFFF0000u);
                ah[q] = ph;
                al[q] = pack_bf16(r0, r1);
            }
            #pragma unroll
            for (int nt = 0; nt < 8; nt++) {
                uint32_t b0h = vb_h[nt >> 1][(nt & 1) * 2];
                uint32_t b1h = vb_h[nt >> 1][(nt & 1) * 2 + 1];
                uint32_t b0l = vb_l[nt >> 1][(nt & 1) * 2];
                uint32_t b1l = vb_l[nt >> 1][(nt & 1) * 2 + 1];
                MMA_BF16(oacc[nt], ah, b0h, b1h);
                MMA_BF16(oacc[nt], ah, b0l, b1l);
                MMA_BF16(oacc[nt], al, b0h, b1h);
            }
        }
        st = (st == 2) ? 0 : st + 1;
    }

    // ---- epilogue
    l_r[0] += __shfl_xor_sync(0xffffffffu, l_r[0], 1);
    l_r[0] += __shfl_xor_sync(0xffffffffu, l_r[0], 2);
    l_r[1] += __shfl_xor_sync(0xffffffffu, l_r[1], 1);
    l_r[1] += __shfl_xor_sync(0xffffffffu, l_r[1], 2);
    float inv0 = 1.0f / l_r[0];
    float inv1 = 1.0f / l_r[1];
    int tok = qt * 64 + rtile + (lane >> 2);
    int colb = (kvh * 4 + hloc) * 64 + (lane & 3) * 2;
    #pragma unroll
    for (int nt = 0; nt < 8; nt++) {
        size_t o0 = (size_t)(b * SS + tok) * QDIM + colb + nt * 8;
        size_t o1 = o0 + (size_t)8 * QDIM;
        float v0 = oacc[nt][0] * inv0, v1 = oacc[nt][1] * inv0;
        float v2 = oacc[nt][2] * inv1, v3 = oacc[nt][3] * inv1;
        uint32_t h01 = pack_bf16(v0, v1);
        uint32_t h23 = pack_bf16(v2, v3);
        *(uint32_t*)&aoh[o0] = h01;
        *(uint32_t*)&aoh[o1] = h23;
        float r0 = v0 - __uint_as_float(h01 << 16);
        float r1 = v1 - __uint_as_float(h01 & 0xFFFF0000u);
        float r2 = v2 - __uint_as_float(h23 << 16);
        float r3 = v3 - __uint_as_float(h23 & 0xFFFF0000u);
        *(uint32_t*)&aol[o0] = pack_bf16(r0, r1);
        *(uint32_t*)&aol[o1] = pack_bf16(r2, r3);
    }
}

// ---------------------------------------------------------------------------
extern "C" void kernel_launch(void* const* d_in, const int* in_sizes, int n_in,
                              void* d_out, int out_size)
{
    (void)in_sizes; (void)n_in; (void)out_size;
    const float* hs  = (const float*)d_in[0];
    const int*   pos = (const int*)d_in[2];
    const float* Wq  = (const float*)d_in[3];
    const float* Wk  = (const float*)d_in[4];
    const float* Wv  = (const float*)d_in[5];
    const float* Wo  = (const float*)d_in[6];
    float* out = (float*)d_out;

    __nv_bfloat16 *hsh, *hsl, *qh, *ql, *kh, *kl, *vh, *vl, *aoh, *aol;
    __nv_bfloat16 *wh, *wl, *woh, *wol;
    cudaGetSymbolAddress((void**)&hsh, g_hs_hi);
    cudaGetSymbolAddress((void**)&hsl, g_hs_lo);
    cudaGetSymbolAddress((void**)&qh, g_qh);
    cudaGetSymbolAddress((void**)&ql, g_ql);
    cudaGetSymbolAddress((void**)&kh, g_kh);
    cudaGetSymbolAddress((void**)&kl, g_kl);
    cudaGetSymbolAddress((void**)&vh, g_vh);
    cudaGetSymbolAddress((void**)&vl, g_vl);
    cudaGetSymbolAddress((void**)&aoh, g_aoh);
    cudaGetSymbolAddress((void**)&aol, g_aol);
    cudaGetSymbolAddress((void**)&wh, g_wqkvT_hi);
    cudaGetSymbolAddress((void**)&wl, g_wqkvT_lo);
    cudaGetSymbolAddress((void**)&woh, g_woT_hi);
    cudaGetSymbolAddress((void**)&wol, g_woT_lo);

    const int M = MTOT;
    cudaFuncSetAttribute(hmma_gemm_c,   cudaFuncAttributeMaxDynamicSharedMemorySize, GEMM_SMEM);
    cudaFuncSetAttribute(hmma_gemm_qkv, cudaFuncAttributeMaxDynamicSharedMemorySize, GEMM_SMEM);
    cudaFuncSetAttribute(attn_hmma,     cudaFuncAttributeMaxDynamicSharedMemorySize, ATT_SMEM);

    split_kernel<<<(M * DIN / 4 + 255) / 256, 256>>>(hs, hsh, hsl, M * DIN / 4);
    transpose_split_qkv<<<dim3(QKVN / 32, DIN / 32), dim3(32, 8)>>>(Wq, Wk, Wv, wh, wl);
    transpose_split_kernel<<<dim3(DOUT / 32, QDIM / 32), dim3(32, 8)>>>(Wo, woh, wol, QDIM, DOUT);
    hmma_gemm_qkv<<<dim3(QKVN / 128, M / 128), 512, GEMM_SMEM>>>(
        hsh, hsl, wh, wl, pos, qh, ql, kh, kl, vh, vl);
    attn_hmma<<<dim3(SS / 64, NKV, BB), 512, ATT_SMEM>>>(qh, ql, kh, kl, vh, vl, aoh, aol);
    hmma_gemm_c<<<dim3(DOUT / 128, M / 128), 512, GEMM_SMEM>>>(aoh, aol, woh, wol, out, M, DOUT, QDIM);
}

// round 8
// speedup vs baseline: 1.4262x; 1.4262x over previous
#include <cuda_runtime.h>
#include <cuda_fp16.h>
#include <math.h>
#include <stdint.h>

#define BB 2
#define SS 2048
#define DIN 4096
#define NH 32
#define NKV 8
#define HD 64
#define QDIM 2048
#define KVDIM 512
#define QKVN 3072
#define DOUT 2048
#define MTOT 4096

// ---------------- scratch (__device__ globals) ------------------------------
__device__ __half g_hs[MTOT*DIN];            // hidden states, fp16 single
__device__ __half g_qh[MTOT*QDIM];           // roped, pre-scaled Q hi/lo (fp16 pair)
__device__ __half g_ql[MTOT*QDIM];
__device__ __half g_kh[MTOT*KVDIM];          // roped K hi/lo
__device__ __half g_kl[MTOT*KVDIM];
__device__ __half g_vh[MTOT*KVDIM];          // V hi/lo
__device__ __half g_vl[MTOT*KVDIM];
__device__ __half g_ao[MTOT*QDIM];           // attention out, fp16 single
__device__ __half g_wqkvT_hi[QKVN*DIN];      // weights fp16 hi/lo pairs
__device__ __half g_wqkvT_lo[QKVN*DIN];
__device__ __half g_woT_hi[DOUT*QDIM];
__device__ __half g_woT_lo[DOUT*QDIM];

// ---------------- helpers ----------------------------------------------------
__device__ __forceinline__ uint32_t smem_u32(const void* p) {
    uint32_t a;
    asm("{ .reg .u64 t; cvta.to.shared.u64 t, %1; cvt.u32.u64 %0, t; }" : "=r"(a) : "l"(p));
    return a;
}

#define LDSM4(r, addr)                                                           \
    asm volatile("ldmatrix.sync.aligned.m8n8.x4.shared.b16 {%0,%1,%2,%3}, [%4];" \
        : "=r"((r)[0]), "=r"((r)[1]), "=r"((r)[2]), "=r"((r)[3]) : "r"(addr))

#define LDSM4T(r, addr)                                                          \
    asm volatile("ldmatrix.sync.aligned.m8n8.x4.trans.shared.b16 {%0,%1,%2,%3}, [%4];" \
        : "=r"((r)[0]), "=r"((r)[1]), "=r"((r)[2]), "=r"((r)[3]) : "r"(addr))

#define MMA_F16(d, a, b0, b1)                                                    \
    asm volatile("mma.sync.aligned.m16n8k16.row.col.f32.f16.f16.f32 "            \
        "{%0,%1,%2,%3}, {%4,%5,%6,%7}, {%8,%9}, {%0,%1,%2,%3};"                  \
        : "+f"((d)[0]), "+f"((d)[1]), "+f"((d)[2]), "+f"((d)[3])                 \
        : "r"((a)[0]), "r"((a)[1]), "r"((a)[2]), "r"((a)[3]), "r"(b0), "r"(b1))

#define CP_ASYNC16(dst, src)                                                     \
    asm volatile("cp.async.cg.shared.global [%0], [%1], 16;" :: "r"(dst), "l"(src) : "memory")
#define CP_COMMIT()  asm volatile("cp.async.commit_group;" ::: "memory")
#define CP_WAIT1()   asm volatile("cp.async.wait_group 1;" ::: "memory")
#define CP_WAIT0()   asm volatile("cp.async.wait_group 0;" ::: "memory")

// pack two fp32 -> f16x2 (first arg -> low half)
__device__ __forceinline__ uint32_t pack_f16(float lo, float hi) {
    uint32_t r;
    asm("cvt.rn.f16x2.f32 %0, %1, %2;" : "=r"(r) : "f"(hi), "f"(lo));
    return r;
}
__device__ __forceinline__ float hfr(float x) {
    return __half2float(__float2half_rn(x));
}

__device__ __forceinline__ float fast_exp(float x) {
    float t = fmaxf(x * 1.4426950408889634f, -126.0f);
    float fi = floorf(t);
    float f = t - fi;
    float p = 1.54035304e-4f;
    p = fmaf(p, f, 1.33335581e-3f);
    p = fmaf(p, f, 9.61812911e-3f);
    p = fmaf(p, f, 5.55041087e-2f);
    p = fmaf(p, f, 2.40226507e-1f);
    p = fmaf(p, f, 6.93147181e-1f);
    p = fmaf(p, f, 1.0f);
    return p * __uint_as_float(((uint32_t)((int)fi + 127)) << 23);
}

// ---------------- prep kernels ------------------------------------------------
__global__ void split16_kernel(const float* __restrict__ x, __half* __restrict__ h, int n4) {
    int i = blockIdx.x * blockDim.x + threadIdx.x;
    if (i >= n4) return;
    float4 v = ((const float4*)x)[i];
    __half hh[4];
    hh[0] = __float2half_rn(v.x); hh[1] = __float2half_rn(v.y);
    hh[2] = __float2half_rn(v.z); hh[3] = __float2half_rn(v.w);
    ((uint2*)h)[i] = *(uint2*)hh;
}

__global__ void transpose_split_qkv(const float* __restrict__ Wq, const float* __restrict__ Wk,
                                    const float* __restrict__ Wv,
                                    __half* __restrict__ Th, __half* __restrict__ Tl) {
    __shared__ float t[32][33];
    int n0 = blockIdx.x * 32;
    int k0 = blockIdx.y * 32;
    const float* W; int srcN, sn0;
    if (n0 < QDIM)              { W = Wq; srcN = QDIM;  sn0 = n0; }
    else if (n0 < QDIM + KVDIM) { W = Wk; srcN = KVDIM; sn0 = n0 - QDIM; }
    else                        { W = Wv; srcN = KVDIM; sn0 = n0 - QDIM - KVDIM; }
    int x = threadIdx.x, y = threadIdx.y;
    #pragma unroll
    for (int i = 0; i < 32; i += 8)
        t[y + i][x] = W[(size_t)(k0 + y + i) * srcN + sn0 + x];
    __syncthreads();
    #pragma unroll
    for (int i = 0; i < 32; i += 8) {
        float v = t[x][y + i];
        float h = hfr(v);
        size_t idx = (size_t)(n0 + y + i) * DIN + k0 + x;
        Th[idx] = __float2half_rn(h);
        Tl[idx] = __float2half_rn(v - h);
    }
}

__global__ void transpose_split_kernel(const float* __restrict__ W,
                                       __half* __restrict__ Th,
                                       __half* __restrict__ Tl, int K, int N) {
    __shared__ float t[32][33];
    int k0 = blockIdx.y * 32, n0 = blockIdx.x * 32;
    int x = threadIdx.x, y = threadIdx.y;
    #pragma unroll
    for (int i = 0; i < 32; i += 8)
        t[y + i][x] = W[(size_t)(k0 + y + i) * N + n0 + x];
    __syncthreads();
    #pragma unroll
    for (int i = 0; i < 32; i += 8) {
        float v = t[x][y + i];
        float h = hfr(v);
        size_t idx = (size_t)(n0 + y + i) * K + k0 + x;
        Th[idx] = __float2half_rn(h);
        Tl[idx] = __float2half_rn(v - h);
    }
}

// ---------------- 2-term fp16 HMMA GEMM core (A single, B hi/lo; 3-stage) ------
#define AST 40
#define TILE_E (128*AST)          // 5120 halfs = 10240 B
#define STAGE_E (3*TILE_E)        // A | Bh | Bl
#define NSTAGE 3
#define GEMM_SMEM (NSTAGE * STAGE_E * 2)   // 92160 B

__device__ __forceinline__ void load_stage(
    uint32_t sbase_bytes, int tid, int bm, int bn, int k0, int K,
    const __half* __restrict__ A,
    const __half* __restrict__ Bh, const __half* __restrict__ Bl)
{
    #pragma unroll
    for (int i = 0; i < 6; i++) {
        int cid = tid + i * 256;       // 0..1535
        int arr = cid >> 9;            // 0:A 1:Bh 2:Bl
        int rem = cid & 511;
        int row = rem >> 2;
        int c16 = rem & 3;
        const __half* g;
        if (arr == 0)      g = A  + (size_t)(bm + row) * K + k0 + c16 * 8;
        else if (arr == 1) g = Bh + (size_t)(bn + row) * K + k0 + c16 * 8;
        else               g = Bl + (size_t)(bn + row) * K + k0 + c16 * 8;
        uint32_t d = sbase_bytes + (uint32_t)(arr * TILE_E + row * AST + c16 * 8) * 2;
        CP_ASYNC16(d, g);
    }
    CP_COMMIT();
}

__device__ __forceinline__ void gemm_mainloop(
    float acc[2][8][4], uint32_t smb, int tid, int bm, int bn, int K,
    const __half* __restrict__ A,
    const __half* __restrict__ Bh, const __half* __restrict__ Bl)
{
    const int wid = tid >> 5;
    const int lane = tid & 31;
    const int wm = (wid & 3) * 32;
    const int wn = (wid >> 2) * 64;
    const int nch = K >> 5;

    load_stage(smb, tid, bm, bn, 0, K, A, Bh, Bl);
    load_stage(smb + STAGE_E * 2, tid, bm, bn, 32, K, A, Bh, Bl);

    int st = 0, pst = 2;
    for (int c = 0; c < nch; c++) {
        CP_WAIT1();
        __syncthreads();

        if (c + 2 < nch)
            load_stage(smb + (uint32_t)pst * STAGE_E * 2, tid, bm, bn,
                       (c + 2) << 5, K, A, Bh, Bl);

        uint32_t Ab  = smb + (uint32_t)st * STAGE_E * 2;
        uint32_t Bb  = Ab + TILE_E * 2;
        uint32_t Blb = Ab + 2 * TILE_E * 2;

        #pragma unroll
        for (int ks = 0; ks < 2; ks++) {
            uint32_t ah[2][4], bh[4][4], bl[4][4];
            #pragma unroll
            for (int mt = 0; mt < 2; mt++) {
                int row = wm + mt * 16 + (lane & 15);
                int col = ks * 16 + ((lane >> 4) << 3);
                LDSM4(ah[mt], Ab + (uint32_t)(row * AST + col) * 2);
            }
            #pragma unroll
            for (int p = 0; p < 4; p++) {
                int row = wn + p * 16 + (lane & 7) + ((lane >> 4) << 3);
                int col = ks * 16 + (((lane >> 3) & 1) << 3);
                uint32_t off = (uint32_t)(row * AST + col) * 2;
                LDSM4(bh[p], Bb + off);
                LDSM4(bl[p], Blb + off);
            }
            #pragma unroll
            for (int mt = 0; mt < 2; mt++) {
                #pragma unroll
                for (int nt = 0; nt < 8; nt++) {
                    uint32_t b0h = bh[nt >> 1][(nt & 1) * 2];
                    uint32_t b1h = bh[nt >> 1][(nt & 1) * 2 + 1];
                    uint32_t b0l = bl[nt >> 1][(nt & 1) * 2];
                    uint32_t b1l = bl[nt >> 1][(nt & 1) * 2 + 1];
                    MMA_F16(acc[mt][nt], ah[mt], b0h, b1h);
                    MMA_F16(acc[mt][nt], ah[mt], b0l, b1l);
                }
            }
        }
        st = (st == 2) ? 0 : st + 1;
        pst = (pst == 2) ? 0 : pst + 1;
    }
}

// O projection: fp32 C output
__global__ __launch_bounds__(256, 1)
void hmma_gemm_c(const __half* __restrict__ A,
                 const __half* __restrict__ Bh, const __half* __restrict__ Bl,
                 float* __restrict__ C, int M, int N, int K)
{
    extern __shared__ __half sm[];
    const int tid = threadIdx.x;
    const int wid = tid >> 5, lane = tid & 31;
    const int bm = blockIdx.y * 128, bn = blockIdx.x * 128;
    const int wm = (wid & 3) * 32, wn = (wid >> 2) * 64;

    float acc[2][8][4];
    #pragma unroll
    for (int mt = 0; mt < 2; mt++)
        #pragma unroll
        for (int nt = 0; nt < 8; nt++)
            #pragma unroll
            for (int j = 0; j < 4; j++) acc[mt][nt][j] = 0.f;

    gemm_mainloop(acc, smem_u32(sm), tid, bm, bn, K, A, Bh, Bl);

    #pragma unroll
    for (int mt = 0; mt < 2; mt++)
        #pragma unroll
        for (int nt = 0; nt < 8; nt++) {
            int r0  = bm + wm + mt * 16 + (lane >> 2);
            int col = bn + wn + nt * 8 + (lane & 3) * 2;
            *(float2*)&C[(size_t)r0 * N + col] = make_float2(acc[mt][nt][0], acc[mt][nt][1]);
            *(float2*)&C[(size_t)(r0 + 8) * N + col] = make_float2(acc[mt][nt][2], acc[mt][nt][3]);
        }
}

// QKV GEMM with fused RoPE + fp16 hi/lo split epilogue
__global__ __launch_bounds__(256, 1)
void hmma_gemm_qkv(const __half* __restrict__ A,
                   const __half* __restrict__ Bh, const __half* __restrict__ Bl,
                   const int* __restrict__ pos,
                   __half* __restrict__ qh, __half* __restrict__ ql,
                   __half* __restrict__ kh, __half* __restrict__ kl,
                   __half* __restrict__ vh, __half* __restrict__ vl)
{
    extern __shared__ __half sm[];
    const int tid = threadIdx.x;
    const int wid = tid >> 5, lane = tid & 31;
    const int bm = blockIdx.y * 128, bn = blockIdx.x * 128;
    const int wm = (wid & 3) * 32, wn = (wid >> 2) * 64;

    float acc[2][8][4];
    #pragma unroll
    for (int mt = 0; mt < 2; mt++)
        #pragma unroll
        for (int nt = 0; nt < 8; nt++)
            #pragma unroll
            for (int j = 0; j < 4; j++) acc[mt][nt][j] = 0.f;

    gemm_mainloop(acc, smem_u32(sm), tid, bm, bn, DIN, A, Bh, Bl);

    const int ncol0 = bn + wn;   // 64-aligned: one head per warp
    if (ncol0 >= QDIM + KVDIM) {
        int colb = ncol0 - (QDIM + KVDIM) + (lane & 3) * 2;
        #pragma unroll
        for (int mt = 0; mt < 2; mt++)
            #pragma unroll
            for (int nt = 0; nt < 8; nt++)
                #pragma unroll
                for (int rs = 0; rs < 2; rs++) {
                    int m = bm + wm + mt * 16 + (lane >> 2) + rs * 8;
                    float v0 = acc[mt][nt][rs * 2], v1 = acc[mt][nt][rs * 2 + 1];
                    float h0 = hfr(v0), h1 = hfr(v1);
                    size_t o = (size_t)m * KVDIM + colb + nt * 8;
                    *(uint32_t*)&vh[o] = pack_f16(h0, h1);
                    *(uint32_t*)&vl[o] = pack_f16(v0 - h0, v1 - h1);
                }
    } else {
        const int isQ = ncol0 < QDIM;
        const float scale = isQ ? 0.125f : 1.0f;
        __half* oh = isQ ? qh : kh;
        __half* ol = isQ ? ql : kl;
        const int stride = isQ ? QDIM : KVDIM;
        const int colbase = isQ ? ncol0 : ncol0 - QDIM;
        #pragma unroll
        for (int mt = 0; mt < 2; mt++)
            #pragma unroll
            for (int rs = 0; rs < 2; rs++) {
                int m = bm + wm + mt * 16 + (lane >> 2) + rs * 8;
                float pf = (float)pos[m];
                #pragma unroll
                for (int nt = 0; nt < 4; nt++) {
                    int jp0 = nt * 8 + (lane & 3) * 2;
                    float y1[2], y2[2];
                    #pragma unroll
                    for (int c = 0; c < 2; c++) {
                        float inv = exp2f(-(float)(jp0 + c) * (13.287712379549449f / 32.0f));
                        float ang = pf * inv;
                        float s, cs;
                        sincosf(ang, &s, &cs);
                        float v1 = acc[mt][nt][rs * 2 + c];
                        float v2 = acc[mt][nt + 4][rs * 2 + c];
                        y1[c] = (v1 * cs - v2 * s) * scale;
                        y2[c] = (v2 * cs + v1 * s) * scale;
                    }
                    size_t o = (size_t)m * stride + colbase + jp0;
                    float h10 = hfr(y1[0]), h11 = hfr(y1[1]);
                    float h20 = hfr(y2[0]), h21 = hfr(y2[1]);
                    *(uint32_t*)&oh[o]      = pack_f16(h10, h11);
                    *(uint32_t*)&ol[o]      = pack_f16(y1[0] - h10, y1[1] - h11);
                    *(uint32_t*)&oh[o + 32] = pack_f16(h20, h21);
                    *(uint32_t*)&ol[o + 32] = pack_f16(y2[0] - h20, y2[1] - h21);
                }
            }
    }
}

// ---------------- HMMA flash attention (fp16; QK 3-term, PV 2-term) ------------
#define QST 72
#define ATT_Q_E  (256*QST)
#define ATT_KV_E (64*QST)
#define ATT_KV_STAGE (4*ATT_KV_E*2)
#define ATT_QBYTES (2*ATT_Q_E*2)
#define ATT_SMEM (ATT_QBYTES + 3*ATT_KV_STAGE)   // 184320 B

__device__ __forceinline__ void attn_load_kv(
    uint32_t stage_base, int tid, int b, int kvh, int kt,
    const __half* __restrict__ kh, const __half* __restrict__ kl,
    const __half* __restrict__ vh, const __half* __restrict__ vl)
{
    #pragma unroll
    for (int it = 0; it < 8; it++) {
        int cid = tid + it * 256;
        int arr = cid >> 9;
        int rem = cid & 511;
        int row = rem >> 3;
        int c   = rem & 7;
        const __half* base = (arr == 0) ? kh : (arr == 1) ? kl : (arr == 2) ? vh : vl;
        const __half* src = base + (size_t)(b * SS + kt * 64 + row) * KVDIM + kvh * 64 + c * 8;
        CP_ASYNC16(stage_base + (uint32_t)arr * ATT_KV_E * 2 + (uint32_t)(row * QST + c * 8) * 2, src);
    }
    CP_COMMIT();
}

__global__ __launch_bounds__(256, 1)
void attn_hmma(const __half* __restrict__ qh, const __half* __restrict__ ql,
               const __half* __restrict__ kh, const __half* __restrict__ kl,
               const __half* __restrict__ vh, const __half* __restrict__ vl,
               __half* __restrict__ ao)
{
    extern __shared__ __half smatt[];
    const int qt  = gridDim.x - 1 - blockIdx.x;
    const int kvh = blockIdx.y;
    const int b   = blockIdx.z;
    const int tid = threadIdx.x, wid = tid >> 5, lane = tid & 31;

    const uint32_t smb  = smem_u32(smatt);
    const uint32_t Qh_o = smb;
    const uint32_t Ql_o = smb + ATT_Q_E * 2;

    // Q tile load
    #pragma unroll
    for (int it = 0; it < 16; it++) {
        int cid = tid + it * 256;
        int arr = cid >> 11;
        int rem = cid & 2047;
        int row = rem >> 3;
        int c   = rem & 7;
        const __half* src = (arr ? ql : qh)
            + (size_t)(b * SS + qt * 64 + (row & 63)) * QDIM
            + (kvh * 4 + (row >> 6)) * 64 + c * 8;
        CP_ASYNC16((arr ? Ql_o : Qh_o) + (uint32_t)(row * QST + c * 8) * 2, src);
    }
    CP_COMMIT();

    attn_load_kv(smb + ATT_QBYTES, tid, b, kvh, 0, kh, kl, vh, vl);
    if (qt >= 1)
        attn_load_kv(smb + ATT_QBYTES + ATT_KV_STAGE, tid, b, kvh, 1, kh, kl, vh, vl);

    float m_r[2][2], l_r[2][2], oacc[2][8][4];
    #pragma unroll
    for (int mt = 0; mt < 2; mt++) {
        m_r[mt][0] = -1e30f; m_r[mt][1] = -1e30f;
        l_r[mt][0] = 0.f;    l_r[mt][1] = 0.f;
        #pragma unroll
        for (int nt = 0; nt < 8; nt++)
            #pragma unroll
            for (int j = 0; j < 4; j++) oacc[mt][nt][j] = 0.f;
    }

    const int wrow  = wid * 32;
    const int hloc  = wid >> 1;
    const int rtile = (wid & 1) * 32;

    int st = 0;
    for (int kt = 0; kt <= qt; kt++) {
        if (kt < qt) CP_WAIT1(); else CP_WAIT0();
        __syncthreads();

        if (kt + 2 <= qt)
            attn_load_kv(smb + ATT_QBYTES + (uint32_t)((kt + 2) % 3) * ATT_KV_STAGE,
                         tid, b, kvh, kt + 2, kh, kl, vh, vl);

        const uint32_t stg  = smb + ATT_QBYTES + (uint32_t)st * ATT_KV_STAGE;
        const uint32_t Kh_o = stg;
        const uint32_t Kl_o = stg + ATT_KV_E * 2;
        const uint32_t Vh_o = stg + 2 * ATT_KV_E * 2;
        const uint32_t Vl_o = stg + 3 * ATT_KV_E * 2;

        // ---- S = Q K^T (3-term: qh*kh + qh*kl + ql*kh)
        float sacc[2][8][4];
        #pragma unroll
        for (int mt = 0; mt < 2; mt++)
            #pragma unroll
            for (int nt = 0; nt < 8; nt++)
                #pragma unroll
                for (int j = 0; j < 4; j++) sacc[mt][nt][j] = 0.f;

        #pragma unroll
        for (int ks = 0; ks < 4; ks++) {
            uint32_t qa_h[2][4], qa_l[2][4], kb_h[4][4], kb_l[4][4];
            #pragma unroll
            for (int mt = 0; mt < 2; mt++) {
                int row = wrow + mt * 16 + (lane & 15);
                int col = ks * 16 + ((lane >> 4) << 3);
                uint32_t off = (uint32_t)(row * QST + col) * 2;
                LDSM4(qa_h[mt], Qh_o + off);
                LDSM4(qa_l[mt], Ql_o + off);
            }
            #pragma unroll
            for (int p = 0; p < 4; p++) {
                int row = p * 16 + (lane & 7) + ((lane >> 4) << 3);
                int col = ks * 16 + (((lane >> 3) & 1) << 3);
                uint32_t off = (uint32_t)(row * QST + col) * 2;
                LDSM4(kb_h[p], Kh_o + off);
                LDSM4(kb_l[p], Kl_o + off);
            }
            #pragma unroll
            for (int mt = 0; mt < 2; mt++) {
                #pragma unroll
                for (int nt = 0; nt < 8; nt++) {
                    uint32_t b0h = kb_h[nt >> 1][(nt & 1) * 2];
                    uint32_t b1h = kb_h[nt >> 1][(nt & 1) * 2 + 1];
                    uint32_t b0l = kb_l[nt >> 1][(nt & 1) * 2];
                    uint32_t b1l = kb_l[nt >> 1][(nt & 1) * 2 + 1];
                    MMA_F16(sacc[mt][nt], qa_h[mt], b0h, b1h);
                    MMA_F16(sacc[mt][nt], qa_h[mt], b0l, b1l);
                    MMA_F16(sacc[mt][nt], qa_l[mt], b0h, b1h);
                }
            }
        }

        if (kt == qt) {
            #pragma unroll
            for (int mt = 0; mt < 2; mt++)
                #pragma unroll
                for (int nt = 0; nt < 8; nt++)
                    #pragma unroll
                    for (int cc = 0; cc < 4; cc++) {
                        int rloc = rtile + mt * 16 + (lane >> 2) + ((cc >= 2) ? 8 : 0);
                        int cloc = nt * 8 + (lane & 3) * 2 + (cc & 1);
                        if (cloc > rloc) sacc[mt][nt][cc] = -1e30f;
                    }
        }

        // ---- online softmax
        #pragma unroll
        for (int mt = 0; mt < 2; mt++) {
            float mx0 = -1e30f, mx1 = -1e30f;
            #pragma unroll
            for (int nt = 0; nt < 8; nt++) {
                mx0 = fmaxf(mx0, fmaxf(sacc[mt][nt][0], sacc[mt][nt][1]));
                mx1 = fmaxf(mx1, fmaxf(sacc[mt][nt][2], sacc[mt][nt][3]));
            }
            mx0 = fmaxf(mx0, __shfl_xor_sync(0xffffffffu, mx0, 1));
            mx0 = fmaxf(mx0, __shfl_xor_sync(0xffffffffu, mx0, 2));
            mx1 = fmaxf(mx1, __shfl_xor_sync(0xffffffffu, mx1, 1));
            mx1 = fmaxf(mx1, __shfl_xor_sync(0xffffffffu, mx1, 2));
            float mn0 = fmaxf(m_r[mt][0], mx0);
            float mn1 = fmaxf(m_r[mt][1], mx1);
            float sc0 = fast_exp(m_r[mt][0] - mn0);
            float sc1 = fast_exp(m_r[mt][1] - mn1);
            m_r[mt][0] = mn0; m_r[mt][1] = mn1;
            float sum0 = 0.f, sum1 = 0.f;
            #pragma unroll
            for (int nt = 0; nt < 8; nt++) {
                float p0 = fast_exp(sacc[mt][nt][0] - mn0);
                float p1 = fast_exp(sacc[mt][nt][1] - mn0);
                float p2 = fast_exp(sacc[mt][nt][2] - mn1);
                float p3 = fast_exp(sacc[mt][nt][3] - mn1);
                sacc[mt][nt][0] = p0; sacc[mt][nt][1] = p1;
                sacc[mt][nt][2] = p2; sacc[mt][nt][3] = p3;
                sum0 += p0 + p1; sum1 += p2 + p3;
                oacc[mt][nt][0] *= sc0; oacc[mt][nt][1] *= sc0;
                oacc[mt][nt][2] *= sc1; oacc[mt][nt][3] *= sc1;
            }
            l_r[mt][0] = l_r[mt][0] * sc0 + sum0;
            l_r[mt][1] = l_r[mt][1] * sc1 + sum1;
        }

        // ---- O += P V (2-term: P fp16-single x V hi/lo)
        #pragma unroll
        for (int j = 0; j < 4; j++) {
            uint32_t vb_h[4][4], vb_l[4][4];
            int tok_off = (lane & 7) + (((lane >> 3) & 1) << 3);
            int d_off   = ((lane >> 4) & 1) << 3;
            #pragma unroll
            for (int p = 0; p < 4; p++) {
                uint32_t off = (uint32_t)((j * 16 + tok_off) * QST + p * 16 + d_off) * 2;
                LDSM4T(vb_h[p], Vh_o + off);
                LDSM4T(vb_l[p], Vl_o + off);
            }
            #pragma unroll
            for (int mt = 0; mt < 2; mt++) {
                uint32_t ah[4];
                #pragma unroll
                for (int q = 0; q < 4; q++) {
                    int nt = 2 * j + (q >> 1);
                    ah[q] = pack_f16(sacc[mt][nt][(q & 1) * 2], sacc[mt][nt][(q & 1) * 2 + 1]);
                }
                #pragma unroll
                for (int nt = 0; nt < 8; nt++) {
                    uint32_t b0h = vb_h[nt >> 1][(nt & 1) * 2];
                    uint32_t b1h = vb_h[nt >> 1][(nt & 1) * 2 + 1];
                    uint32_t b0l = vb_l[nt >> 1][(nt & 1) * 2];
                    uint32_t b1l = vb_l[nt >> 1][(nt & 1) * 2 + 1];
                    MMA_F16(oacc[mt][nt], ah, b0h, b1h);
                    MMA_F16(oacc[mt][nt], ah, b0l, b1l);
                }
            }
        }
        st = (st == 2) ? 0 : st + 1;
    }

    // ---- epilogue: normalize + fp16 single output
    #pragma unroll
    for (int mt = 0; mt < 2; mt++) {
        l_r[mt][0] += __shfl_xor_sync(0xffffffffu, l_r[mt][0], 1);
        l_r[mt][0] += __shfl_xor_sync(0xffffffffu, l_r[mt][0], 2);
        l_r[mt][1] += __shfl_xor_sync(0xffffffffu, l_r[mt][1], 1);
        l_r[mt][1] += __shfl_xor_sync(0xffffffffu, l_r[mt][1], 2);
        float inv0 = 1.0f / l_r[mt][0];
        float inv1 = 1.0f / l_r[mt][1];
        int tok = qt * 64 + rtile + mt * 16 + (lane >> 2);
        int colb = (kvh * 4 + hloc) * 64 + (lane & 3) * 2;
        #pragma unroll
        for (int nt = 0; nt < 8; nt++) {
            size_t o0 = (size_t)(b * SS + tok) * QDIM + colb + nt * 8;
            size_t o1 = o0 + (size_t)8 * QDIM;
            *(uint32_t*)&ao[o0] = pack_f16(oacc[mt][nt][0] * inv0, oacc[mt][nt][1] * inv0);
            *(uint32_t*)&ao[o1] = pack_f16(oacc[mt][nt][2] * inv1, oacc[mt][nt][3] * inv1);
        }
    }
}

// ---------------------------------------------------------------------------
extern "C" void kernel_launch(void* const* d_in, const int* in_sizes, int n_in,
                              void* d_out, int out_size)
{
    (void)in_sizes; (void)n_in; (void)out_size;
    const float* hs  = (const float*)d_in[0];
    const int*   pos = (const int*)d_in[2];
    const float* Wq  = (const float*)d_in[3];
    const float* Wk  = (const float*)d_in[4];
    const float* Wv  = (const float*)d_in[5];
    const float* Wo  = (const float*)d_in[6];
    float* out = (float*)d_out;

    __half *hsb, *qh, *ql, *kh, *kl, *vh, *vl, *ao, *wh, *wl, *woh, *wol;
    cudaGetSymbolAddress((void**)&hsb, g_hs);
    cudaGetSymbolAddress((void**)&qh, g_qh);
    cudaGetSymbolAddress((void**)&ql, g_ql);
    cudaGetSymbolAddress((void**)&kh, g_kh);
    cudaGetSymbolAddress((void**)&kl, g_kl);
    cudaGetSymbolAddress((void**)&vh, g_vh);
    cudaGetSymbolAddress((void**)&vl, g_vl);
    cudaGetSymbolAddress((void**)&ao, g_ao);
    cudaGetSymbolAddress((void**)&wh, g_wqkvT_hi);
    cudaGetSymbolAddress((void**)&wl, g_wqkvT_lo);
    cudaGetSymbolAddress((void**)&woh, g_woT_hi);
    cudaGetSymbolAddress((void**)&wol, g_woT_lo);

    const int M = MTOT;
    cudaFuncSetAttribute(hmma_gemm_c,   cudaFuncAttributeMaxDynamicSharedMemorySize, GEMM_SMEM);
    cudaFuncSetAttribute(hmma_gemm_qkv, cudaFuncAttributeMaxDynamicSharedMemorySize, GEMM_SMEM);
    cudaFuncSetAttribute(attn_hmma,     cudaFuncAttributeMaxDynamicSharedMemorySize, ATT_SMEM);

    split16_kernel<<<(M * DIN / 4 + 255) / 256, 256>>>(hs, hsb, M * DIN / 4);                  // 1
    transpose_split_qkv<<<dim3(QKVN / 32, DIN / 32), dim3(32, 8)>>>(Wq, Wk, Wv, wh, wl);       // 2
    transpose_split_kernel<<<dim3(DOUT / 32, QDIM / 32), dim3(32, 8)>>>(Wo, woh, wol, QDIM, DOUT); // 3
    hmma_gemm_qkv<<<dim3(QKVN / 128, M / 128), 256, GEMM_SMEM>>>(
        hsb, wh, wl, pos, qh, ql, kh, kl, vh, vl);                                             // 4
    attn_hmma<<<dim3(SS / 64, NKV, BB), 256, ATT_SMEM>>>(qh, ql, kh, kl, vh, vl, ao);          // 5 (profiled)
    hmma_gemm_c<<<dim3(DOUT / 128, M / 128), 256, GEMM_SMEM>>>(ao, woh, wol, out, M, DOUT, QDIM); // 6
}

// round 9
// speedup vs baseline: 2.2982x; 1.6114x over previous
#include <cuda_runtime.h>
#include <cuda_fp16.h>
#include <math.h>
#include <stdint.h>

#define BB 2
#define SS 2048
#define DIN 4096
#define NH 32
#define NKV 8
#define HD 64
#define QDIM 2048
#define KVDIM 512
#define QKVN 3072
#define DOUT 2048
#define MTOT 4096

// ---------------- scratch (__device__ globals) ------------------------------
__device__ __half g_hs[MTOT*DIN];            // hidden states, fp16 single
__device__ __half g_qh[MTOT*QDIM];           // roped, pre-scaled Q hi/lo (fp16 pair)
__device__ __half g_ql[MTOT*QDIM];
__device__ __half g_kh[MTOT*KVDIM];          // roped K hi/lo
__device__ __half g_kl[MTOT*KVDIM];
__device__ __half g_vh[MTOT*KVDIM];          // V hi/lo
__device__ __half g_vl[MTOT*KVDIM];
__device__ __half g_ao[MTOT*QDIM];           // attention out, fp16 single
__device__ __half g_wqkvT[QKVN*DIN];         // weights fp16 single
__device__ __half g_woT[DOUT*QDIM];

// ---------------- helpers ----------------------------------------------------
__device__ __forceinline__ uint32_t smem_u32(const void* p) {
    uint32_t a;
    asm("{ .reg .u64 t; cvta.to.shared.u64 t, %1; cvt.u32.u64 %0, t; }" : "=r"(a) : "l"(p));
    return a;
}

#define LDSM4(r, addr)                                                           \
    asm volatile("ldmatrix.sync.aligned.m8n8.x4.shared.b16 {%0,%1,%2,%3}, [%4];" \
        : "=r"((r)[0]), "=r"((r)[1]), "=r"((r)[2]), "=r"((r)[3]) : "r"(addr))

#define LDSM4T(r, addr)                                                          \
    asm volatile("ldmatrix.sync.aligned.m8n8.x4.trans.shared.b16 {%0,%1,%2,%3}, [%4];" \
        : "=r"((r)[0]), "=r"((r)[1]), "=r"((r)[2]), "=r"((r)[3]) : "r"(addr))

#define MMA_F16(d, a, b0, b1)                                                    \
    asm volatile("mma.sync.aligned.m16n8k16.row.col.f32.f16.f16.f32 "            \
        "{%0,%1,%2,%3}, {%4,%5,%6,%7}, {%8,%9}, {%0,%1,%2,%3};"                  \
        : "+f"((d)[0]), "+f"((d)[1]), "+f"((d)[2]), "+f"((d)[3])                 \
        : "r"((a)[0]), "r"((a)[1]), "r"((a)[2]), "r"((a)[3]), "r"(b0), "r"(b1))

#define CP_ASYNC16(dst, src)                                                     \
    asm volatile("cp.async.cg.shared.global [%0], [%1], 16;" :: "r"(dst), "l"(src) : "memory")
#define CP_COMMIT()  asm volatile("cp.async.commit_group;" ::: "memory")
#define CP_WAIT1()   asm volatile("cp.async.wait_group 1;" ::: "memory")
#define CP_WAIT0()   asm volatile("cp.async.wait_group 0;" ::: "memory")

__device__ __forceinline__ uint32_t pack_f16(float lo, float hi) {
    uint32_t r;
    asm("cvt.rn.f16x2.f32 %0, %1, %2;" : "=r"(r) : "f"(hi), "f"(lo));
    return r;
}
__device__ __forceinline__ float hfr(float x) {
    return __half2float(__float2half_rn(x));
}

__device__ __forceinline__ float fast_exp(float x) {
    float t = fmaxf(x * 1.4426950408889634f, -126.0f);
    float fi = floorf(t);
    float f = t - fi;
    float p = 1.54035304e-4f;
    p = fmaf(p, f, 1.33335581e-3f);
    p = fmaf(p, f, 9.61812911e-3f);
    p = fmaf(p, f, 5.55041087e-2f);
    p = fmaf(p, f, 2.40226507e-1f);
    p = fmaf(p, f, 6.93147181e-1f);
    p = fmaf(p, f, 1.0f);
    return p * __uint_as_float(((uint32_t)((int)fi + 127)) << 23);
}

// ---------------- prep kernels ------------------------------------------------
__global__ void split16_kernel(const float* __restrict__ x, __half* __restrict__ h, int n4) {
    int i = blockIdx.x * blockDim.x + threadIdx.x;
    if (i >= n4) return;
    float4 v = ((const float4*)x)[i];
    __half hh[4];
    hh[0] = __float2half_rn(v.x); hh[1] = __float2half_rn(v.y);
    hh[2] = __float2half_rn(v.z); hh[3] = __float2half_rn(v.w);
    ((uint2*)h)[i] = *(uint2*)hh;
}

__global__ void transpose_qkv16(const float* __restrict__ Wq, const float* __restrict__ Wk,
                                const float* __restrict__ Wv, __half* __restrict__ T) {
    __shared__ float t[32][33];
    int n0 = blockIdx.x * 32;
    int k0 = blockIdx.y * 32;
    const float* W; int srcN, sn0;
    if (n0 < QDIM)              { W = Wq; srcN = QDIM;  sn0 = n0; }
    else if (n0 < QDIM + KVDIM) { W = Wk; srcN = KVDIM; sn0 = n0 - QDIM; }
    else                        { W = Wv; srcN = KVDIM; sn0 = n0 - QDIM - KVDIM; }
    int x = threadIdx.x, y = threadIdx.y;
    #pragma unroll
    for (int i = 0; i < 32; i += 8)
        t[y + i][x] = W[(size_t)(k0 + y + i) * srcN + sn0 + x];
    __syncthreads();
    #pragma unroll
    for (int i = 0; i < 32; i += 8)
        T[(size_t)(n0 + y + i) * DIN + k0 + x] = __float2half_rn(t[x][y + i]);
}

__global__ void transpose16(const float* __restrict__ W, __half* __restrict__ T, int K, int N) {
    __shared__ float t[32][33];
    int k0 = blockIdx.y * 32, n0 = blockIdx.x * 32;
    int x = threadIdx.x, y = threadIdx.y;
    #pragma unroll
    for (int i = 0; i < 32; i += 8)
        t[y + i][x] = W[(size_t)(k0 + y + i) * N + n0 + x];
    __syncthreads();
    #pragma unroll
    for (int i = 0; i < 32; i += 8)
        T[(size_t)(n0 + y + i) * K + k0 + x] = __float2half_rn(t[x][y + i]);
}

// ---------------- 1-term fp16 HMMA GEMM core (3-stage) --------------------------
#define AST 40
#define TILE_E (128*AST)          // 5120 halfs = 10240 B
#define STAGE_E (2*TILE_E)        // A | B
#define NSTAGE 3
#define GEMM_SMEM (NSTAGE * STAGE_E * 2)   // 61440 B

__device__ __forceinline__ void load_stage(
    uint32_t sbase_bytes, int tid, int bm, int bn, int k0, int K,
    const __half* __restrict__ A, const __half* __restrict__ B)
{
    #pragma unroll
    for (int i = 0; i < 4; i++) {
        int cid = tid + i * 256;       // 0..1023
        int arr = cid >> 9;            // 0:A 1:B
        int rem = cid & 511;
        int row = rem >> 2;
        int c16 = rem & 3;
        const __half* g = (arr == 0)
            ? A + (size_t)(bm + row) * K + k0 + c16 * 8
            : B + (size_t)(bn + row) * K + k0 + c16 * 8;
        uint32_t d = sbase_bytes + (uint32_t)(arr * TILE_E + row * AST + c16 * 8) * 2;
        CP_ASYNC16(d, g);
    }
    CP_COMMIT();
}

__device__ __forceinline__ void gemm_mainloop(
    float acc[2][8][4], uint32_t smb, int tid, int bm, int bn, int K,
    const __half* __restrict__ A, const __half* __restrict__ B)
{
    const int wid = tid >> 5;
    const int lane = tid & 31;
    const int wm = (wid & 3) * 32;
    const int wn = (wid >> 2) * 64;
    const int nch = K >> 5;

    load_stage(smb, tid, bm, bn, 0, K, A, B);
    load_stage(smb + STAGE_E * 2, tid, bm, bn, 32, K, A, B);

    int st = 0, pst = 2;
    for (int c = 0; c < nch; c++) {
        CP_WAIT1();
        __syncthreads();

        if (c + 2 < nch)
            load_stage(smb + (uint32_t)pst * STAGE_E * 2, tid, bm, bn,
                       (c + 2) << 5, K, A, B);

        uint32_t Ab = smb + (uint32_t)st * STAGE_E * 2;
        uint32_t Bb = Ab + TILE_E * 2;

        #pragma unroll
        for (int ks = 0; ks < 2; ks++) {
            uint32_t ah[2][4], bf[4][4];
            #pragma unroll
            for (int mt = 0; mt < 2; mt++) {
                int row = wm + mt * 16 + (lane & 15);
                int col = ks * 16 + ((lane >> 4) << 3);
                LDSM4(ah[mt], Ab + (uint32_t)(row * AST + col) * 2);
            }
            #pragma unroll
            for (int p = 0; p < 4; p++) {
                int row = wn + p * 16 + (lane & 7) + ((lane >> 4) << 3);
                int col = ks * 16 + (((lane >> 3) & 1) << 3);
                LDSM4(bf[p], Bb + (uint32_t)(row * AST + col) * 2);
            }
            #pragma unroll
            for (int mt = 0; mt < 2; mt++) {
                #pragma unroll
                for (int nt = 0; nt < 8; nt++) {
                    uint32_t b0 = bf[nt >> 1][(nt & 1) * 2];
                    uint32_t b1 = bf[nt >> 1][(nt & 1) * 2 + 1];
                    MMA_F16(acc[mt][nt], ah[mt], b0, b1);
                }
            }
        }
        st = (st == 2) ? 0 : st + 1;
        pst = (pst == 2) ? 0 : pst + 1;
    }
}

// O projection: fp32 C output
__global__ __launch_bounds__(256)
void hmma_gemm_c(const __half* __restrict__ A, const __half* __restrict__ B,
                 float* __restrict__ C, int M, int N, int K)
{
    extern __shared__ __half sm[];
    const int tid = threadIdx.x;
    const int wid = tid >> 5, lane = tid & 31;
    const int bm = blockIdx.y * 128, bn = blockIdx.x * 128;
    const int wm = (wid & 3) * 32, wn = (wid >> 2) * 64;

    float acc[2][8][4];
    #pragma unroll
    for (int mt = 0; mt < 2; mt++)
        #pragma unroll
        for (int nt = 0; nt < 8; nt++)
            #pragma unroll
            for (int j = 0; j < 4; j++) acc[mt][nt][j] = 0.f;

    gemm_mainloop(acc, smem_u32(sm), tid, bm, bn, K, A, B);

    #pragma unroll
    for (int mt = 0; mt < 2; mt++)
        #pragma unroll
        for (int nt = 0; nt < 8; nt++) {
            int r0  = bm + wm + mt * 16 + (lane >> 2);
            int col = bn + wn + nt * 8 + (lane & 3) * 2;
            *(float2*)&C[(size_t)r0 * N + col] = make_float2(acc[mt][nt][0], acc[mt][nt][1]);
            *(float2*)&C[(size_t)(r0 + 8) * N + col] = make_float2(acc[mt][nt][2], acc[mt][nt][3]);
        }
}

// QKV GEMM with fused RoPE + fp16 hi/lo split epilogue
__global__ __launch_bounds__(256)
void hmma_gemm_qkv(const __half* __restrict__ A, const __half* __restrict__ B,
                   const int* __restrict__ pos,
                   __half* __restrict__ qh, __half* __restrict__ ql,
                   __half* __restrict__ kh, __half* __restrict__ kl,
                   __half* __restrict__ vh, __half* __restrict__ vl)
{
    extern __shared__ __half sm[];
    const int tid = threadIdx.x;
    const int wid = tid >> 5, lane = tid & 31;
    const int bm = blockIdx.y * 128, bn = blockIdx.x * 128;
    const int wm = (wid & 3) * 32, wn = (wid >> 2) * 64;

    float acc[2][8][4];
    #pragma unroll
    for (int mt = 0; mt < 2; mt++)
        #pragma unroll
        for (int nt = 0; nt < 8; nt++)
            #pragma unroll
            for (int j = 0; j < 4; j++) acc[mt][nt][j] = 0.f;

    gemm_mainloop(acc, smem_u32(sm), tid, bm, bn, DIN, A, B);

    const int ncol0 = bn + wn;   // 64-aligned: one head per warp
    if (ncol0 >= QDIM + KVDIM) {
        int colb = ncol0 - (QDIM + KVDIM) + (lane & 3) * 2;
        #pragma unroll
        for (int mt = 0; mt < 2; mt++)
            #pragma unroll
            for (int nt = 0; nt < 8; nt++)
                #pragma unroll
                for (int rs = 0; rs < 2; rs++) {
                    int m = bm + wm + mt * 16 + (lane >> 2) + rs * 8;
                    float v0 = acc[mt][nt][rs * 2], v1 = acc[mt][nt][rs * 2 + 1];
                    float h0 = hfr(v0), h1 = hfr(v1);
                    size_t o = (size_t)m * KVDIM + colb + nt * 8;
                    *(uint32_t*)&vh[o] = pack_f16(h0, h1);
                    *(uint32_t*)&vl[o] = pack_f16(v0 - h0, v1 - h1);
                }
    } else {
        const int isQ = ncol0 < QDIM;
        const float scale = isQ ? 0.125f : 1.0f;
        __half* oh = isQ ? qh : kh;
        __half* ol = isQ ? ql : kl;
        const int stride = isQ ? QDIM : KVDIM;
        const int colbase = isQ ? ncol0 : ncol0 - QDIM;
        #pragma unroll
        for (int mt = 0; mt < 2; mt++)
            #pragma unroll
            for (int rs = 0; rs < 2; rs++) {
                int m = bm + wm + mt * 16 + (lane >> 2) + rs * 8;
                float pf = (float)pos[m];
                #pragma unroll
                for (int nt = 0; nt < 4; nt++) {
                    int jp0 = nt * 8 + (lane & 3) * 2;
                    float y1[2], y2[2];
                    #pragma unroll
                    for (int c = 0; c < 2; c++) {
                        float inv = exp2f(-(float)(jp0 + c) * (13.287712379549449f / 32.0f));
                        float ang = pf * inv;
                        float s, cs;
                        sincosf(ang, &s, &cs);
                        float v1 = acc[mt][nt][rs * 2 + c];
                        float v2 = acc[mt][nt + 4][rs * 2 + c];
                        y1[c] = (v1 * cs - v2 * s) * scale;
                        y2[c] = (v2 * cs + v1 * s) * scale;
                    }
                    size_t o = (size_t)m * stride + colbase + jp0;
                    float h10 = hfr(y1[0]), h11 = hfr(y1[1]);
                    float h20 = hfr(y2[0]), h21 = hfr(y2[1]);
                    *(uint32_t*)&oh[o]      = pack_f16(h10, h11);
                    *(uint32_t*)&ol[o]      = pack_f16(y1[0] - h10, y1[1] - h11);
                    *(uint32_t*)&oh[o + 32] = pack_f16(h20, h21);
                    *(uint32_t*)&ol[o + 32] = pack_f16(y2[0] - h20, y2[1] - h21);
                }
            }
    }
}

// ---------------- HMMA flash attention (fp16; QK 3-term, PV 2-term) ------------
#define QST 72
#define ATT_Q_E  (256*QST)
#define ATT_KV_E (64*QST)
#define ATT_KV_STAGE (4*ATT_KV_E*2)
#define ATT_QBYTES (2*ATT_Q_E*2)
#define ATT_SMEM (ATT_QBYTES + 3*ATT_KV_STAGE)   // 184320 B

__device__ __forceinline__ void attn_load_kv(
    uint32_t stage_base, int tid, int b, int kvh, int kt,
    const __half* __restrict__ kh, const __half* __restrict__ kl,
    const __half* __restrict__ vh, const __half* __restrict__ vl)
{
    #pragma unroll
    for (int it = 0; it < 8; it++) {
        int cid = tid + it * 256;
        int arr = cid >> 9;
        int rem = cid & 511;
        int row = rem >> 3;
        int c   = rem & 7;
        const __half* base = (arr == 0) ? kh : (arr == 1) ? kl : (arr == 2) ? vh : vl;
        const __half* src = base + (size_t)(b * SS + kt * 64 + row) * KVDIM + kvh * 64 + c * 8;
        CP_ASYNC16(stage_base + (uint32_t)arr * ATT_KV_E * 2 + (uint32_t)(row * QST + c * 8) * 2, src);
    }
    CP_COMMIT();
}

__global__ __launch_bounds__(256, 1)
void attn_hmma(const __half* __restrict__ qh, const __half* __restrict__ ql,
               const __half* __restrict__ kh, const __half* __restrict__ kl,
               const __half* __restrict__ vh, const __half* __restrict__ vl,
               __half* __restrict__ ao)
{
    extern __shared__ __half smatt[];
    const int qt  = gridDim.x - 1 - blockIdx.x;
    const int kvh = blockIdx.y;
    const int b   = blockIdx.z;
    const int tid = threadIdx.x, wid = tid >> 5, lane = tid & 31;

    const uint32_t smb  = smem_u32(smatt);
    const uint32_t Qh_o = smb;
    const uint32_t Ql_o = smb + ATT_Q_E * 2;

    // Q tile load
    #pragma unroll
    for (int it = 0; it < 16; it++) {
        int cid = tid + it * 256;
        int arr = cid >> 11;
        int rem = cid & 2047;
        int row = rem >> 3;
        int c   = rem & 7;
        const __half* src = (arr ? ql : qh)
            + (size_t)(b * SS + qt * 64 + (row & 63)) * QDIM
            + (kvh * 4 + (row >> 6)) * 64 + c * 8;
        CP_ASYNC16((arr ? Ql_o : Qh_o) + (uint32_t)(row * QST + c * 8) * 2, src);
    }
    CP_COMMIT();

    attn_load_kv(smb + ATT_QBYTES, tid, b, kvh, 0, kh, kl, vh, vl);
    if (qt >= 1)
        attn_load_kv(smb + ATT_QBYTES + ATT_KV_STAGE, tid, b, kvh, 1, kh, kl, vh, vl);

    float m_r[2][2], l_r[2][2], oacc[2][8][4];
    #pragma unroll
    for (int mt = 0; mt < 2; mt++) {
        m_r[mt][0] = -1e30f; m_r[mt][1] = -1e30f;
        l_r[mt][0] = 0.f;    l_r[mt][1] = 0.f;
        #pragma unroll
        for (int nt = 0; nt < 8; nt++)
            #pragma unroll
            for (int j = 0; j < 4; j++) oacc[mt][nt][j] = 0.f;
    }

    const int wrow  = wid * 32;
    const int hloc  = wid >> 1;
    const int rtile = (wid & 1) * 32;

    int st = 0;
    for (int kt = 0; kt <= qt; kt++) {
        if (kt < qt) CP_WAIT1(); else CP_WAIT0();
        __syncthreads();

        if (kt + 2 <= qt)
            attn_load_kv(smb + ATT_QBYTES + (uint32_t)((kt + 2) % 3) * ATT_KV_STAGE,
                         tid, b, kvh, kt + 2, kh, kl, vh, vl);

        const uint32_t stg  = smb + ATT_QBYTES + (uint32_t)st * ATT_KV_STAGE;
        const uint32_t Kh_o = stg;
        const uint32_t Kl_o = stg + ATT_KV_E * 2;
        const uint32_t Vh_o = stg + 2 * ATT_KV_E * 2;
        const uint32_t Vl_o = stg + 3 * ATT_KV_E * 2;

        // ---- S = Q K^T (3-term)
        float sacc[2][8][4];
        #pragma unroll
        for (int mt = 0; mt < 2; mt++)
            #pragma unroll
            for (int nt = 0; nt < 8; nt++)
                #pragma unroll
                for (int j = 0; j < 4; j++) sacc[mt][nt][j] = 0.f;

        #pragma unroll
        for (int ks = 0; ks < 4; ks++) {
            uint32_t qa_h[2][4], qa_l[2][4], kb_h[4][4], kb_l[4][4];
            #pragma unroll
            for (int mt = 0; mt < 2; mt++) {
                int row = wrow + mt * 16 + (lane & 15);
                int col = ks * 16 + ((lane >> 4) << 3);
                uint32_t off = (uint32_t)(row * QST + col) * 2;
                LDSM4(qa_h[mt], Qh_o + off);
                LDSM4(qa_l[mt], Ql_o + off);
            }
            #pragma unroll
            for (int p = 0; p < 4; p++) {
                int row = p * 16 + (lane & 7) + ((lane >> 4) << 3);
                int col = ks * 16 + (((lane >> 3) & 1) << 3);
                uint32_t off = (uint32_t)(row * QST + col) * 2;
                LDSM4(kb_h[p], Kh_o + off);
                LDSM4(kb_l[p], Kl_o + off);
            }
            #pragma unroll
            for (int mt = 0; mt < 2; mt++) {
                #pragma unroll
                for (int nt = 0; nt < 8; nt++) {
                    uint32_t b0h = kb_h[nt >> 1][(nt & 1) * 2];
                    uint32_t b1h = kb_h[nt >> 1][(nt & 1) * 2 + 1];
                    uint32_t b0l = kb_l[nt >> 1][(nt & 1) * 2];
                    uint32_t b1l = kb_l[nt >> 1][(nt & 1) * 2 + 1];
                    MMA_F16(sacc[mt][nt], qa_h[mt], b0h, b1h);
                    MMA_F16(sacc[mt][nt], qa_h[mt], b0l, b1l);
                    MMA_F16(sacc[mt][nt], qa_l[mt], b0h, b1h);
                }
            }
        }

        if (kt == qt) {
            #pragma unroll
            for (int mt = 0; mt < 2; mt++)
                #pragma unroll
                for (int nt = 0; nt < 8; nt++)
                    #pragma unroll
                    for (int cc = 0; cc < 4; cc++) {
                        int rloc = rtile + mt * 16 + (lane >> 2) + ((cc >= 2) ? 8 : 0);
                        int cloc = nt * 8 + (lane & 3) * 2 + (cc & 1);
                        if (cloc > rloc) sacc[mt][nt][cc] = -1e30f;
                    }
        }

        // ---- online softmax
        #pragma unroll
        for (int mt = 0; mt < 2; mt++) {
            float mx0 = -1e30f, mx1 = -1e30f;
            #pragma unroll
            for (int nt = 0; nt < 8; nt++) {
                mx0 = fmaxf(mx0, fmaxf(sacc[mt][nt][0], sacc[mt][nt][1]));
                mx1 = fmaxf(mx1, fmaxf(sacc[mt][nt][2], sacc[mt][nt][3]));
            }
            mx0 = fmaxf(mx0, __shfl_xor_sync(0xffffffffu, mx0, 1));
            mx0 = fmaxf(mx0, __shfl_xor_sync(0xffffffffu, mx0, 2));
            mx1 = fmaxf(mx1, __shfl_xor_sync(0xffffffffu, mx1, 1));
            mx1 = fmaxf(mx1, __shfl_xor_sync(0xffffffffu, mx1, 2));
            float mn0 = fmaxf(m_r[mt][0], mx0);
            float mn1 = fmaxf(m_r[mt][1], mx1);
            float sc0 = fast_exp(m_r[mt][0] - mn0);
            float sc1 = fast_exp(m_r[mt][1] - mn1);
            m_r[mt][0] = mn0; m_r[mt][1] = mn1;
            float sum0 = 0.f, sum1 = 0.f;
            #pragma unroll
            for (int nt = 0; nt < 8; nt++) {
                float p0 = fast_exp(sacc[mt][nt][0] - mn0);
                float p1 = fast_exp(sacc[mt][nt][1] - mn0);
                float p2 = fast_exp(sacc[mt][nt][2] - mn1);
                float p3 = fast_exp(sacc[mt][nt][3] - mn1);
                sacc[mt][nt][0] = p0; sacc[mt][nt][1] = p1;
                sacc[mt][nt][2] = p2; sacc[mt][nt][3] = p3;
                sum0 += p0 + p1; sum1 += p2 + p3;
                oacc[mt][nt][0] *= sc0; oacc[mt][nt][1] *= sc0;
                oacc[mt][nt][2] *= sc1; oacc[mt][nt][3] *= sc1;
            }
            l_r[mt][0] = l_r[mt][0] * sc0 + sum0;
            l_r[mt][1] = l_r[mt][1] * sc1 + sum1;
        }

        // ---- O += P V (2-term: P fp16-single x V hi/lo)
        #pragma unroll
        for (int j = 0; j < 4; j++) {
            uint32_t vb_h[4][4], vb_l[4][4];
            int tok_off = (lane & 7) + (((lane >> 3) & 1) << 3);
            int d_off   = ((lane >> 4) & 1) << 3;
            #pragma unroll
            for (int p = 0; p < 4; p++) {
                uint32_t off = (uint32_t)((j * 16 + tok_off) * QST + p * 16 + d_off) * 2;
                LDSM4T(vb_h[p], Vh_o + off);
                LDSM4T(vb_l[p], Vl_o + off);
            }
            #pragma unroll
            for (int mt = 0; mt < 2; mt++) {
                uint32_t ah[4];
                #pragma unroll
                for (int q = 0; q < 4; q++) {
                    int nt = 2 * j + (q >> 1);
                    ah[q] = pack_f16(sacc[mt][nt][(q & 1) * 2], sacc[mt][nt][(q & 1) * 2 + 1]);
                }
                #pragma unroll
                for (int nt = 0; nt < 8; nt++) {
                    uint32_t b0h = vb_h[nt >> 1][(nt & 1) * 2];
                    uint32_t b1h = vb_h[nt >> 1][(nt & 1) * 2 + 1];
                    uint32_t b0l = vb_l[nt >> 1][(nt & 1) * 2];
                    uint32_t b1l = vb_l[nt >> 1][(nt & 1) * 2 + 1];
                    MMA_F16(oacc[mt][nt], ah, b0h, b1h);
                    MMA_F16(oacc[mt][nt], ah, b0l, b1l);
                }
            }
        }
        st = (st == 2) ? 0 : st + 1;
    }

    // ---- epilogue: normalize + fp16 single output
    #pragma unroll
    for (int mt = 0; mt < 2; mt++) {
        l_r[mt][0] += __shfl_xor_sync(0xffffffffu, l_r[mt][0], 1);
        l_r[mt][0] += __shfl_xor_sync(0xffffffffu, l_r[mt][0], 2);
        l_r[mt][1] += __shfl_xor_sync(0xffffffffu, l_r[mt][1], 1);
        l_r[mt][1] += __shfl_xor_sync(0xffffffffu, l_r[mt][1], 2);
        float inv0 = 1.0f / l_r[mt][0];
        float inv1 = 1.0f / l_r[mt][1];
        int tok = qt * 64 + rtile + mt * 16 + (lane >> 2);
        int colb = (kvh * 4 + hloc) * 64 + (lane & 3) * 2;
        #pragma unroll
        for (int nt = 0; nt < 8; nt++) {
            size_t o0 = (size_t)(b * SS + tok) * QDIM + colb + nt * 8;
            size_t o1 = o0 + (size_t)8 * QDIM;
            *(uint32_t*)&ao[o0] = pack_f16(oacc[mt][nt][0] * inv0, oacc[mt][nt][1] * inv0);
            *(uint32_t*)&ao[o1] = pack_f16(oacc[mt][nt][2] * inv1, oacc[mt][nt][3] * inv1);
        }
    }
}

// ---------------------------------------------------------------------------
extern "C" void kernel_launch(void* const* d_in, const int* in_sizes, int n_in,
                              void* d_out, int out_size)
{
    (void)in_sizes; (void)n_in; (void)out_size;
    const float* hs  = (const float*)d_in[0];
    const int*   pos = (const int*)d_in[2];
    const float* Wq  = (const float*)d_in[3];
    const float* Wk  = (const float*)d_in[4];
    const float* Wv  = (const float*)d_in[5];
    const float* Wo  = (const float*)d_in[6];
    float* out = (float*)d_out;

    __half *hsb, *qh, *ql, *kh, *kl, *vh, *vl, *ao, *w, *wo;
    cudaGetSymbolAddress((void**)&hsb, g_hs);
    cudaGetSymbolAddress((void**)&qh, g_qh);
    cudaGetSymbolAddress((void**)&ql, g_ql);
    cudaGetSymbolAddress((void**)&kh, g_kh);
    cudaGetSymbolAddress((void**)&kl, g_kl);
    cudaGetSymbolAddress((void**)&vh, g_vh);
    cudaGetSymbolAddress((void**)&vl, g_vl);
    cudaGetSymbolAddress((void**)&ao, g_ao);
    cudaGetSymbolAddress((void**)&w,  g_wqkvT);
    cudaGetSymbolAddress((void**)&wo, g_woT);

    const int M = MTOT;
    cudaFuncSetAttribute(hmma_gemm_c,   cudaFuncAttributeMaxDynamicSharedMemorySize, GEMM_SMEM);
    cudaFuncSetAttribute(hmma_gemm_qkv, cudaFuncAttributeMaxDynamicSharedMemorySize, GEMM_SMEM);
    cudaFuncSetAttribute(attn_hmma,     cudaFuncAttributeMaxDynamicSharedMemorySize, ATT_SMEM);

    split16_kernel<<<(M * DIN / 4 + 255) / 256, 256>>>(hs, hsb, M * DIN / 4);                  // 1
    transpose_qkv16<<<dim3(QKVN / 32, DIN / 32), dim3(32, 8)>>>(Wq, Wk, Wv, w);                // 2
    transpose16<<<dim3(DOUT / 32, QDIM / 32), dim3(32, 8)>>>(Wo, wo, QDIM, DOUT);              // 3
    hmma_gemm_qkv<<<dim3(QKVN / 128, M / 128), 256, GEMM_SMEM>>>(
        hsb, w, pos, qh, ql, kh, kl, vh, vl);                                                  // 4
    attn_hmma<<<dim3(SS / 64, NKV, BB), 256, ATT_SMEM>>>(qh, ql, kh, kl, vh, vl, ao);          // 5 (profiled)
    hmma_gemm_c<<<dim3(DOUT / 128, M / 128), 256, GEMM_SMEM>>>(ao, wo, out, M, DOUT, QDIM);    // 6
}

// round 10
// speedup vs baseline: 2.4293x; 1.0571x over previous
#include <cuda_runtime.h>
#include <cuda_fp16.h>
#include <math.h>
#include <stdint.h>

#define BB 2
#define SS 2048
#define DIN 4096
#define NH 32
#define NKV 8
#define HD 64
#define QDIM 2048
#define KVDIM 512
#define QKVN 3072
#define DOUT 2048
#define MTOT 4096

// ---------------- scratch (__device__ globals) ------------------------------
__device__ __half g_hs[MTOT*DIN];            // hidden states, fp16 single
__device__ __half g_q[MTOT*QDIM];            // roped, pre-scaled Q (single)
__device__ __half g_kh[MTOT*KVDIM];          // roped K hi/lo pair
__device__ __half g_kl[MTOT*KVDIM];
__device__ __half g_v[MTOT*KVDIM];           // V single
__device__ __half g_ao[MTOT*QDIM];           // attention out, fp16 single
__device__ __half g_wqkvT[QKVN*DIN];         // weights fp16 single
__device__ __half g_woT[DOUT*QDIM];

// ---------------- helpers ----------------------------------------------------
__device__ __forceinline__ uint32_t smem_u32(const void* p) {
    uint32_t a;
    asm("{ .reg .u64 t; cvta.to.shared.u64 t, %1; cvt.u32.u64 %0, t; }" : "=r"(a) : "l"(p));
    return a;
}

#define LDSM4(r, addr)                                                           \
    asm volatile("ldmatrix.sync.aligned.m8n8.x4.shared.b16 {%0,%1,%2,%3}, [%4];" \
        : "=r"((r)[0]), "=r"((r)[1]), "=r"((r)[2]), "=r"((r)[3]) : "r"(addr))

#define LDSM4T(r, addr)                                                          \
    asm volatile("ldmatrix.sync.aligned.m8n8.x4.trans.shared.b16 {%0,%1,%2,%3}, [%4];" \
        : "=r"((r)[0]), "=r"((r)[1]), "=r"((r)[2]), "=r"((r)[3]) : "r"(addr))

#define MMA_F16(d, a, b0, b1)                                                    \
    asm volatile("mma.sync.aligned.m16n8k16.row.col.f32.f16.f16.f32 "            \
        "{%0,%1,%2,%3}, {%4,%5,%6,%7}, {%8,%9}, {%0,%1,%2,%3};"                  \
        : "+f"((d)[0]), "+f"((d)[1]), "+f"((d)[2]), "+f"((d)[3])                 \
        : "r"((a)[0]), "r"((a)[1]), "r"((a)[2]), "r"((a)[3]), "r"(b0), "r"(b1))

#define CP_ASYNC16(dst, src)                                                     \
    asm volatile("cp.async.cg.shared.global [%0], [%1], 16;" :: "r"(dst), "l"(src) : "memory")
#define CP_COMMIT()  asm volatile("cp.async.commit_group;" ::: "memory")
#define CP_WAIT1()   asm volatile("cp.async.wait_group 1;" ::: "memory")
#define CP_WAIT0()   asm volatile("cp.async.wait_group 0;" ::: "memory")

__device__ __forceinline__ uint32_t pack_f16(float lo, float hi) {
    uint32_t r;
    asm("cvt.rn.f16x2.f32 %0, %1, %2;" : "=r"(r) : "f"(hi), "f"(lo));
    return r;
}
__device__ __forceinline__ float hfr(float x) {
    return __half2float(__float2half_rn(x));
}

__device__ __forceinline__ float fast_exp(float x) {
    float t = fmaxf(x * 1.4426950408889634f, -126.0f);
    float fi = floorf(t);
    float f = t - fi;
    float p = 1.54035304e-4f;
    p = fmaf(p, f, 1.33335581e-3f);
    p = fmaf(p, f, 9.61812911e-3f);
    p = fmaf(p, f, 5.55041087e-2f);
    p = fmaf(p, f, 2.40226507e-1f);
    p = fmaf(p, f, 6.93147181e-1f);
    p = fmaf(p, f, 1.0f);
    return p * __uint_as_float(((uint32_t)((int)fi + 127)) << 23);
}

// ---------------- prep kernels ------------------------------------------------
__global__ void split16_kernel(const float* __restrict__ x, __half* __restrict__ h, int n4) {
    int i = blockIdx.x * blockDim.x + threadIdx.x;
    if (i >= n4) return;
    float4 v = ((const float4*)x)[i];
    __half hh[4];
    hh[0] = __float2half_rn(v.x); hh[1] = __float2half_rn(v.y);
    hh[2] = __float2half_rn(v.z); hh[3] = __float2half_rn(v.w);
    ((uint2*)h)[i] = *(uint2*)hh;
}

__global__ void transpose_qkv16(const float* __restrict__ Wq, const float* __restrict__ Wk,
                                const float* __restrict__ Wv, __half* __restrict__ T) {
    __shared__ float t[32][33];
    int n0 = blockIdx.x * 32;
    int k0 = blockIdx.y * 32;
    const float* W; int srcN, sn0;
    if (n0 < QDIM)              { W = Wq; srcN = QDIM;  sn0 = n0; }
    else if (n0 < QDIM + KVDIM) { W = Wk; srcN = KVDIM; sn0 = n0 - QDIM; }
    else                        { W = Wv; srcN = KVDIM; sn0 = n0 - QDIM - KVDIM; }
    int x = threadIdx.x, y = threadIdx.y;
    #pragma unroll
    for (int i = 0; i < 32; i += 8)
        t[y + i][x] = W[(size_t)(k0 + y + i) * srcN + sn0 + x];
    __syncthreads();
    #pragma unroll
    for (int i = 0; i < 32; i += 8)
        T[(size_t)(n0 + y + i) * DIN + k0 + x] = __float2half_rn(t[x][y + i]);
}

__global__ void transpose16(const float* __restrict__ W, __half* __restrict__ T, int K, int N) {
    __shared__ float t[32][33];
    int k0 = blockIdx.y * 32, n0 = blockIdx.x * 32;
    int x = threadIdx.x, y = threadIdx.y;
    #pragma unroll
    for (int i = 0; i < 32; i += 8)
        t[y + i][x] = W[(size_t)(k0 + y + i) * N + n0 + x];
    __syncthreads();
    #pragma unroll
    for (int i = 0; i < 32; i += 8)
        T[(size_t)(n0 + y + i) * K + k0 + x] = __float2half_rn(t[x][y + i]);
}

// ---------------- 1-term fp16 HMMA GEMM core (3-stage) --------------------------
#define AST 40
#define TILE_E (128*AST)
#define STAGE_E (2*TILE_E)
#define NSTAGE 3
#define GEMM_SMEM (NSTAGE * STAGE_E * 2)   // 61440 B

__device__ __forceinline__ void load_stage(
    uint32_t sbase_bytes, int tid, int bm, int bn, int k0, int K,
    const __half* __restrict__ A, const __half* __restrict__ B)
{
    #pragma unroll
    for (int i = 0; i < 4; i++) {
        int cid = tid + i * 256;
        int arr = cid >> 9;
        int rem = cid & 511;
        int row = rem >> 2;
        int c16 = rem & 3;
        const __half* g = (arr == 0)
            ? A + (size_t)(bm + row) * K + k0 + c16 * 8
            : B + (size_t)(bn + row) * K + k0 + c16 * 8;
        uint32_t d = sbase_bytes + (uint32_t)(arr * TILE_E + row * AST + c16 * 8) * 2;
        CP_ASYNC16(d, g);
    }
    CP_COMMIT();
}

__device__ __forceinline__ void gemm_mainloop(
    float acc[2][8][4], uint32_t smb, int tid, int bm, int bn, int K,
    const __half* __restrict__ A, const __half* __restrict__ B)
{
    const int wid = tid >> 5;
    const int lane = tid & 31;
    const int wm = (wid & 3) * 32;
    const int wn = (wid >> 2) * 64;
    const int nch = K >> 5;

    load_stage(smb, tid, bm, bn, 0, K, A, B);
    load_stage(smb + STAGE_E * 2, tid, bm, bn, 32, K, A, B);

    int st = 0, pst = 2;
    for (int c = 0; c < nch; c++) {
        CP_WAIT1();
        __syncthreads();

        if (c + 2 < nch)
            load_stage(smb + (uint32_t)pst * STAGE_E * 2, tid, bm, bn,
                       (c + 2) << 5, K, A, B);

        uint32_t Ab = smb + (uint32_t)st * STAGE_E * 2;
        uint32_t Bb = Ab + TILE_E * 2;

        #pragma unroll
        for (int ks = 0; ks < 2; ks++) {
            uint32_t ah[2][4], bf[4][4];
            #pragma unroll
            for (int mt = 0; mt < 2; mt++) {
                int row = wm + mt * 16 + (lane & 15);
                int col = ks * 16 + ((lane >> 4) << 3);
                LDSM4(ah[mt], Ab + (uint32_t)(row * AST + col) * 2);
            }
            #pragma unroll
            for (int p = 0; p < 4; p++) {
                int row = wn + p * 16 + (lane & 7) + ((lane >> 4) << 3);
                int col = ks * 16 + (((lane >> 3) & 1) << 3);
                LDSM4(bf[p], Bb + (uint32_t)(row * AST + col) * 2);
            }
            #pragma unroll
            for (int mt = 0; mt < 2; mt++) {
                #pragma unroll
                for (int nt = 0; nt < 8; nt++) {
                    uint32_t b0 = bf[nt >> 1][(nt & 1) * 2];
                    uint32_t b1 = bf[nt >> 1][(nt & 1) * 2 + 1];
                    MMA_F16(acc[mt][nt], ah[mt], b0, b1);
                }
            }
        }
        st = (st == 2) ? 0 : st + 1;
        pst = (pst == 2) ? 0 : pst + 1;
    }
}

// O projection: fp32 C output
__global__ __launch_bounds__(256)
void hmma_gemm_c(const __half* __restrict__ A, const __half* __restrict__ B,
                 float* __restrict__ C, int M, int N, int K)
{
    extern __shared__ __half sm[];
    const int tid = threadIdx.x;
    const int wid = tid >> 5, lane = tid & 31;
    const int bm = blockIdx.y * 128, bn = blockIdx.x * 128;
    const int wm = (wid & 3) * 32, wn = (wid >> 2) * 64;

    float acc[2][8][4];
    #pragma unroll
    for (int mt = 0; mt < 2; mt++)
        #pragma unroll
        for (int nt = 0; nt < 8; nt++)
            #pragma unroll
            for (int j = 0; j < 4; j++) acc[mt][nt][j] = 0.f;

    gemm_mainloop(acc, smem_u32(sm), tid, bm, bn, K, A, B);

    #pragma unroll
    for (int mt = 0; mt < 2; mt++)
        #pragma unroll
        for (int nt = 0; nt < 8; nt++) {
            int r0  = bm + wm + mt * 16 + (lane >> 2);
            int col = bn + wn + nt * 8 + (lane & 3) * 2;
            *(float2*)&C[(size_t)r0 * N + col] = make_float2(acc[mt][nt][0], acc[mt][nt][1]);
            *(float2*)&C[(size_t)(r0 + 8) * N + col] = make_float2(acc[mt][nt][2], acc[mt][nt][3]);
        }
}

// QKV GEMM with fused RoPE epilogue: Q single, K hi/lo, V single
__global__ __launch_bounds__(256)
void hmma_gemm_qkv(const __half* __restrict__ A, const __half* __restrict__ B,
                   const int* __restrict__ pos,
                   __half* __restrict__ q,
                   __half* __restrict__ kh, __half* __restrict__ kl,
                   __half* __restrict__ v)
{
    extern __shared__ __half sm[];
    const int tid = threadIdx.x;
    const int wid = tid >> 5, lane = tid & 31;
    const int bm = blockIdx.y * 128, bn = blockIdx.x * 128;
    const int wm = (wid & 3) * 32, wn = (wid >> 2) * 64;

    float acc[2][8][4];
    #pragma unroll
    for (int mt = 0; mt < 2; mt++)
        #pragma unroll
        for (int nt = 0; nt < 8; nt++)
            #pragma unroll
            for (int j = 0; j < 4; j++) acc[mt][nt][j] = 0.f;

    gemm_mainloop(acc, smem_u32(sm), tid, bm, bn, DIN, A, B);

    const int ncol0 = bn + wn;   // 64-aligned: one head per warp
    if (ncol0 >= QDIM + KVDIM) {
        // V: single fp16
        int colb = ncol0 - (QDIM + KVDIM) + (lane & 3) * 2;
        #pragma unroll
        for (int mt = 0; mt < 2; mt++)
            #pragma unroll
            for (int nt = 0; nt < 8; nt++)
                #pragma unroll
                for (int rs = 0; rs < 2; rs++) {
                    int m = bm + wm + mt * 16 + (lane >> 2) + rs * 8;
                    size_t o = (size_t)m * KVDIM + colb + nt * 8;
                    *(uint32_t*)&v[o] = pack_f16(acc[mt][nt][rs * 2], acc[mt][nt][rs * 2 + 1]);
                }
    } else {
        const int isQ = ncol0 < QDIM;
        const float scale = isQ ? 0.125f : 1.0f;
        const int stride = isQ ? QDIM : KVDIM;
        const int colbase = isQ ? ncol0 : ncol0 - QDIM;
        #pragma unroll
        for (int mt = 0; mt < 2; mt++)
            #pragma unroll
            for (int rs = 0; rs < 2; rs++) {
                int m = bm + wm + mt * 16 + (lane >> 2) + rs * 8;
                float pf = (float)pos[m];
                #pragma unroll
                for (int nt = 0; nt < 4; nt++) {
                    int jp0 = nt * 8 + (lane & 3) * 2;
                    float y1[2], y2[2];
                    #pragma unroll
                    for (int c = 0; c < 2; c++) {
                        float inv = exp2f(-(float)(jp0 + c) * (13.287712379549449f / 32.0f));
                        float ang = pf * inv;
                        float s, cs;
                        sincosf(ang, &s, &cs);
                        float v1 = acc[mt][nt][rs * 2 + c];
                        float v2 = acc[mt][nt + 4][rs * 2 + c];
                        y1[c] = (v1 * cs - v2 * s) * scale;
                        y2[c] = (v2 * cs + v1 * s) * scale;
                    }
                    size_t o = (size_t)m * stride + colbase + jp0;
                    if (isQ) {
                        *(uint32_t*)&q[o]      = pack_f16(y1[0], y1[1]);
                        *(uint32_t*)&q[o + 32] = pack_f16(y2[0], y2[1]);
                    } else {
                        float h10 = hfr(y1[0]), h11 = hfr(y1[1]);
                        float h20 = hfr(y2[0]), h21 = hfr(y2[1]);
                        *(uint32_t*)&kh[o]      = pack_f16(h10, h11);
                        *(uint32_t*)&kl[o]      = pack_f16(y1[0] - h10, y1[1] - h11);
                        *(uint32_t*)&kh[o + 32] = pack_f16(h20, h21);
                        *(uint32_t*)&kl[o + 32] = pack_f16(y2[0] - h20, y2[1] - h21);
                    }
                }
            }
    }
}

// ---------------- HMMA flash attention (QK 2-term, PV 1-term) ------------------
#define QST 72
#define ATT_Q_E  (256*QST)
#define ATT_KV_E (64*QST)
#define ATT_KV_STAGE (3*ATT_KV_E*2)       // Kh | Kl | V
#define ATT_QBYTES (ATT_Q_E*2)
#define ATT_SMEM (ATT_QBYTES + 3*ATT_KV_STAGE)   // 119808 B

__device__ __forceinline__ void attn_load_kv(
    uint32_t stage_base, int tid, int b, int kvh, int kt,
    const __half* __restrict__ kh, const __half* __restrict__ kl,
    const __half* __restrict__ v)
{
    #pragma unroll
    for (int it = 0; it < 6; it++) {
        int cid = tid + it * 256;       // 0..1535
        int arr = cid >> 9;             // 0:Kh 1:Kl 2:V
        int rem = cid & 511;
        int row = rem >> 3;
        int c   = rem & 7;
        const __half* base = (arr == 0) ? kh : (arr == 1) ? kl : v;
        const __half* src = base + (size_t)(b * SS + kt * 64 + row) * KVDIM + kvh * 64 + c * 8;
        CP_ASYNC16(stage_base + (uint32_t)arr * ATT_KV_E * 2 + (uint32_t)(row * QST + c * 8) * 2, src);
    }
    CP_COMMIT();
}

__global__ __launch_bounds__(256, 1)
void attn_hmma(const __half* __restrict__ q,
               const __half* __restrict__ kh, const __half* __restrict__ kl,
               const __half* __restrict__ v,
               __half* __restrict__ ao)
{
    extern __shared__ __half smatt[];
    const int qt  = gridDim.x - 1 - blockIdx.x;
    const int kvh = blockIdx.y;
    const int b   = blockIdx.z;
    const int tid = threadIdx.x, wid = tid >> 5, lane = tid & 31;

    const uint32_t smb = smem_u32(smatt);
    const uint32_t Q_o = smb;

    // Q tile load (256 rows x 64 cols single)
    #pragma unroll
    for (int it = 0; it < 8; it++) {
        int cid = tid + it * 256;       // 0..2047
        int row = cid >> 3;
        int c   = cid & 7;
        const __half* src = q
            + (size_t)(b * SS + qt * 64 + (row & 63)) * QDIM
            + (kvh * 4 + (row >> 6)) * 64 + c * 8;
        CP_ASYNC16(Q_o + (uint32_t)(row * QST + c * 8) * 2, src);
    }
    CP_COMMIT();

    attn_load_kv(smb + ATT_QBYTES, tid, b, kvh, 0, kh, kl, v);
    if (qt >= 1)
        attn_load_kv(smb + ATT_QBYTES + ATT_KV_STAGE, tid, b, kvh, 1, kh, kl, v);

    float m_r[2][2], l_r[2][2], oacc[2][8][4];
    #pragma unroll
    for (int mt = 0; mt < 2; mt++) {
        m_r[mt][0] = -1e30f; m_r[mt][1] = -1e30f;
        l_r[mt][0] = 0.f;    l_r[mt][1] = 0.f;
        #pragma unroll
        for (int nt = 0; nt < 8; nt++)
            #pragma unroll
            for (int j = 0; j < 4; j++) oacc[mt][nt][j] = 0.f;
    }

    const int wrow  = wid * 32;
    const int hloc  = wid >> 1;
    const int rtile = (wid & 1) * 32;

    int st = 0;
    for (int kt = 0; kt <= qt; kt++) {
        if (kt < qt) CP_WAIT1(); else CP_WAIT0();
        __syncthreads();

        if (kt + 2 <= qt)
            attn_load_kv(smb + ATT_QBYTES + (uint32_t)((kt + 2) % 3) * ATT_KV_STAGE,
                         tid, b, kvh, kt + 2, kh, kl, v);

        const uint32_t stg  = smb + ATT_QBYTES + (uint32_t)st * ATT_KV_STAGE;
        const uint32_t Kh_o = stg;
        const uint32_t Kl_o = stg + ATT_KV_E * 2;
        const uint32_t V_o  = stg + 2 * ATT_KV_E * 2;

        // ---- S = Q K^T (2-term: q single x (kh + kl))
        float sacc[2][8][4];
        #pragma unroll
        for (int mt = 0; mt < 2; mt++)
            #pragma unroll
            for (int nt = 0; nt < 8; nt++)
                #pragma unroll
                for (int j = 0; j < 4; j++) sacc[mt][nt][j] = 0.f;

        #pragma unroll
        for (int ks = 0; ks < 4; ks++) {
            uint32_t qa[2][4], kb_h[4][4], kb_l[4][4];
            #pragma unroll
            for (int mt = 0; mt < 2; mt++) {
                int row = wrow + mt * 16 + (lane & 15);
                int col = ks * 16 + ((lane >> 4) << 3);
                LDSM4(qa[mt], Q_o + (uint32_t)(row * QST + col) * 2);
            }
            #pragma unroll
            for (int p = 0; p < 4; p++) {
                int row = p * 16 + (lane & 7) + ((lane >> 4) << 3);
                int col = ks * 16 + (((lane >> 3) & 1) << 3);
                uint32_t off = (uint32_t)(row * QST + col) * 2;
                LDSM4(kb_h[p], Kh_o + off);
                LDSM4(kb_l[p], Kl_o + off);
            }
            #pragma unroll
            for (int mt = 0; mt < 2; mt++) {
                #pragma unroll
                for (int nt = 0; nt < 8; nt++) {
                    uint32_t b0h = kb_h[nt >> 1][(nt & 1) * 2];
                    uint32_t b1h = kb_h[nt >> 1][(nt & 1) * 2 + 1];
                    uint32_t b0l = kb_l[nt >> 1][(nt & 1) * 2];
                    uint32_t b1l = kb_l[nt >> 1][(nt & 1) * 2 + 1];
                    MMA_F16(sacc[mt][nt], qa[mt], b0h, b1h);
                    MMA_F16(sacc[mt][nt], qa[mt], b0l, b1l);
                }
            }
        }

        if (kt == qt) {
            #pragma unroll
            for (int mt = 0; mt < 2; mt++)
                #pragma unroll
                for (int nt = 0; nt < 8; nt++)
                    #pragma unroll
                    for (int cc = 0; cc < 4; cc++) {
                        int rloc = rtile + mt * 16 + (lane >> 2) + ((cc >= 2) ? 8 : 0);
                        int cloc = nt * 8 + (lane & 3) * 2 + (cc & 1);
                        if (cloc > rloc) sacc[mt][nt][cc] = -1e30f;
                    }
        }

        // ---- online softmax
        #pragma unroll
        for (int mt = 0; mt < 2; mt++) {
            float mx0 = -1e30f, mx1 = -1e30f;
            #pragma unroll
            for (int nt = 0; nt < 8; nt++) {
                mx0 = fmaxf(mx0, fmaxf(sacc[mt][nt][0], sacc[mt][nt][1]));
                mx1 = fmaxf(mx1, fmaxf(sacc[mt][nt][2], sacc[mt][nt][3]));
            }
            mx0 = fmaxf(mx0, __shfl_xor_sync(0xffffffffu, mx0, 1));
            mx0 = fmaxf(mx0, __shfl_xor_sync(0xffffffffu, mx0, 2));
            mx1 = fmaxf(mx1, __shfl_xor_sync(0xffffffffu, mx1, 1));
            mx1 = fmaxf(mx1, __shfl_xor_sync(0xffffffffu, mx1, 2));
            float mn0 = fmaxf(m_r[mt][0], mx0);
            float mn1 = fmaxf(m_r[mt][1], mx1);
            float sc0 = fast_exp(m_r[mt][0] - mn0);
            float sc1 = fast_exp(m_r[mt][1] - mn1);
            m_r[mt][0] = mn0; m_r[mt][1] = mn1;
            float sum0 = 0.f, sum1 = 0.f;
            #pragma unroll
            for (int nt = 0; nt < 8; nt++) {
                float p0 = fast_exp(sacc[mt][nt][0] - mn0);
                float p1 = fast_exp(sacc[mt][nt][1] - mn0);
                float p2 = fast_exp(sacc[mt][nt][2] - mn1);
                float p3 = fast_exp(sacc[mt][nt][3] - mn1);
                sacc[mt][nt][0] = p0; sacc[mt][nt][1] = p1;
                sacc[mt][nt][2] = p2; sacc[mt][nt][3] = p3;
                sum0 += p0 + p1; sum1 += p2 + p3;
                oacc[mt][nt][0] *= sc0; oacc[mt][nt][1] *= sc0;
                oacc[mt][nt][2] *= sc1; oacc[mt][nt][3] *= sc1;
            }
            l_r[mt][0] = l_r[mt][0] * sc0 + sum0;
            l_r[mt][1] = l_r[mt][1] * sc1 + sum1;
        }

        // ---- O += P V (1-term: P single x V single)
        #pragma unroll
        for (int j = 0; j < 4; j++) {
            uint32_t vb[4][4];
            int tok_off = (lane & 7) + (((lane >> 3) & 1) << 3);
            int d_off   = ((lane >> 4) & 1) << 3;
            #pragma unroll
            for (int p = 0; p < 4; p++) {
                uint32_t off = (uint32_t)((j * 16 + tok_off) * QST + p * 16 + d_off) * 2;
                LDSM4T(vb[p], V_o + off);
            }
            #pragma unroll
            for (int mt = 0; mt < 2; mt++) {
                uint32_t ah[4];
                #pragma unroll
                for (int qd = 0; qd < 4; qd++) {
                    int nt = 2 * j + (qd >> 1);
                    ah[qd] = pack_f16(sacc[mt][nt][(qd & 1) * 2], sacc[mt][nt][(qd & 1) * 2 + 1]);
                }
                #pragma unroll
                for (int nt = 0; nt < 8; nt++) {
                    uint32_t b0 = vb[nt >> 1][(nt & 1) * 2];
                    uint32_t b1 = vb[nt >> 1][(nt & 1) * 2 + 1];
                    MMA_F16(oacc[mt][nt], ah, b0, b1);
                }
            }
        }
        st = (st == 2) ? 0 : st + 1;
    }

    // ---- epilogue: normalize + fp16 single output
    #pragma unroll
    for (int mt = 0; mt < 2; mt++) {
        l_r[mt][0] += __shfl_xor_sync(0xffffffffu, l_r[mt][0], 1);
        l_r[mt][0] += __shfl_xor_sync(0xffffffffu, l_r[mt][0], 2);
        l_r[mt][1] += __shfl_xor_sync(0xffffffffu, l_r[mt][1], 1);
        l_r[mt][1] += __shfl_xor_sync(0xffffffffu, l_r[mt][1], 2);
        float inv0 = 1.0f / l_r[mt][0];
        float inv1 = 1.0f / l_r[mt][1];
        int tok = qt * 64 + rtile + mt * 16 + (lane >> 2);
        int colb = (kvh * 4 + hloc) * 64 + (lane & 3) * 2;
        #pragma unroll
        for (int nt = 0; nt < 8; nt++) {
            size_t o0 = (size_t)(b * SS + tok) * QDIM + colb + nt * 8;
            size_t o1 = o0 + (size_t)8 * QDIM;
            *(uint32_t*)&ao[o0] = pack_f16(oacc[mt][nt][0] * inv0, oacc[mt][nt][1] * inv0);
            *(uint32_t*)&ao[o1] = pack_f16(oacc[mt][nt][2] * inv1, oacc[mt][nt][3] * inv1);
        }
    }
}

// ---------------------------------------------------------------------------
extern "C" void kernel_launch(void* const* d_in, const int* in_sizes, int n_in,
                              void* d_out, int out_size)
{
    (void)in_sizes; (void)n_in; (void)out_size;
    const float* hs  = (const float*)d_in[0];
    const int*   pos = (const int*)d_in[2];
    const float* Wq  = (const float*)d_in[3];
    const float* Wk  = (const float*)d_in[4];
    const float* Wv  = (const float*)d_in[5];
    const float* Wo  = (const float*)d_in[6];
    float* out = (float*)d_out;

    __half *hsb, *q, *kh, *kl, *v, *ao, *w, *wo;
    cudaGetSymbolAddress((void**)&hsb, g_hs);
    cudaGetSymbolAddress((void**)&q,  g_q);
    cudaGetSymbolAddress((void**)&kh, g_kh);
    cudaGetSymbolAddress((void**)&kl, g_kl);
    cudaGetSymbolAddress((void**)&v,  g_v);
    cudaGetSymbolAddress((void**)&ao, g_ao);
    cudaGetSymbolAddress((void**)&w,  g_wqkvT);
    cudaGetSymbolAddress((void**)&wo, g_woT);

    const int M = MTOT;
    cudaFuncSetAttribute(hmma_gemm_c,   cudaFuncAttributeMaxDynamicSharedMemorySize, GEMM_SMEM);
    cudaFuncSetAttribute(hmma_gemm_qkv, cudaFuncAttributeMaxDynamicSharedMemorySize, GEMM_SMEM);
    cudaFuncSetAttribute(attn_hmma,     cudaFuncAttributeMaxDynamicSharedMemorySize, ATT_SMEM);

    split16_kernel<<<(M * DIN / 4 + 255) / 256, 256>>>(hs, hsb, M * DIN / 4);                  // 1
    transpose_qkv16<<<dim3(QKVN / 32, DIN / 32), dim3(32, 8)>>>(Wq, Wk, Wv, w);                // 2
    transpose16<<<dim3(DOUT / 32, QDIM / 32), dim3(32, 8)>>>(Wo, wo, QDIM, DOUT);              // 3
    hmma_gemm_qkv<<<dim3(QKVN / 128, M / 128), 256, GEMM_SMEM>>>(hsb, w, pos, q, kh, kl, v);   // 4
    attn_hmma<<<dim3(SS / 64, NKV, BB), 256, ATT_SMEM>>>(q, kh, kl, v, ao);                    // 5 (profiled)
    hmma_gemm_c<<<dim3(DOUT / 128, M / 128), 256, GEMM_SMEM>>>(ao, wo, out, M, DOUT, QDIM);    // 6
}

// round 11
// speedup vs baseline: 2.5884x; 1.0655x over previous
#include <cuda_runtime.h>
#include <cuda_fp16.h>
#include <math.h>
#include <stdint.h>

#define BB 2
#define SS 2048
#define DIN 4096
#define NH 32
#define NKV 8
#define HD 64
#define QDIM 2048
#define KVDIM 512
#define QKVN 3072
#define DOUT 2048
#define MTOT 4096

// ---------------- scratch (__device__ globals) ------------------------------
__device__ __half g_hs[MTOT*DIN];            // hidden states, fp16 single
__device__ __half g_q[MTOT*QDIM];            // roped, pre-scaled Q (single)
__device__ __half g_k[MTOT*KVDIM];           // roped K (single)
__device__ __half g_v[MTOT*KVDIM];           // V (single)
__device__ __half g_ao[MTOT*QDIM];           // attention out, fp16 single
__device__ __half g_wqkvT[QKVN*DIN];         // weights fp16 single
__device__ __half g_woT[DOUT*QDIM];

// ---------------- helpers ----------------------------------------------------
__device__ __forceinline__ uint32_t smem_u32(const void* p) {
    uint32_t a;
    asm("{ .reg .u64 t; cvta.to.shared.u64 t, %1; cvt.u32.u64 %0, t; }" : "=r"(a) : "l"(p));
    return a;
}

#define LDSM4(r, addr)                                                           \
    asm volatile("ldmatrix.sync.aligned.m8n8.x4.shared.b16 {%0,%1,%2,%3}, [%4];" \
        : "=r"((r)[0]), "=r"((r)[1]), "=r"((r)[2]), "=r"((r)[3]) : "r"(addr))

#define LDSM4T(r, addr)                                                          \
    asm volatile("ldmatrix.sync.aligned.m8n8.x4.trans.shared.b16 {%0,%1,%2,%3}, [%4];" \
        : "=r"((r)[0]), "=r"((r)[1]), "=r"((r)[2]), "=r"((r)[3]) : "r"(addr))

#define MMA_F16(d, a, b0, b1)                                                    \
    asm volatile("mma.sync.aligned.m16n8k16.row.col.f32.f16.f16.f32 "            \
        "{%0,%1,%2,%3}, {%4,%5,%6,%7}, {%8,%9}, {%0,%1,%2,%3};"                  \
        : "+f"((d)[0]), "+f"((d)[1]), "+f"((d)[2]), "+f"((d)[3])                 \
        : "r"((a)[0]), "r"((a)[1]), "r"((a)[2]), "r"((a)[3]), "r"(b0), "r"(b1))

#define CP_ASYNC16(dst, src)                                                     \
    asm volatile("cp.async.cg.shared.global [%0], [%1], 16;" :: "r"(dst), "l"(src) : "memory")
#define CP_COMMIT()  asm volatile("cp.async.commit_group;" ::: "memory")
#define CP_WAIT1()   asm volatile("cp.async.wait_group 1;" ::: "memory")
#define CP_WAIT0()   asm volatile("cp.async.wait_group 0;" ::: "memory")

__device__ __forceinline__ uint32_t pack_f16(float lo, float hi) {
    uint32_t r;
    asm("cvt.rn.f16x2.f32 %0, %1, %2;" : "=r"(r) : "f"(hi), "f"(lo));
    return r;
}

__device__ __forceinline__ float fast_exp(float x) {
    float t = fmaxf(x * 1.4426950408889634f, -126.0f);
    float fi = floorf(t);
    float f = t - fi;
    float p = 1.54035304e-4f;
    p = fmaf(p, f, 1.33335581e-3f);
    p = fmaf(p, f, 9.61812911e-3f);
    p = fmaf(p, f, 5.55041087e-2f);
    p = fmaf(p, f, 2.40226507e-1f);
    p = fmaf(p, f, 6.93147181e-1f);
    p = fmaf(p, f, 1.0f);
    return p * __uint_as_float(((uint32_t)((int)fi + 127)) << 23);
}

// ---------------- unified prep kernel (grid-sectioned) -------------------------
// section A: hs fp32 -> fp16 (16384 blocks)
// section B: Wq|Wk|Wv transpose -> fp16 (12288 blocks)
// section C: Wo transpose -> fp16 (4096 blocks)
#define PREP_A 16384
#define PREP_B 12288
#define PREP_C 4096

__global__ void prep_all(const float* __restrict__ hs,
                         const float* __restrict__ Wq, const float* __restrict__ Wk,
                         const float* __restrict__ Wv, const float* __restrict__ Wo,
                         __half* __restrict__ hsh, __half* __restrict__ wqkvT,
                         __half* __restrict__ woT)
{
    __shared__ float t[32][33];
    int bid = blockIdx.x;
    int tid = threadIdx.x;

    if (bid < PREP_A) {
        int i = bid * 256 + tid;    // float4 index
        float4 v = ((const float4*)hs)[i];
        __half hh[4];
        hh[0] = __float2half_rn(v.x); hh[1] = __float2half_rn(v.y);
        hh[2] = __float2half_rn(v.z); hh[3] = __float2half_rn(v.w);
        ((uint2*)hsh)[i] = *(uint2*)hh;
        return;
    }

    int x = tid & 31, y = tid >> 5;   // 32 x 8
    if (bid < PREP_A + PREP_B) {
        int b2 = bid - PREP_A;
        int n0 = (b2 % (QKVN / 32)) * 32;
        int k0 = (b2 / (QKVN / 32)) * 32;
        const float* W; int srcN, sn0;
        if (n0 < QDIM)              { W = Wq; srcN = QDIM;  sn0 = n0; }
        else if (n0 < QDIM + KVDIM) { W = Wk; srcN = KVDIM; sn0 = n0 - QDIM; }
        else                        { W = Wv; srcN = KVDIM; sn0 = n0 - QDIM - KVDIM; }
        #pragma unroll
        for (int i = 0; i < 32; i += 8)
            t[y + i][x] = W[(size_t)(k0 + y + i) * srcN + sn0 + x];
        __syncthreads();
        #pragma unroll
        for (int i = 0; i < 32; i += 8)
            wqkvT[(size_t)(n0 + y + i) * DIN + k0 + x] = __float2half_rn(t[x][y + i]);
    } else {
        int b3 = bid - PREP_A - PREP_B;
        int n0 = (b3 % (DOUT / 32)) * 32;
        int k0 = (b3 / (DOUT / 32)) * 32;
        #pragma unroll
        for (int i = 0; i < 32; i += 8)
            t[y + i][x] = Wo[(size_t)(k0 + y + i) * DOUT + n0 + x];
        __syncthreads();
        #pragma unroll
        for (int i = 0; i < 32; i += 8)
            woT[(size_t)(n0 + y + i) * QDIM + k0 + x] = __float2half_rn(t[x][y + i]);
    }
}

// ---------------- 1-term fp16 HMMA GEMM core (3-stage) --------------------------
#define AST 40
#define TILE_E (128*AST)
#define STAGE_E (2*TILE_E)
#define NSTAGE 3
#define GEMM_SMEM (NSTAGE * STAGE_E * 2)   // 61440 B

__device__ __forceinline__ void load_stage(
    uint32_t sbase_bytes, int tid, int bm, int bn, int k0, int K,
    const __half* __restrict__ A, const __half* __restrict__ B)
{
    #pragma unroll
    for (int i = 0; i < 4; i++) {
        int cid = tid + i * 256;
        int arr = cid >> 9;
        int rem = cid & 511;
        int row = rem >> 2;
        int c16 = rem & 3;
        const __half* g = (arr == 0)
            ? A + (size_t)(bm + row) * K + k0 + c16 * 8
            : B + (size_t)(bn + row) * K + k0 + c16 * 8;
        uint32_t d = sbase_bytes + (uint32_t)(arr * TILE_E + row * AST + c16 * 8) * 2;
        CP_ASYNC16(d, g);
    }
    CP_COMMIT();
}

__device__ __forceinline__ void gemm_mainloop(
    float acc[2][8][4], uint32_t smb, int tid, int bm, int bn, int K,
    const __half* __restrict__ A, const __half* __restrict__ B)
{
    const int wid = tid >> 5;
    const int lane = tid & 31;
    const int wm = (wid & 3) * 32;
    const int wn = (wid >> 2) * 64;
    const int nch = K >> 5;

    load_stage(smb, tid, bm, bn, 0, K, A, B);
    load_stage(smb + STAGE_E * 2, tid, bm, bn, 32, K, A, B);

    int st = 0, pst = 2;
    for (int c = 0; c < nch; c++) {
        CP_WAIT1();
        __syncthreads();

        if (c + 2 < nch)
            load_stage(smb + (uint32_t)pst * STAGE_E * 2, tid, bm, bn,
                       (c + 2) << 5, K, A, B);

        uint32_t Ab = smb + (uint32_t)st * STAGE_E * 2;
        uint32_t Bb = Ab + TILE_E * 2;

        #pragma unroll
        for (int ks = 0; ks < 2; ks++) {
            uint32_t ah[2][4], bf[4][4];
            #pragma unroll
            for (int mt = 0; mt < 2; mt++) {
                int row = wm + mt * 16 + (lane & 15);
                int col = ks * 16 + ((lane >> 4) << 3);
                LDSM4(ah[mt], Ab + (uint32_t)(row * AST + col) * 2);
            }
            #pragma unroll
            for (int p = 0; p < 4; p++) {
                int row = wn + p * 16 + (lane & 7) + ((lane >> 4) << 3);
                int col = ks * 16 + (((lane >> 3) & 1) << 3);
                LDSM4(bf[p], Bb + (uint32_t)(row * AST + col) * 2);
            }
            #pragma unroll
            for (int mt = 0; mt < 2; mt++) {
                #pragma unroll
                for (int nt = 0; nt < 8; nt++) {
                    uint32_t b0 = bf[nt >> 1][(nt & 1) * 2];
                    uint32_t b1 = bf[nt >> 1][(nt & 1) * 2 + 1];
                    MMA_F16(acc[mt][nt], ah[mt], b0, b1);
                }
            }
        }
        st = (st == 2) ? 0 : st + 1;
        pst = (pst == 2) ? 0 : pst + 1;
    }
}

// O projection: fp32 C output
__global__ __launch_bounds__(256)
void hmma_gemm_c(const __half* __restrict__ A, const __half* __restrict__ B,
                 float* __restrict__ C, int M, int N, int K)
{
    extern __shared__ __half sm[];
    const int tid = threadIdx.x;
    const int wid = tid >> 5, lane = tid & 31;
    const int bm = blockIdx.y * 128, bn = blockIdx.x * 128;
    const int wm = (wid & 3) * 32, wn = (wid >> 2) * 64;

    float acc[2][8][4];
    #pragma unroll
    for (int mt = 0; mt < 2; mt++)
        #pragma unroll
        for (int nt = 0; nt < 8; nt++)
            #pragma unroll
            for (int j = 0; j < 4; j++) acc[mt][nt][j] = 0.f;

    gemm_mainloop(acc, smem_u32(sm), tid, bm, bn, K, A, B);

    #pragma unroll
    for (int mt = 0; mt < 2; mt++)
        #pragma unroll
        for (int nt = 0; nt < 8; nt++) {
            int r0  = bm + wm + mt * 16 + (lane >> 2);
            int col = bn + wn + nt * 8 + (lane & 3) * 2;
            *(float2*)&C[(size_t)r0 * N + col] = make_float2(acc[mt][nt][0], acc[mt][nt][1]);
            *(float2*)&C[(size_t)(r0 + 8) * N + col] = make_float2(acc[mt][nt][2], acc[mt][nt][3]);
        }
}

// QKV GEMM with fused RoPE epilogue: Q, K, V all single fp16
__global__ __launch_bounds__(256)
void hmma_gemm_qkv(const __half* __restrict__ A, const __half* __restrict__ B,
                   const int* __restrict__ pos,
                   __half* __restrict__ q, __half* __restrict__ k,
                   __half* __restrict__ v)
{
    extern __shared__ __half sm[];
    const int tid = threadIdx.x;
    const int wid = tid >> 5, lane = tid & 31;
    const int bm = blockIdx.y * 128, bn = blockIdx.x * 128;
    const int wm = (wid & 3) * 32, wn = (wid >> 2) * 64;

    float acc[2][8][4];
    #pragma unroll
    for (int mt = 0; mt < 2; mt++)
        #pragma unroll
        for (int nt = 0; nt < 8; nt++)
            #pragma unroll
            for (int j = 0; j < 4; j++) acc[mt][nt][j] = 0.f;

    gemm_mainloop(acc, smem_u32(sm), tid, bm, bn, DIN, A, B);

    const int ncol0 = bn + wn;   // 64-aligned: one head per warp
    if (ncol0 >= QDIM + KVDIM) {
        // V: single fp16
        int colb = ncol0 - (QDIM + KVDIM) + (lane & 3) * 2;
        #pragma unroll
        for (int mt = 0; mt < 2; mt++)
            #pragma unroll
            for (int nt = 0; nt < 8; nt++)
                #pragma unroll
                for (int rs = 0; rs < 2; rs++) {
                    int m = bm + wm + mt * 16 + (lane >> 2) + rs * 8;
                    size_t o = (size_t)m * KVDIM + colb + nt * 8;
                    *(uint32_t*)&v[o] = pack_f16(acc[mt][nt][rs * 2], acc[mt][nt][rs * 2 + 1]);
                }
    } else {
        const int isQ = ncol0 < QDIM;
        const float scale = isQ ? 0.125f : 1.0f;
        __half* dst = isQ ? q : k;
        const int stride = isQ ? QDIM : KVDIM;
        const int colbase = isQ ? ncol0 : ncol0 - QDIM;
        #pragma unroll
        for (int mt = 0; mt < 2; mt++)
            #pragma unroll
            for (int rs = 0; rs < 2; rs++) {
                int m = bm + wm + mt * 16 + (lane >> 2) + rs * 8;
                float pf = (float)pos[m];
                #pragma unroll
                for (int nt = 0; nt < 4; nt++) {
                    int jp0 = nt * 8 + (lane & 3) * 2;
                    float y1[2], y2[2];
                    #pragma unroll
                    for (int c = 0; c < 2; c++) {
                        float inv = exp2f(-(float)(jp0 + c) * (13.287712379549449f / 32.0f));
                        float ang = pf * inv;
                        float s, cs;
                        sincosf(ang, &s, &cs);
                        float v1 = acc[mt][nt][rs * 2 + c];
                        float v2 = acc[mt][nt + 4][rs * 2 + c];
                        y1[c] = (v1 * cs - v2 * s) * scale;
                        y2[c] = (v2 * cs + v1 * s) * scale;
                    }
                    size_t o = (size_t)m * stride + colbase + jp0;
                    *(uint32_t*)&dst[o]      = pack_f16(y1[0], y1[1]);
                    *(uint32_t*)&dst[o + 32] = pack_f16(y2[0], y2[1]);
                }
            }
    }
}

// ---------------- HMMA flash attention (QK 1-term, PV 1-term) ------------------
#define QST 72
#define ATT_Q_E  (256*QST)
#define ATT_KV_E (64*QST)
#define ATT_KV_STAGE (2*ATT_KV_E*2)       // K | V
#define ATT_QBYTES (ATT_Q_E*2)
#define ATT_SMEM (ATT_QBYTES + 3*ATT_KV_STAGE)   // 92160 B

__device__ __forceinline__ void attn_load_kv(
    uint32_t stage_base, int tid, int b, int kvh, int kt,
    const __half* __restrict__ k, const __half* __restrict__ v)
{
    #pragma unroll
    for (int it = 0; it < 4; it++) {
        int cid = tid + it * 256;       // 0..1023
        int arr = cid >> 9;             // 0:K 1:V
        int rem = cid & 511;
        int row = rem >> 3;
        int c   = rem & 7;
        const __half* base = (arr == 0) ? k : v;
        const __half* src = base + (size_t)(b * SS + kt * 64 + row) * KVDIM + kvh * 64 + c * 8;
        CP_ASYNC16(stage_base + (uint32_t)arr * ATT_KV_E * 2 + (uint32_t)(row * QST + c * 8) * 2, src);
    }
    CP_COMMIT();
}

__global__ __launch_bounds__(256, 1)
void attn_hmma(const __half* __restrict__ q, const __half* __restrict__ k,
               const __half* __restrict__ v, __half* __restrict__ ao)
{
    extern __shared__ __half smatt[];
    const int qt  = gridDim.x - 1 - blockIdx.x;
    const int kvh = blockIdx.y;
    const int b   = blockIdx.z;
    const int tid = threadIdx.x, wid = tid >> 5, lane = tid & 31;

    const uint32_t smb = smem_u32(smatt);
    const uint32_t Q_o = smb;

    // Q tile load (256 rows x 64 cols single)
    #pragma unroll
    for (int it = 0; it < 8; it++) {
        int cid = tid + it * 256;
        int row = cid >> 3;
        int c   = cid & 7;
        const __half* src = q
            + (size_t)(b * SS + qt * 64 + (row & 63)) * QDIM
            + (kvh * 4 + (row >> 6)) * 64 + c * 8;
        CP_ASYNC16(Q_o + (uint32_t)(row * QST + c * 8) * 2, src);
    }
    CP_COMMIT();

    attn_load_kv(smb + ATT_QBYTES, tid, b, kvh, 0, k, v);
    if (qt >= 1)
        attn_load_kv(smb + ATT_QBYTES + ATT_KV_STAGE, tid, b, kvh, 1, k, v);

    float m_r[2][2], l_r[2][2], oacc[2][8][4];
    #pragma unroll
    for (int mt = 0; mt < 2; mt++) {
        m_r[mt][0] = -1e30f; m_r[mt][1] = -1e30f;
        l_r[mt][0] = 0.f;    l_r[mt][1] = 0.f;
        #pragma unroll
        for (int nt = 0; nt < 8; nt++)
            #pragma unroll
            for (int j = 0; j < 4; j++) oacc[mt][nt][j] = 0.f;
    }

    const int wrow  = wid * 32;
    const int hloc  = wid >> 1;
    const int rtile = (wid & 1) * 32;

    int st = 0;
    for (int kt = 0; kt <= qt; kt++) {
        if (kt < qt) CP_WAIT1(); else CP_WAIT0();
        __syncthreads();

        if (kt + 2 <= qt)
            attn_load_kv(smb + ATT_QBYTES + (uint32_t)((kt + 2) % 3) * ATT_KV_STAGE,
                         tid, b, kvh, kt + 2, k, v);

        const uint32_t stg = smb + ATT_QBYTES + (uint32_t)st * ATT_KV_STAGE;
        const uint32_t K_o = stg;
        const uint32_t V_o = stg + ATT_KV_E * 2;

        // ---- S = Q K^T (1-term)
        float sacc[2][8][4];
        #pragma unroll
        for (int mt = 0; mt < 2; mt++)
            #pragma unroll
            for (int nt = 0; nt < 8; nt++)
                #pragma unroll
                for (int j = 0; j < 4; j++) sacc[mt][nt][j] = 0.f;

        #pragma unroll
        for (int ks = 0; ks < 4; ks++) {
            uint32_t qa[2][4], kb[4][4];
            #pragma unroll
            for (int mt = 0; mt < 2; mt++) {
                int row = wrow + mt * 16 + (lane & 15);
                int col = ks * 16 + ((lane >> 4) << 3);
                LDSM4(qa[mt], Q_o + (uint32_t)(row * QST + col) * 2);
            }
            #pragma unroll
            for (int p = 0; p < 4; p++) {
                int row = p * 16 + (lane & 7) + ((lane >> 4) << 3);
                int col = ks * 16 + (((lane >> 3) & 1) << 3);
                LDSM4(kb[p], K_o + (uint32_t)(row * QST + col) * 2);
            }
            #pragma unroll
            for (int mt = 0; mt < 2; mt++) {
                #pragma unroll
                for (int nt = 0; nt < 8; nt++) {
                    uint32_t b0 = kb[nt >> 1][(nt & 1) * 2];
                    uint32_t b1 = kb[nt >> 1][(nt & 1) * 2 + 1];
                    MMA_F16(sacc[mt][nt], qa[mt], b0, b1);
                }
            }
        }

        if (kt == qt) {
            #pragma unroll
            for (int mt = 0; mt < 2; mt++)
                #pragma unroll
                for (int nt = 0; nt < 8; nt++)
                    #pragma unroll
                    for (int cc = 0; cc < 4; cc++) {
                        int rloc = rtile + mt * 16 + (lane >> 2) + ((cc >= 2) ? 8 : 0);
                        int cloc = nt * 8 + (lane & 3) * 2 + (cc & 1);
                        if (cloc > rloc) sacc[mt][nt][cc] = -1e30f;
                    }
        }

        // ---- online softmax
        #pragma unroll
        for (int mt = 0; mt < 2; mt++) {
            float mx0 = -1e30f, mx1 = -1e30f;
            #pragma unroll
            for (int nt = 0; nt < 8; nt++) {
                mx0 = fmaxf(mx0, fmaxf(sacc[mt][nt][0], sacc[mt][nt][1]));
                mx1 = fmaxf(mx1, fmaxf(sacc[mt][nt][2], sacc[mt][nt][3]));
            }
            mx0 = fmaxf(mx0, __shfl_xor_sync(0xffffffffu, mx0, 1));
            mx0 = fmaxf(mx0, __shfl_xor_sync(0xffffffffu, mx0, 2));
            mx1 = fmaxf(mx1, __shfl_xor_sync(0xffffffffu, mx1, 1));
            mx1 = fmaxf(mx1, __shfl_xor_sync(0xffffffffu, mx1, 2));
            float mn0 = fmaxf(m_r[mt][0], mx0);
            float mn1 = fmaxf(m_r[mt][1], mx1);
            float sc0 = fast_exp(m_r[mt][0] - mn0);
            float sc1 = fast_exp(m_r[mt][1] - mn1);
            m_r[mt][0] = mn0; m_r[mt][1] = mn1;
            float sum0 = 0.f, sum1 = 0.f;
            #pragma unroll
            for (int nt = 0; nt < 8; nt++) {
                float p0 = fast_exp(sacc[mt][nt][0] - mn0);
                float p1 = fast_exp(sacc[mt][nt][1] - mn0);
                float p2 = fast_exp(sacc[mt][nt][2] - mn1);
                float p3 = fast_exp(sacc[mt][nt][3] - mn1);
                sacc[mt][nt][0] = p0; sacc[mt][nt][1] = p1;
                sacc[mt][nt][2] = p2; sacc[mt][nt][3] = p3;
                sum0 += p0 + p1; sum1 += p2 + p3;
                oacc[mt][nt][0] *= sc0; oacc[mt][nt][1] *= sc0;
                oacc[mt][nt][2] *= sc1; oacc[mt][nt][3] *= sc1;
            }
            l_r[mt][0] = l_r[mt][0] * sc0 + sum0;
            l_r[mt][1] = l_r[mt][1] * sc1 + sum1;
        }

        // ---- O += P V (1-term)
        #pragma unroll
        for (int j = 0; j < 4; j++) {
            uint32_t vb[4][4];
            int tok_off = (lane & 7) + (((lane >> 3) & 1) << 3);
            int d_off   = ((lane >> 4) & 1) << 3;
            #pragma unroll
            for (int p = 0; p < 4; p++) {
                uint32_t off = (uint32_t)((j * 16 + tok_off) * QST + p * 16 + d_off) * 2;
                LDSM4T(vb[p], V_o + off);
            }
            #pragma unroll
            for (int mt = 0; mt < 2; mt++) {
                uint32_t ah[4];
                #pragma unroll
                for (int qd = 0; qd < 4; qd++) {
                    int nt = 2 * j + (qd >> 1);
                    ah[qd] = pack_f16(sacc[mt][nt][(qd & 1) * 2], sacc[mt][nt][(qd & 1) * 2 + 1]);
                }
                #pragma unroll
                for (int nt = 0; nt < 8; nt++) {
                    uint32_t b0 = vb[nt >> 1][(nt & 1) * 2];
                    uint32_t b1 = vb[nt >> 1][(nt & 1) * 2 + 1];
                    MMA_F16(oacc[mt][nt], ah, b0, b1);
                }
            }
        }
        st = (st == 2) ? 0 : st + 1;
    }

    // ---- epilogue: normalize + fp16 single output
    #pragma unroll
    for (int mt = 0; mt < 2; mt++) {
        l_r[mt][0] += __shfl_xor_sync(0xffffffffu, l_r[mt][0], 1);
        l_r[mt][0] += __shfl_xor_sync(0xffffffffu, l_r[mt][0], 2);
        l_r[mt][1] += __shfl_xor_sync(0xffffffffu, l_r[mt][1], 1);
        l_r[mt][1] += __shfl_xor_sync(0xffffffffu, l_r[mt][1], 2);
        float inv0 = 1.0f / l_r[mt][0];
        float inv1 = 1.0f / l_r[mt][1];
        int tok = qt * 64 + rtile + mt * 16 + (lane >> 2);
        int colb = (kvh * 4 + hloc) * 64 + (lane & 3) * 2;
        #pragma unroll
        for (int nt = 0; nt < 8; nt++) {
            size_t o0 = (size_t)(b * SS + tok) * QDIM + colb + nt * 8;
            size_t o1 = o0 + (size_t)8 * QDIM;
            *(uint32_t*)&ao[o0] = pack_f16(oacc[mt][nt][0] * inv0, oacc[mt][nt][1] * inv0);
            *(uint32_t*)&ao[o1] = pack_f16(oacc[mt][nt][2] * inv1, oacc[mt][nt][3] * inv1);
        }
    }
}

// ---------------------------------------------------------------------------
extern "C" void kernel_launch(void* const* d_in, const int* in_sizes, int n_in,
                              void* d_out, int out_size)
{
    (void)in_sizes; (void)n_in; (void)out_size;
    const float* hs  = (const float*)d_in[0];
    const int*   pos = (const int*)d_in[2];
    const float* Wq  = (const float*)d_in[3];
    const float* Wk  = (const float*)d_in[4];
    const float* Wv  = (const float*)d_in[5];
    const float* Wo  = (const float*)d_in[6];
    float* out = (float*)d_out;

    __half *hsb, *q, *k, *v, *ao, *w, *wo;
    cudaGetSymbolAddress((void**)&hsb, g_hs);
    cudaGetSymbolAddress((void**)&q,  g_q);
    cudaGetSymbolAddress((void**)&k,  g_k);
    cudaGetSymbolAddress((void**)&v,  g_v);
    cudaGetSymbolAddress((void**)&ao, g_ao);
    cudaGetSymbolAddress((void**)&w,  g_wqkvT);
    cudaGetSymbolAddress((void**)&wo, g_woT);

    const int M = MTOT;
    cudaFuncSetAttribute(hmma_gemm_c,   cudaFuncAttributeMaxDynamicSharedMemorySize, GEMM_SMEM);
    cudaFuncSetAttribute(hmma_gemm_qkv, cudaFuncAttributeMaxDynamicSharedMemorySize, GEMM_SMEM);
    cudaFuncSetAttribute(attn_hmma,     cudaFuncAttributeMaxDynamicSharedMemorySize, ATT_SMEM);

    prep_all<<<PREP_A + PREP_B + PREP_C, 256>>>(hs, Wq, Wk, Wv, Wo, hsb, w, wo);              // 1
    hmma_gemm_qkv<<<dim3(QKVN / 128, M / 128), 256, GEMM_SMEM>>>(hsb, w, pos, q, k, v);       // 2
    attn_hmma<<<dim3(SS / 64, NKV, BB), 256, ATT_SMEM>>>(q, k, v, ao);                        // 3
    hmma_gemm_c<<<dim3(DOUT / 128, M / 128), 256, GEMM_SMEM>>>(ao, wo, out, M, DOUT, QDIM);   // 4
}

// round 12
// speedup vs baseline: 2.7412x; 1.0590x over previous
#include <cuda_runtime.h>
#include <cuda_fp16.h>
#include <math.h>
#include <stdint.h>

#define BB 2
#define SS 2048
#define DIN 4096
#define NH 32
#define NKV 8
#define HD 64
#define QDIM 2048
#define KVDIM 512
#define QKVN 3072
#define DOUT 2048
#define MTOT 4096

// ---------------- scratch (__device__ globals) ------------------------------
__device__ __half g_hs[MTOT*DIN];            // hidden states, fp16 single
__device__ __half g_q[MTOT*QDIM];            // roped, pre-scaled Q (single)
__device__ __half g_k[MTOT*KVDIM];           // roped K (single)
__device__ __half g_v[MTOT*KVDIM];           // V (single)
__device__ __half g_ao[MTOT*QDIM];           // attention out, fp16 single
__device__ __half g_wqkvT[QKVN*DIN];         // weights fp16 single
__device__ __half g_woT[DOUT*QDIM];

// ---------------- helpers ----------------------------------------------------
__device__ __forceinline__ uint32_t smem_u32(const void* p) {
    uint32_t a;
    asm("{ .reg .u64 t; cvta.to.shared.u64 t, %1; cvt.u32.u64 %0, t; }" : "=r"(a) : "l"(p));
    return a;
}

#define LDSM4(r, addr)                                                           \
    asm volatile("ldmatrix.sync.aligned.m8n8.x4.shared.b16 {%0,%1,%2,%3}, [%4];" \
        : "=r"((r)[0]), "=r"((r)[1]), "=r"((r)[2]), "=r"((r)[3]) : "r"(addr))

#define LDSM4T(r, addr)                                                          \
    asm volatile("ldmatrix.sync.aligned.m8n8.x4.trans.shared.b16 {%0,%1,%2,%3}, [%4];" \
        : "=r"((r)[0]), "=r"((r)[1]), "=r"((r)[2]), "=r"((r)[3]) : "r"(addr))

#define MMA_F16(d, a, b0, b1)                                                    \
    asm volatile("mma.sync.aligned.m16n8k16.row.col.f32.f16.f16.f32 "            \
        "{%0,%1,%2,%3}, {%4,%5,%6,%7}, {%8,%9}, {%0,%1,%2,%3};"                  \
        : "+f"((d)[0]), "+f"((d)[1]), "+f"((d)[2]), "+f"((d)[3])                 \
        : "r"((a)[0]), "r"((a)[1]), "r"((a)[2]), "r"((a)[3]), "r"(b0), "r"(b1))

#define CP_ASYNC16(dst, src)                                                     \
    asm volatile("cp.async.cg.shared.global [%0], [%1], 16;" :: "r"(dst), "l"(src) : "memory")
#define CP_COMMIT()  asm volatile("cp.async.commit_group;" ::: "memory")
#define CP_WAIT1()   asm volatile("cp.async.wait_group 1;" ::: "memory")
#define CP_WAIT0()   asm volatile("cp.async.wait_group 0;" ::: "memory")

__device__ __forceinline__ uint32_t pack_f16(float lo, float hi) {
    uint32_t r;
    asm("cvt.rn.f16x2.f32 %0, %1, %2;" : "=r"(r) : "f"(hi), "f"(lo));
    return r;
}

__device__ __forceinline__ float fast_exp(float x) {
    float t = fmaxf(x * 1.4426950408889634f, -126.0f);
    float fi = floorf(t);
    float f = t - fi;
    float p = 1.54035304e-4f;
    p = fmaf(p, f, 1.33335581e-3f);
    p = fmaf(p, f, 9.61812911e-3f);
    p = fmaf(p, f, 5.55041087e-2f);
    p = fmaf(p, f, 2.40226507e-1f);
    p = fmaf(p, f, 6.93147181e-1f);
    p = fmaf(p, f, 1.0f);
    return p * __uint_as_float(((uint32_t)((int)fi + 127)) << 23);
}

// ---------------- unified prep kernel (grid-sectioned) -------------------------
#define PREP_A 16384
#define PREP_B 12288
#define PREP_C 4096

__global__ void prep_all(const float* __restrict__ hs,
                         const float* __restrict__ Wq, const float* __restrict__ Wk,
                         const float* __restrict__ Wv, const float* __restrict__ Wo,
                         __half* __restrict__ hsh, __half* __restrict__ wqkvT,
                         __half* __restrict__ woT)
{
    __shared__ float t[32][33];
    int bid = blockIdx.x;
    int tid = threadIdx.x;

    if (bid < PREP_A) {
        int i = bid * 256 + tid;
        float4 v = ((const float4*)hs)[i];
        __half hh[4];
        hh[0] = __float2half_rn(v.x); hh[1] = __float2half_rn(v.y);
        hh[2] = __float2half_rn(v.z); hh[3] = __float2half_rn(v.w);
        ((uint2*)hsh)[i] = *(uint2*)hh;
        return;
    }

    int x = tid & 31, y = tid >> 5;
    if (bid < PREP_A + PREP_B) {
        int b2 = bid - PREP_A;
        int n0 = (b2 % (QKVN / 32)) * 32;
        int k0 = (b2 / (QKVN / 32)) * 32;
        const float* W; int srcN, sn0;
        if (n0 < QDIM)              { W = Wq; srcN = QDIM;  sn0 = n0; }
        else if (n0 < QDIM + KVDIM) { W = Wk; srcN = KVDIM; sn0 = n0 - QDIM; }
        else                        { W = Wv; srcN = KVDIM; sn0 = n0 - QDIM - KVDIM; }
        #pragma unroll
        for (int i = 0; i < 32; i += 8)
            t[y + i][x] = W[(size_t)(k0 + y + i) * srcN + sn0 + x];
        __syncthreads();
        #pragma unroll
        for (int i = 0; i < 32; i += 8)
            wqkvT[(size_t)(n0 + y + i) * DIN + k0 + x] = __float2half_rn(t[x][y + i]);
    } else {
        int b3 = bid - PREP_A - PREP_B;
        int n0 = (b3 % (DOUT / 32)) * 32;
        int k0 = (b3 / (DOUT / 32)) * 32;
        #pragma unroll
        for (int i = 0; i < 32; i += 8)
            t[y + i][x] = Wo[(size_t)(k0 + y + i) * DOUT + n0 + x];
        __syncthreads();
        #pragma unroll
        for (int i = 0; i < 32; i += 8)
            woT[(size_t)(n0 + y + i) * QDIM + k0 + x] = __float2half_rn(t[x][y + i]);
    }
}

// ---------------- 1-term fp16 HMMA GEMM core (3-stage, 2 CTAs/SM) --------------
#define AST 40
#define TILE_E (128*AST)
#define STAGE_E (2*TILE_E)
#define NSTAGE 3
#define GEMM_SMEM (NSTAGE * STAGE_E * 2)   // 61440 B -> 2 CTAs/SM = 122880 B

__device__ __forceinline__ void load_stage(
    uint32_t sbase_bytes, int tid, int bm, int bn, int k0, int K,
    const __half* __restrict__ A, const __half* __restrict__ B)
{
    #pragma unroll
    for (int i = 0; i < 4; i++) {
        int cid = tid + i * 256;
        int arr = cid >> 9;
        int rem = cid & 511;
        int row = rem >> 2;
        int c16 = rem & 3;
        const __half* g = (arr == 0)
            ? A + (size_t)(bm + row) * K + k0 + c16 * 8
            : B + (size_t)(bn + row) * K + k0 + c16 * 8;
        uint32_t d = sbase_bytes + (uint32_t)(arr * TILE_E + row * AST + c16 * 8) * 2;
        CP_ASYNC16(d, g);
    }
    CP_COMMIT();
}

__device__ __forceinline__ void gemm_mainloop(
    float acc[2][8][4], uint32_t smb, int tid, int bm, int bn, int K,
    const __half* __restrict__ A, const __half* __restrict__ B)
{
    const int wid = tid >> 5;
    const int lane = tid & 31;
    const int wm = (wid & 3) * 32;
    const int wn = (wid >> 2) * 64;
    const int nch = K >> 5;

    load_stage(smb, tid, bm, bn, 0, K, A, B);
    load_stage(smb + STAGE_E * 2, tid, bm, bn, 32, K, A, B);

    int st = 0, pst = 2;
    for (int c = 0; c < nch; c++) {
        CP_WAIT1();
        __syncthreads();

        if (c + 2 < nch)
            load_stage(smb + (uint32_t)pst * STAGE_E * 2, tid, bm, bn,
                       (c + 2) << 5, K, A, B);

        uint32_t Ab = smb + (uint32_t)st * STAGE_E * 2;
        uint32_t Bb = Ab + TILE_E * 2;

        #pragma unroll
        for (int ks = 0; ks < 2; ks++) {
            uint32_t ah[2][4], bf[4][4];
            #pragma unroll
            for (int mt = 0; mt < 2; mt++) {
                int row = wm + mt * 16 + (lane & 15);
                int col = ks * 16 + ((lane >> 4) << 3);
                LDSM4(ah[mt], Ab + (uint32_t)(row * AST + col) * 2);
            }
            #pragma unroll
            for (int p = 0; p < 4; p++) {
                int row = wn + p * 16 + (lane & 7) + ((lane >> 4) << 3);
                int col = ks * 16 + (((lane >> 3) & 1) << 3);
                LDSM4(bf[p], Bb + (uint32_t)(row * AST + col) * 2);
            }
            #pragma unroll
            for (int mt = 0; mt < 2; mt++) {
                #pragma unroll
                for (int nt = 0; nt < 8; nt++) {
                    uint32_t b0 = bf[nt >> 1][(nt & 1) * 2];
                    uint32_t b1 = bf[nt >> 1][(nt & 1) * 2 + 1];
                    MMA_F16(acc[mt][nt], ah[mt], b0, b1);
                }
            }
        }
        st = (st == 2) ? 0 : st + 1;
        pst = (pst == 2) ? 0 : pst + 1;
    }
}

// O projection: fp32 C output (2 CTAs/SM)
__global__ __launch_bounds__(256, 2)
void hmma_gemm_c(const __half* __restrict__ A, const __half* __restrict__ B,
                 float* __restrict__ C, int M, int N, int K)
{
    extern __shared__ __half sm[];
    const int tid = threadIdx.x;
    const int wid = tid >> 5, lane = tid & 31;
    const int bm = blockIdx.y * 128, bn = blockIdx.x * 128;
    const int wm = (wid & 3) * 32, wn = (wid >> 2) * 64;

    float acc[2][8][4];
    #pragma unroll
    for (int mt = 0; mt < 2; mt++)
        #pragma unroll
        for (int nt = 0; nt < 8; nt++)
            #pragma unroll
            for (int j = 0; j < 4; j++) acc[mt][nt][j] = 0.f;

    gemm_mainloop(acc, smem_u32(sm), tid, bm, bn, K, A, B);

    #pragma unroll
    for (int mt = 0; mt < 2; mt++)
        #pragma unroll
        for (int nt = 0; nt < 8; nt++) {
            int r0  = bm + wm + mt * 16 + (lane >> 2);
            int col = bn + wn + nt * 8 + (lane & 3) * 2;
            *(float2*)&C[(size_t)r0 * N + col] = make_float2(acc[mt][nt][0], acc[mt][nt][1]);
            *(float2*)&C[(size_t)(r0 + 8) * N + col] = make_float2(acc[mt][nt][2], acc[mt][nt][3]);
        }
}

// QKV GEMM with fused RoPE epilogue (2 CTAs/SM)
__global__ __launch_bounds__(256, 2)
void hmma_gemm_qkv(const __half* __restrict__ A, const __half* __restrict__ B,
                   const int* __restrict__ pos,
                   __half* __restrict__ q, __half* __restrict__ k,
                   __half* __restrict__ v)
{
    extern __shared__ __half sm[];
    const int tid = threadIdx.x;
    const int wid = tid >> 5, lane = tid & 31;
    const int bm = blockIdx.y * 128, bn = blockIdx.x * 128;
    const int wm = (wid & 3) * 32, wn = (wid >> 2) * 64;

    float acc[2][8][4];
    #pragma unroll
    for (int mt = 0; mt < 2; mt++)
        #pragma unroll
        for (int nt = 0; nt < 8; nt++)
            #pragma unroll
            for (int j = 0; j < 4; j++) acc[mt][nt][j] = 0.f;

    gemm_mainloop(acc, smem_u32(sm), tid, bm, bn, DIN, A, B);

    const int ncol0 = bn + wn;   // 64-aligned: one head per warp
    if (ncol0 >= QDIM + KVDIM) {
        int colb = ncol0 - (QDIM + KVDIM) + (lane & 3) * 2;
        #pragma unroll
        for (int mt = 0; mt < 2; mt++)
            #pragma unroll
            for (int nt = 0; nt < 8; nt++)
                #pragma unroll
                for (int rs = 0; rs < 2; rs++) {
                    int m = bm + wm + mt * 16 + (lane >> 2) + rs * 8;
                    size_t o = (size_t)m * KVDIM + colb + nt * 8;
                    *(uint32_t*)&v[o] = pack_f16(acc[mt][nt][rs * 2], acc[mt][nt][rs * 2 + 1]);
                }
    } else {
        const int isQ = ncol0 < QDIM;
        const float scale = isQ ? 0.125f : 1.0f;
        __half* dst = isQ ? q : k;
        const int stride = isQ ? QDIM : KVDIM;
        const int colbase = isQ ? ncol0 : ncol0 - QDIM;
        #pragma unroll
        for (int mt = 0; mt < 2; mt++)
            #pragma unroll
            for (int rs = 0; rs < 2; rs++) {
                int m = bm + wm + mt * 16 + (lane >> 2) + rs * 8;
                float pf = (float)pos[m];
                #pragma unroll
                for (int nt = 0; nt < 4; nt++) {
                    int jp0 = nt * 8 + (lane & 3) * 2;
                    float y1[2], y2[2];
                    #pragma unroll
                    for (int c = 0; c < 2; c++) {
                        float inv = exp2f(-(float)(jp0 + c) * (13.287712379549449f / 32.0f));
                        float ang = pf * inv;
                        float s, cs;
                        sincosf(ang, &s, &cs);
                        float v1 = acc[mt][nt][rs * 2 + c];
                        float v2 = acc[mt][nt + 4][rs * 2 + c];
                        y1[c] = (v1 * cs - v2 * s) * scale;
                        y2[c] = (v2 * cs + v1 * s) * scale;
                    }
                    size_t o = (size_t)m * stride + colbase + jp0;
                    *(uint32_t*)&dst[o]      = pack_f16(y1[0], y1[1]);
                    *(uint32_t*)&dst[o + 32] = pack_f16(y2[0], y2[1]);
                }
            }
    }
}

// ---------------- HMMA flash attention (QK 1-term, PV 1-term) ------------------
#define QST 72
#define ATT_Q_E  (256*QST)
#define ATT_KV_E (64*QST)
#define ATT_KV_STAGE (2*ATT_KV_E*2)
#define ATT_QBYTES (ATT_Q_E*2)
#define ATT_SMEM (ATT_QBYTES + 3*ATT_KV_STAGE)   // 92160 B

__device__ __forceinline__ void attn_load_kv(
    uint32_t stage_base, int tid, int b, int kvh, int kt,
    const __half* __restrict__ k, const __half* __restrict__ v)
{
    #pragma unroll
    for (int it = 0; it < 4; it++) {
        int cid = tid + it * 256;
        int arr = cid >> 9;
        int rem = cid & 511;
        int row = rem >> 3;
        int c   = rem & 7;
        const __half* base = (arr == 0) ? k : v;
        const __half* src = base + (size_t)(b * SS + kt * 64 + row) * KVDIM + kvh * 64 + c * 8;
        CP_ASYNC16(stage_base + (uint32_t)arr * ATT_KV_E * 2 + (uint32_t)(row * QST + c * 8) * 2, src);
    }
    CP_COMMIT();
}

__global__ __launch_bounds__(256, 1)
void attn_hmma(const __half* __restrict__ q, const __half* __restrict__ k,
               const __half* __restrict__ v, __half* __restrict__ ao)
{
    extern __shared__ __half smatt[];
    const int qt  = gridDim.x - 1 - blockIdx.x;
    const int kvh = blockIdx.y;
    const int b   = blockIdx.z;
    const int tid = threadIdx.x, wid = tid >> 5, lane = tid & 31;

    const uint32_t smb = smem_u32(smatt);
    const uint32_t Q_o = smb;

    #pragma unroll
    for (int it = 0; it < 8; it++) {
        int cid = tid + it * 256;
        int row = cid >> 3;
        int c   = cid & 7;
        const __half* src = q
            + (size_t)(b * SS + qt * 64 + (row & 63)) * QDIM
            + (kvh * 4 + (row >> 6)) * 64 + c * 8;
        CP_ASYNC16(Q_o + (uint32_t)(row * QST + c * 8) * 2, src);
    }
    CP_COMMIT();

    attn_load_kv(smb + ATT_QBYTES, tid, b, kvh, 0, k, v);
    if (qt >= 1)
        attn_load_kv(smb + ATT_QBYTES + ATT_KV_STAGE, tid, b, kvh, 1, k, v);

    float m_r[2][2], l_r[2][2], oacc[2][8][4];
    #pragma unroll
    for (int mt = 0; mt < 2; mt++) {
        m_r[mt][0] = -1e30f; m_r[mt][1] = -1e30f;
        l_r[mt][0] = 0.f;    l_r[mt][1] = 0.f;
        #pragma unroll
        for (int nt = 0; nt < 8; nt++)
            #pragma unroll
            for (int j = 0; j < 4; j++) oacc[mt][nt][j] = 0.f;
    }

    const int wrow  = wid * 32;
    const int hloc  = wid >> 1;
    const int rtile = (wid & 1) * 32;

    int st = 0;
    for (int kt = 0; kt <= qt; kt++) {
        if (kt < qt) CP_WAIT1(); else CP_WAIT0();
        __syncthreads();

        if (kt + 2 <= qt)
            attn_load_kv(smb + ATT_QBYTES + (uint32_t)((kt + 2) % 3) * ATT_KV_STAGE,
                         tid, b, kvh, kt + 2, k, v);

        const uint32_t stg = smb + ATT_QBYTES + (uint32_t)st * ATT_KV_STAGE;
        const uint32_t K_o = stg;
        const uint32_t V_o = stg + ATT_KV_E * 2;

        float sacc[2][8][4];
        #pragma unroll
        for (int mt = 0; mt < 2; mt++)
            #pragma unroll
            for (int nt = 0; nt < 8; nt++)
                #pragma unroll
                for (int j = 0; j < 4; j++) sacc[mt][nt][j] = 0.f;

        #pragma unroll
        for (int ks = 0; ks < 4; ks++) {
            uint32_t qa[2][4], kb[4][4];
            #pragma unroll
            for (int mt = 0; mt < 2; mt++) {
                int row = wrow + mt * 16 + (lane & 15);
                int col = ks * 16 + ((lane >> 4) << 3);
                LDSM4(qa[mt], Q_o + (uint32_t)(row * QST + col) * 2);
            }
            #pragma unroll
            for (int p = 0; p < 4; p++) {
                int row = p * 16 + (lane & 7) + ((lane >> 4) << 3);
                int col = ks * 16 + (((lane >> 3) & 1) << 3);
                LDSM4(kb[p], K_o + (uint32_t)(row * QST + col) * 2);
            }
            #pragma unroll
            for (int mt = 0; mt < 2; mt++) {
                #pragma unroll
                for (int nt = 0; nt < 8; nt++) {
                    uint32_t b0 = kb[nt >> 1][(nt & 1) * 2];
                    uint32_t b1 = kb[nt >> 1][(nt & 1) * 2 + 1];
                    MMA_F16(sacc[mt][nt], qa[mt], b0, b1);
                }
            }
        }

        if (kt == qt) {
            #pragma unroll
            for (int mt = 0; mt < 2; mt++)
                #pragma unroll
                for (int nt = 0; nt < 8; nt++)
                    #pragma unroll
                    for (int cc = 0; cc < 4; cc++) {
                        int rloc = rtile + mt * 16 + (lane >> 2) + ((cc >= 2) ? 8 : 0);
                        int cloc = nt * 8 + (lane & 3) * 2 + (cc & 1);
                        if (cloc > rloc) sacc[mt][nt][cc] = -1e30f;
                    }
        }

        #pragma unroll
        for (int mt = 0; mt < 2; mt++) {
            float mx0 = -1e30f, mx1 = -1e30f;
            #pragma unroll
            for (int nt = 0; nt < 8; nt++) {
                mx0 = fmaxf(mx0, fmaxf(sacc[mt][nt][0], sacc[mt][nt][1]));
                mx1 = fmaxf(mx1, fmaxf(sacc[mt][nt][2], sacc[mt][nt][3]));
            }
            mx0 = fmaxf(mx0, __shfl_xor_sync(0xffffffffu, mx0, 1));
            mx0 = fmaxf(mx0, __shfl_xor_sync(0xffffffffu, mx0, 2));
            mx1 = fmaxf(mx1, __shfl_xor_sync(0xffffffffu, mx1, 1));
            mx1 = fmaxf(mx1, __shfl_xor_sync(0xffffffffu, mx1, 2));
            float mn0 = fmaxf(m_r[mt][0], mx0);
            float mn1 = fmaxf(m_r[mt][1], mx1);
            float sc0 = fast_exp(m_r[mt][0] - mn0);
            float sc1 = fast_exp(m_r[mt][1] - mn1);
            m_r[mt][0] = mn0; m_r[mt][1] = mn1;
            float sum0 = 0.f, sum1 = 0.f;
            #pragma unroll
            for (int nt = 0; nt < 8; nt++) {
                float p0 = fast_exp(sacc[mt][nt][0] - mn0);
                float p1 = fast_exp(sacc[mt][nt][1] - mn0);
                float p2 = fast_exp(sacc[mt][nt][2] - mn1);
                float p3 = fast_exp(sacc[mt][nt][3] - mn1);
                sacc[mt][nt][0] = p0; sacc[mt][nt][1] = p1;
                sacc[mt][nt][2] = p2; sacc[mt][nt][3] = p3;
                sum0 += p0 + p1; sum1 += p2 + p3;
                oacc[mt][nt][0] *= sc0; oacc[mt][nt][1] *= sc0;
                oacc[mt][nt][2] *= sc1; oacc[mt][nt][3] *= sc1;
            }
            l_r[mt][0] = l_r[mt][0] * sc0 + sum0;
            l_r[mt][1] = l_r[mt][1] * sc1 + sum1;
        }

        #pragma unroll
        for (int j = 0; j < 4; j++) {
            uint32_t vb[4][4];
            int tok_off = (lane & 7) + (((lane >> 3) & 1) << 3);
            int d_off   = ((lane >> 4) & 1) << 3;
            #pragma unroll
            for (int p = 0; p < 4; p++) {
                uint32_t off = (uint32_t)((j * 16 + tok_off) * QST + p * 16 + d_off) * 2;
                LDSM4T(vb[p], V_o + off);
            }
            #pragma unroll
            for (int mt = 0; mt < 2; mt++) {
                uint32_t ah[4];
                #pragma unroll
                for (int qd = 0; qd < 4; qd++) {
                    int nt = 2 * j + (qd >> 1);
                    ah[qd] = pack_f16(sacc[mt][nt][(qd & 1) * 2], sacc[mt][nt][(qd & 1) * 2 + 1]);
                }
                #pragma unroll
                for (int nt = 0; nt < 8; nt++) {
                    uint32_t b0 = vb[nt >> 1][(nt & 1) * 2];
                    uint32_t b1 = vb[nt >> 1][(nt & 1) * 2 + 1];
                    MMA_F16(oacc[mt][nt], ah, b0, b1);
                }
            }
        }
        st = (st == 2) ? 0 : st + 1;
    }

    #pragma unroll
    for (int mt = 0; mt < 2; mt++) {
        l_r[mt][0] += __shfl_xor_sync(0xffffffffu, l_r[mt][0], 1);
        l_r[mt][0] += __shfl_xor_sync(0xffffffffu, l_r[mt][0], 2);
        l_r[mt][1] += __shfl_xor_sync(0xffffffffu, l_r[mt][1], 1);
        l_r[mt][1] += __shfl_xor_sync(0xffffffffu, l_r[mt][1], 2);
        float inv0 = 1.0f / l_r[mt][0];
        float inv1 = 1.0f / l_r[mt][1];
        int tok = qt * 64 + rtile + mt * 16 + (lane >> 2);
        int colb = (kvh * 4 + hloc) * 64 + (lane & 3) * 2;
        #pragma unroll
        for (int nt = 0; nt < 8; nt++) {
            size_t o0 = (size_t)(b * SS + tok) * QDIM + colb + nt * 8;
            size_t o1 = o0 + (size_t)8 * QDIM;
            *(uint32_t*)&ao[o0] = pack_f16(oacc[mt][nt][0] * inv0, oacc[mt][nt][1] * inv0);
            *(uint32_t*)&ao[o1] = pack_f16(oacc[mt][nt][2] * inv1, oacc[mt][nt][3] * inv1);
        }
    }
}

// ---------------------------------------------------------------------------
extern "C" void kernel_launch(void* const* d_in, const int* in_sizes, int n_in,
                              void* d_out, int out_size)
{
    (void)in_sizes; (void)n_in; (void)out_size;
    const float* hs  = (const float*)d_in[0];
    const int*   pos = (const int*)d_in[2];
    const float* Wq  = (const float*)d_in[3];
    const float* Wk  = (const float*)d_in[4];
    const float* Wv  = (const float*)d_in[5];
    const float* Wo  = (const float*)d_in[6];
    float* out = (float*)d_out;

    __half *hsb, *q, *k, *v, *ao, *w, *wo;
    cudaGetSymbolAddress((void**)&hsb, g_hs);
    cudaGetSymbolAddress((void**)&q,  g_q);
    cudaGetSymbolAddress((void**)&k,  g_k);
    cudaGetSymbolAddress((void**)&v,  g_v);
    cudaGetSymbolAddress((void**)&ao, g_ao);
    cudaGetSymbolAddress((void**)&w,  g_wqkvT);
    cudaGetSymbolAddress((void**)&wo, g_woT);

    const int M = MTOT;
    cudaFuncSetAttribute(hmma_gemm_c,   cudaFuncAttributeMaxDynamicSharedMemorySize, GEMM_SMEM);
    cudaFuncSetAttribute(hmma_gemm_qkv, cudaFuncAttributeMaxDynamicSharedMemorySize, GEMM_SMEM);
    cudaFuncSetAttribute(attn_hmma,     cudaFuncAttributeMaxDynamicSharedMemorySize, ATT_SMEM);

    prep_all<<<PREP_A + PREP_B + PREP_C, 256>>>(hs, Wq, Wk, Wv, Wo, hsb, w, wo);              // 1
    hmma_gemm_qkv<<<dim3(QKVN / 128, M / 128), 256, GEMM_SMEM>>>(hsb, w, pos, q, k, v);       // 2
    attn_hmma<<<dim3(SS / 64, NKV, BB), 256, ATT_SMEM>>>(q, k, v, ao);                        // 3
    hmma_gemm_c<<<dim3(DOUT / 128, M / 128), 256, GEMM_SMEM>>>(ao, wo, out, M, DOUT, QDIM);   // 4
}

// round 13
// speedup vs baseline: 2.7413x; 1.0000x over previous
#include <cuda_runtime.h>
#include <cuda_fp16.h>
#include <math.h>
#include <stdint.h>

#define BB 2
#define SS 2048
#define DIN 4096
#define NH 32
#define NKV 8
#define HD 64
#define QDIM 2048
#define KVDIM 512
#define QKVN 3072
#define DOUT 2048
#define MTOT 4096

// ---------------- scratch (__device__ globals) ------------------------------
__device__ __half g_hs[MTOT*DIN];            // hidden states, fp16 single
__device__ __half g_q[MTOT*QDIM];            // roped, pre-scaled Q (single)
__device__ __half g_k[MTOT*KVDIM];           // roped K (single)
__device__ __half g_v[MTOT*KVDIM];           // V (single)
__device__ __half g_ao[MTOT*QDIM];           // attention out, fp16 single
__device__ __half g_wqkvT[QKVN*DIN];         // weights fp16 single
__device__ __half g_woT[DOUT*QDIM];
__device__ float2 g_rope[SS*32];             // [pos][jp] -> (cos, sin)

// ---------------- helpers ----------------------------------------------------
__device__ __forceinline__ uint32_t smem_u32(const void* p) {
    uint32_t a;
    asm("{ .reg .u64 t; cvta.to.shared.u64 t, %1; cvt.u32.u64 %0, t; }" : "=r"(a) : "l"(p));
    return a;
}

#define LDSM4(r, addr)                                                           \
    asm volatile("ldmatrix.sync.aligned.m8n8.x4.shared.b16 {%0,%1,%2,%3}, [%4];" \
        : "=r"((r)[0]), "=r"((r)[1]), "=r"((r)[2]), "=r"((r)[3]) : "r"(addr))

#define LDSM4T(r, addr)                                                          \
    asm volatile("ldmatrix.sync.aligned.m8n8.x4.trans.shared.b16 {%0,%1,%2,%3}, [%4];" \
        : "=r"((r)[0]), "=r"((r)[1]), "=r"((r)[2]), "=r"((r)[3]) : "r"(addr))

#define MMA_F16(d, a, b0, b1)                                                    \
    asm volatile("mma.sync.aligned.m16n8k16.row.col.f32.f16.f16.f32 "            \
        "{%0,%1,%2,%3}, {%4,%5,%6,%7}, {%8,%9}, {%0,%1,%2,%3};"                  \
        : "+f"((d)[0]), "+f"((d)[1]), "+f"((d)[2]), "+f"((d)[3])                 \
        : "r"((a)[0]), "r"((a)[1]), "r"((a)[2]), "r"((a)[3]), "r"(b0), "r"(b1))

#define CP_ASYNC16(dst, src)                                                     \
    asm volatile("cp.async.cg.shared.global [%0], [%1], 16;" :: "r"(dst), "l"(src) : "memory")
#define CP_COMMIT()  asm volatile("cp.async.commit_group;" ::: "memory")
#define CP_WAIT1()   asm volatile("cp.async.wait_group 1;" ::: "memory")
#define CP_WAIT0()   asm volatile("cp.async.wait_group 0;" ::: "memory")

__device__ __forceinline__ uint32_t pack_f16(float lo, float hi) {
    uint32_t r;
    asm("cvt.rn.f16x2.f32 %0, %1, %2;" : "=r"(r) : "f"(hi), "f"(lo));
    return r;
}

__device__ __forceinline__ float fast_exp(float x) {
    float t = fmaxf(x * 1.4426950408889634f, -126.0f);
    float fi = floorf(t);
    float f = t - fi;
    float p = 1.54035304e-4f;
    p = fmaf(p, f, 1.33335581e-3f);
    p = fmaf(p, f, 9.61812911e-3f);
    p = fmaf(p, f, 5.55041087e-2f);
    p = fmaf(p, f, 2.40226507e-1f);
    p = fmaf(p, f, 6.93147181e-1f);
    p = fmaf(p, f, 1.0f);
    return p * __uint_as_float(((uint32_t)((int)fi + 127)) << 23);
}

// ---------------- unified prep kernel (grid-sectioned) -------------------------
#define PREP_A 16384
#define PREP_B 12288
#define PREP_C 4096
#define PREP_D 256        // rope table: 2048*32 entries / 256 thr

__global__ void prep_all(const float* __restrict__ hs,
                         const float* __restrict__ Wq, const float* __restrict__ Wk,
                         const float* __restrict__ Wv, const float* __restrict__ Wo,
                         __half* __restrict__ hsh, __half* __restrict__ wqkvT,
                         __half* __restrict__ woT, float2* __restrict__ rope)
{
    __shared__ float t[32][33];
    int bid = blockIdx.x;
    int tid = threadIdx.x;

    if (bid < PREP_A) {
        int i = bid * 256 + tid;
        float4 v = ((const float4*)hs)[i];
        __half hh[4];
        hh[0] = __float2half_rn(v.x); hh[1] = __float2half_rn(v.y);
        hh[2] = __float2half_rn(v.z); hh[3] = __float2half_rn(v.w);
        ((uint2*)hsh)[i] = *(uint2*)hh;
        return;
    }
    if (bid >= PREP_A + PREP_B + PREP_C) {
        int idx = (bid - PREP_A - PREP_B - PREP_C) * 256 + tid;   // 0..65535
        int p  = idx >> 5;
        int jp = idx & 31;
        float inv = exp2f(-(float)jp * (13.287712379549449f / 32.0f));
        float s, c;
        sincosf((float)p * inv, &s, &c);
        rope[idx] = make_float2(c, s);
        return;
    }

    int x = tid & 31, y = tid >> 5;
    if (bid < PREP_A + PREP_B) {
        int b2 = bid - PREP_A;
        int n0 = (b2 % (QKVN / 32)) * 32;
        int k0 = (b2 / (QKVN / 32)) * 32;
        const float* W; int srcN, sn0;
        if (n0 < QDIM)              { W = Wq; srcN = QDIM;  sn0 = n0; }
        else if (n0 < QDIM + KVDIM) { W = Wk; srcN = KVDIM; sn0 = n0 - QDIM; }
        else                        { W = Wv; srcN = KVDIM; sn0 = n0 - QDIM - KVDIM; }
        #pragma unroll
        for (int i = 0; i < 32; i += 8)
            t[y + i][x] = W[(size_t)(k0 + y + i) * srcN + sn0 + x];
        __syncthreads();
        #pragma unroll
        for (int i = 0; i < 32; i += 8)
            wqkvT[(size_t)(n0 + y + i) * DIN + k0 + x] = __float2half_rn(t[x][y + i]);
    } else {
        int b3 = bid - PREP_A - PREP_B;
        int n0 = (b3 % (DOUT / 32)) * 32;
        int k0 = (b3 / (DOUT / 32)) * 32;
        #pragma unroll
        for (int i = 0; i < 32; i += 8)
            t[y + i][x] = Wo[(size_t)(k0 + y + i) * DOUT + n0 + x];
        __syncthreads();
        #pragma unroll
        for (int i = 0; i < 32; i += 8)
            woT[(size_t)(n0 + y + i) * QDIM + k0 + x] = __float2half_rn(t[x][y + i]);
    }
}

// ---------------- 1-term fp16 HMMA GEMM core (3-stage, 2 CTAs/SM) --------------
#define AST 40
#define TILE_E (128*AST)
#define STAGE_E (2*TILE_E)
#define NSTAGE 3
#define GEMM_SMEM (NSTAGE * STAGE_E * 2)   // 61440 B -> 2 CTAs/SM

__device__ __forceinline__ void load_stage(
    uint32_t sbase_bytes, int tid, int bm, int bn, int k0, int K,
    const __half* __restrict__ A, const __half* __restrict__ B)
{
    #pragma unroll
    for (int i = 0; i < 4; i++) {
        int cid = tid + i * 256;
        int arr = cid >> 9;
        int rem = cid & 511;
        int row = rem >> 2;
        int c16 = rem & 3;
        const __half* g = (arr == 0)
            ? A + (size_t)(bm + row) * K + k0 + c16 * 8
            : B + (size_t)(bn + row) * K + k0 + c16 * 8;
        uint32_t d = sbase_bytes + (uint32_t)(arr * TILE_E + row * AST + c16 * 8) * 2;
        CP_ASYNC16(d, g);
    }
    CP_COMMIT();
}

__device__ __forceinline__ void gemm_mainloop(
    float acc[2][8][4], uint32_t smb, int tid, int bm, int bn, int K,
    const __half* __restrict__ A, const __half* __restrict__ B)
{
    const int wid = tid >> 5;
    const int lane = tid & 31;
    const int wm = (wid & 3) * 32;
    const int wn = (wid >> 2) * 64;
    const int nch = K >> 5;

    load_stage(smb, tid, bm, bn, 0, K, A, B);
    load_stage(smb + STAGE_E * 2, tid, bm, bn, 32, K, A, B);

    int st = 0, pst = 2;
    for (int c = 0; c < nch; c++) {
        CP_WAIT1();
        __syncthreads();

        if (c + 2 < nch)
            load_stage(smb + (uint32_t)pst * STAGE_E * 2, tid, bm, bn,
                       (c + 2) << 5, K, A, B);

        uint32_t Ab = smb + (uint32_t)st * STAGE_E * 2;
        uint32_t Bb = Ab + TILE_E * 2;

        #pragma unroll
        for (int ks = 0; ks < 2; ks++) {
            uint32_t ah[2][4], bf[4][4];
            #pragma unroll
            for (int mt = 0; mt < 2; mt++) {
                int row = wm + mt * 16 + (lane & 15);
                int col = ks * 16 + ((lane >> 4) << 3);
                LDSM4(ah[mt], Ab + (uint32_t)(row * AST + col) * 2);
            }
            #pragma unroll
            for (int p = 0; p < 4; p++) {
                int row = wn + p * 16 + (lane & 7) + ((lane >> 4) << 3);
                int col = ks * 16 + (((lane >> 3) & 1) << 3);
                LDSM4(bf[p], Bb + (uint32_t)(row * AST + col) * 2);
            }
            #pragma unroll
            for (int mt = 0; mt < 2; mt++) {
                #pragma unroll
                for (int nt = 0; nt < 8; nt++) {
                    uint32_t b0 = bf[nt >> 1][(nt & 1) * 2];
                    uint32_t b1 = bf[nt >> 1][(nt & 1) * 2 + 1];
                    MMA_F16(acc[mt][nt], ah[mt], b0, b1);
                }
            }
        }
        st = (st == 2) ? 0 : st + 1;
        pst = (pst == 2) ? 0 : pst + 1;
    }
}

// O projection: fp32 C output (2 CTAs/SM)
__global__ __launch_bounds__(256, 2)
void hmma_gemm_c(const __half* __restrict__ A, const __half* __restrict__ B,
                 float* __restrict__ C, int M, int N, int K)
{
    extern __shared__ __half sm[];
    const int tid = threadIdx.x;
    const int wid = tid >> 5, lane = tid & 31;
    const int bm = blockIdx.y * 128, bn = blockIdx.x * 128;
    const int wm = (wid & 3) * 32, wn = (wid >> 2) * 64;

    float acc[2][8][4];
    #pragma unroll
    for (int mt = 0; mt < 2; mt++)
        #pragma unroll
        for (int nt = 0; nt < 8; nt++)
            #pragma unroll
            for (int j = 0; j < 4; j++) acc[mt][nt][j] = 0.f;

    gemm_mainloop(acc, smem_u32(sm), tid, bm, bn, K, A, B);

    #pragma unroll
    for (int mt = 0; mt < 2; mt++)
        #pragma unroll
        for (int nt = 0; nt < 8; nt++) {
            int r0  = bm + wm + mt * 16 + (lane >> 2);
            int col = bn + wn + nt * 8 + (lane & 3) * 2;
            *(float2*)&C[(size_t)r0 * N + col] = make_float2(acc[mt][nt][0], acc[mt][nt][1]);
            *(float2*)&C[(size_t)(r0 + 8) * N + col] = make_float2(acc[mt][nt][2], acc[mt][nt][3]);
        }
}

// QKV GEMM with fused RoPE epilogue (table-based; 2 CTAs/SM)
__global__ __launch_bounds__(256, 2)
void hmma_gemm_qkv(const __half* __restrict__ A, const __half* __restrict__ B,
                   const int* __restrict__ pos, const float2* __restrict__ rope,
                   __half* __restrict__ q, __half* __restrict__ k,
                   __half* __restrict__ v)
{
    extern __shared__ __half sm[];
    const int tid = threadIdx.x;
    const int wid = tid >> 5, lane = tid & 31;
    const int bm = blockIdx.y * 128, bn = blockIdx.x * 128;
    const int wm = (wid & 3) * 32, wn = (wid >> 2) * 64;

    float acc[2][8][4];
    #pragma unroll
    for (int mt = 0; mt < 2; mt++)
        #pragma unroll
        for (int nt = 0; nt < 8; nt++)
            #pragma unroll
            for (int j = 0; j < 4; j++) acc[mt][nt][j] = 0.f;

    gemm_mainloop(acc, smem_u32(sm), tid, bm, bn, DIN, A, B);

    const int ncol0 = bn + wn;   // 64-aligned: one head per warp
    if (ncol0 >= QDIM + KVDIM) {
        int colb = ncol0 - (QDIM + KVDIM) + (lane & 3) * 2;
        #pragma unroll
        for (int mt = 0; mt < 2; mt++)
            #pragma unroll
            for (int nt = 0; nt < 8; nt++)
                #pragma unroll
                for (int rs = 0; rs < 2; rs++) {
                    int m = bm + wm + mt * 16 + (lane >> 2) + rs * 8;
                    size_t o = (size_t)m * KVDIM + colb + nt * 8;
                    *(uint32_t*)&v[o] = pack_f16(acc[mt][nt][rs * 2], acc[mt][nt][rs * 2 + 1]);
                }
    } else {
        const int isQ = ncol0 < QDIM;
        const float scale = isQ ? 0.125f : 1.0f;
        __half* dst = isQ ? q : k;
        const int stride = isQ ? QDIM : KVDIM;
        const int colbase = isQ ? ncol0 : ncol0 - QDIM;
        #pragma unroll
        for (int mt = 0; mt < 2; mt++)
            #pragma unroll
            for (int rs = 0; rs < 2; rs++) {
                int m = bm + wm + mt * 16 + (lane >> 2) + rs * 8;
                const float2* rrow = rope + (size_t)pos[m] * 32;
                #pragma unroll
                for (int nt = 0; nt < 4; nt++) {
                    int jp0 = nt * 8 + (lane & 3) * 2;
                    float4 cs2 = *(const float4*)&rrow[jp0];   // (c0,s0,c1,s1)
                    float y1[2], y2[2];
                    {
                        float v1 = acc[mt][nt][rs * 2], v2 = acc[mt][nt + 4][rs * 2];
                        y1[0] = (v1 * cs2.x - v2 * cs2.y) * scale;
                        y2[0] = (v2 * cs2.x + v1 * cs2.y) * scale;
                    }
                    {
                        float v1 = acc[mt][nt][rs * 2 + 1], v2 = acc[mt][nt + 4][rs * 2 + 1];
                        y1[1] = (v1 * cs2.z - v2 * cs2.w) * scale;
                        y2[1] = (v2 * cs2.z + v1 * cs2.w) * scale;
                    }
                    size_t o = (size_t)m * stride + colbase + jp0;
                    *(uint32_t*)&dst[o]      = pack_f16(y1[0], y1[1]);
                    *(uint32_t*)&dst[o + 32] = pack_f16(y2[0], y2[1]);
                }
            }
    }
}

// ---------------- HMMA flash attention (QK 1-term, PV 1-term) ------------------
#define QST 72
#define ATT_Q_E  (256*QST)
#define ATT_KV_E (64*QST)
#define ATT_KV_STAGE (2*ATT_KV_E*2)
#define ATT_QBYTES (ATT_Q_E*2)
#define ATT_SMEM (ATT_QBYTES + 3*ATT_KV_STAGE)   // 92160 B

__device__ __forceinline__ void attn_load_kv(
    uint32_t stage_base, int tid, int b, int kvh, int kt,
    const __half* __restrict__ k, const __half* __restrict__ v)
{
    #pragma unroll
    for (int it = 0; it < 4; it++) {
        int cid = tid + it * 256;
        int arr = cid >> 9;
        int rem = cid & 511;
        int row = rem >> 3;
        int c   = rem & 7;
        const __half* base = (arr == 0) ? k : v;
        const __half* src = base + (size_t)(b * SS + kt * 64 + row) * KVDIM + kvh * 64 + c * 8;
        CP_ASYNC16(stage_base + (uint32_t)arr * ATT_KV_E * 2 + (uint32_t)(row * QST + c * 8) * 2, src);
    }
    CP_COMMIT();
}

__global__ __launch_bounds__(256, 1)
void attn_hmma(const __half* __restrict__ q, const __half* __restrict__ k,
               const __half* __restrict__ v, __half* __restrict__ ao)
{
    extern __shared__ __half smatt[];
    const int qt  = gridDim.x - 1 - blockIdx.x;
    const int kvh = blockIdx.y;
    const int b   = blockIdx.z;
    const int tid = threadIdx.x, wid = tid >> 5, lane = tid & 31;

    const uint32_t smb = smem_u32(smatt);
    const uint32_t Q_o = smb;

    #pragma unroll
    for (int it = 0; it < 8; it++) {
        int cid = tid + it * 256;
        int row = cid >> 3;
        int c   = cid & 7;
        const __half* src = q
            + (size_t)(b * SS + qt * 64 + (row & 63)) * QDIM
            + (kvh * 4 + (row >> 6)) * 64 + c * 8;
        CP_ASYNC16(Q_o + (uint32_t)(row * QST + c * 8) * 2, src);
    }
    CP_COMMIT();

    attn_load_kv(smb + ATT_QBYTES, tid, b, kvh, 0, k, v);
    if (qt >= 1)
        attn_load_kv(smb + ATT_QBYTES + ATT_KV_STAGE, tid, b, kvh, 1, k, v);

    float m_r[2][2], l_r[2][2], oacc[2][8][4];
    #pragma unroll
    for (int mt = 0; mt < 2; mt++) {
        m_r[mt][0] = -1e30f; m_r[mt][1] = -1e30f;
        l_r[mt][0] = 0.f;    l_r[mt][1] = 0.f;
        #pragma unroll
        for (int nt = 0; nt < 8; nt++)
            #pragma unroll
            for (int j = 0; j < 4; j++) oacc[mt][nt][j] = 0.f;
    }

    const int wrow  = wid * 32;
    const int hloc  = wid >> 1;
    const int rtile = (wid & 1) * 32;

    int st = 0;
    for (int kt = 0; kt <= qt; kt++) {
        if (kt < qt) CP_WAIT1(); else CP_WAIT0();
        __syncthreads();

        if (kt + 2 <= qt)
            attn_load_kv(smb + ATT_QBYTES + (uint32_t)((kt + 2) % 3) * ATT_KV_STAGE,
                         tid, b, kvh, kt + 2, k, v);

        const uint32_t stg = smb + ATT_QBYTES + (uint32_t)st * ATT_KV_STAGE;
        const uint32_t K_o = stg;
        const uint32_t V_o = stg + ATT_KV_E * 2;

        float sacc[2][8][4];
        #pragma unroll
        for (int mt = 0; mt < 2; mt++)
            #pragma unroll
            for (int nt = 0; nt < 8; nt++)
                #pragma unroll
                for (int j = 0; j < 4; j++) sacc[mt][nt][j] = 0.f;

        #pragma unroll
        for (int ks = 0; ks < 4; ks++) {
            uint32_t qa[2][4], kb[4][4];
            #pragma unroll
            for (int mt = 0; mt < 2; mt++) {
                int row = wrow + mt * 16 + (lane & 15);
                int col = ks * 16 + ((lane >> 4) << 3);
                LDSM4(qa[mt], Q_o + (uint32_t)(row * QST + col) * 2);
            }
            #pragma unroll
            for (int p = 0; p < 4; p++) {
                int row = p * 16 + (lane & 7) + ((lane >> 4) << 3);
                int col = ks * 16 + (((lane >> 3) & 1) << 3);
                LDSM4(kb[p], K_o + (uint32_t)(row * QST + col) * 2);
            }
            #pragma unroll
            for (int mt = 0; mt < 2; mt++) {
                #pragma unroll
                for (int nt = 0; nt < 8; nt++) {
                    uint32_t b0 = kb[nt >> 1][(nt & 1) * 2];
                    uint32_t b1 = kb[nt >> 1][(nt & 1) * 2 + 1];
                    MMA_F16(sacc[mt][nt], qa[mt], b0, b1);
                }
            }
        }

        if (kt == qt) {
            #pragma unroll
            for (int mt = 0; mt < 2; mt++)
                #pragma unroll
                for (int nt = 0; nt < 8; nt++)
                    #pragma unroll
                    for (int cc = 0; cc < 4; cc++) {
                        int rloc = rtile + mt * 16 + (lane >> 2) + ((cc >= 2) ? 8 : 0);
                        int cloc = nt * 8 + (lane & 3) * 2 + (cc & 1);
                        if (cloc > rloc) sacc[mt][nt][cc] = -1e30f;
                    }
        }

        #pragma unroll
        for (int mt = 0; mt < 2; mt++) {
            float mx0 = -1e30f, mx1 = -1e30f;
            #pragma unroll
            for (int nt = 0; nt < 8; nt++) {
                mx0 = fmaxf(mx0, fmaxf(sacc[mt][nt][0], sacc[mt][nt][1]));
                mx1 = fmaxf(mx1, fmaxf(sacc[mt][nt][2], sacc[mt][nt][3]));
            }
            mx0 = fmaxf(mx0, __shfl_xor_sync(0xffffffffu, mx0, 1));
            mx0 = fmaxf(mx0, __shfl_xor_sync(0xffffffffu, mx0, 2));
            mx1 = fmaxf(mx1, __shfl_xor_sync(0xffffffffu, mx1, 1));
            mx1 = fmaxf(mx1, __shfl_xor_sync(0xffffffffu, mx1, 2));
            float mn0 = fmaxf(m_r[mt][0], mx0);
            float mn1 = fmaxf(m_r[mt][1], mx1);
            float sc0 = fast_exp(m_r[mt][0] - mn0);
            float sc1 = fast_exp(m_r[mt][1] - mn1);
            m_r[mt][0] = mn0; m_r[mt][1] = mn1;
            float sum0 = 0.f, sum1 = 0.f;
            #pragma unroll
            for (int nt = 0; nt < 8; nt++) {
                float p0 = fast_exp(sacc[mt][nt][0] - mn0);
                float p1 = fast_exp(sacc[mt][nt][1] - mn0);
                float p2 = fast_exp(sacc[mt][nt][2] - mn1);
                float p3 = fast_exp(sacc[mt][nt][3] - mn1);
                sacc[mt][nt][0] = p0; sacc[mt][nt][1] = p1;
                sacc[mt][nt][2] = p2; sacc[mt][nt][3] = p3;
                sum0 += p0 + p1; sum1 += p2 + p3;
                oacc[mt][nt][0] *= sc0; oacc[mt][nt][1] *= sc0;
                oacc[mt][nt][2] *= sc1; oacc[mt][nt][3] *= sc1;
            }
            l_r[mt][0] = l_r[mt][0] * sc0 + sum0;
            l_r[mt][1] = l_r[mt][1] * sc1 + sum1;
        }

        #pragma unroll
        for (int j = 0; j < 4; j++) {
            uint32_t vb[4][4];
            int tok_off = (lane & 7) + (((lane >> 3) & 1) << 3);
            int d_off   = ((lane >> 4) & 1) << 3;
            #pragma unroll
            for (int p = 0; p < 4; p++) {
                uint32_t off = (uint32_t)((j * 16 + tok_off) * QST + p * 16 + d_off) * 2;
                LDSM4T(vb[p], V_o + off);
            }
            #pragma unroll
            for (int mt = 0; mt < 2; mt++) {
                uint32_t ah[4];
                #pragma unroll
                for (int qd = 0; qd < 4; qd++) {
                    int nt = 2 * j + (qd >> 1);
                    ah[qd] = pack_f16(sacc[mt][nt][(qd & 1) * 2], sacc[mt][nt][(qd & 1) * 2 + 1]);
                }
                #pragma unroll
                for (int nt = 0; nt < 8; nt++) {
                    uint32_t b0 = vb[nt >> 1][(nt & 1) * 2];
                    uint32_t b1 = vb[nt >> 1][(nt & 1) * 2 + 1];
                    MMA_F16(oacc[mt][nt], ah, b0, b1);
                }
            }
        }
        st = (st == 2) ? 0 : st + 1;
    }

    #pragma unroll
    for (int mt = 0; mt < 2; mt++) {
        l_r[mt][0] += __shfl_xor_sync(0xffffffffu, l_r[mt][0], 1);
        l_r[mt][0] += __shfl_xor_sync(0xffffffffu, l_r[mt][0], 2);
        l_r[mt][1] += __shfl_xor_sync(0xffffffffu, l_r[mt][1], 1);
        l_r[mt][1] += __shfl_xor_sync(0xffffffffu, l_r[mt][1], 2);
        float inv0 = 1.0f / l_r[mt][0];
        float inv1 = 1.0f / l_r[mt][1];
        int tok = qt * 64 + rtile + mt * 16 + (lane >> 2);
        int colb = (kvh * 4 + hloc) * 64 + (lane & 3) * 2;
        #pragma unroll
        for (int nt = 0; nt < 8; nt++) {
            size_t o0 = (size_t)(b * SS + tok) * QDIM + colb + nt * 8;
            size_t o1 = o0 + (size_t)8 * QDIM;
            *(uint32_t*)&ao[o0] = pack_f16(oacc[mt][nt][0] * inv0, oacc[mt][nt][1] * inv0);
            *(uint32_t*)&ao[o1] = pack_f16(oacc[mt][nt][2] * inv1, oacc[mt][nt][3] * inv1);
        }
    }
}

// ---------------------------------------------------------------------------
extern "C" void kernel_launch(void* const* d_in, const int* in_sizes, int n_in,
                              void* d_out, int out_size)
{
    (void)in_sizes; (void)n_in; (void)out_size;
    const float* hs  = (const float*)d_in[0];
    const int*   pos = (const int*)d_in[2];
    const float* Wq  = (const float*)d_in[3];
    const float* Wk  = (const float*)d_in[4];
    const float* Wv  = (const float*)d_in[5];
    const float* Wo  = (const float*)d_in[6];
    float* out = (float*)d_out;

    __half *hsb, *q, *k, *v, *ao, *w, *wo;
    float2* rope;
    cudaGetSymbolAddress((void**)&hsb, g_hs);
    cudaGetSymbolAddress((void**)&q,  g_q);
    cudaGetSymbolAddress((void**)&k,  g_k);
    cudaGetSymbolAddress((void**)&v,  g_v);
    cudaGetSymbolAddress((void**)&ao, g_ao);
    cudaGetSymbolAddress((void**)&w,  g_wqkvT);
    cudaGetSymbolAddress((void**)&wo, g_woT);
    cudaGetSymbolAddress((void**)&rope, g_rope);

    const int M = MTOT;
    cudaFuncSetAttribute(hmma_gemm_c,   cudaFuncAttributeMaxDynamicSharedMemorySize, GEMM_SMEM);
    cudaFuncSetAttribute(hmma_gemm_qkv, cudaFuncAttributeMaxDynamicSharedMemorySize, GEMM_SMEM);
    cudaFuncSetAttribute(attn_hmma,     cudaFuncAttributeMaxDynamicSharedMemorySize, ATT_SMEM);

    prep_all<<<PREP_A + PREP_B + PREP_C + PREP_D, 256>>>(hs, Wq, Wk, Wv, Wo, hsb, w, wo, rope); // 1
    hmma_gemm_qkv<<<dim3(QKVN / 128, M / 128), 256, GEMM_SMEM>>>(hsb, w, pos, rope, q, k, v);   // 2
    attn_hmma<<<dim3(SS / 64, NKV, BB), 256, ATT_SMEM>>>(q, k, v, ao);                          // 3
    hmma_gemm_c<<<dim3(DOUT / 128, M / 128), 256, GEMM_SMEM>>>(ao, wo, out, M, DOUT, QDIM);     // 4
}

// round 14
// speedup vs baseline: 2.7930x; 1.0188x over previous
#include <cuda_runtime.h>
#include <cuda_fp16.h>
#include <math.h>
#include <stdint.h>

#define BB 2
#define SS 2048
#define DIN 4096
#define NH 32
#define NKV 8
#define HD 64
#define QDIM 2048
#define KVDIM 512
#define QKVN 3072
#define DOUT 2048
#define MTOT 4096

// ---------------- scratch (__device__ globals) ------------------------------
__device__ __half g_hs[MTOT*DIN];
__device__ __half g_q[MTOT*QDIM];
__device__ __half g_k[MTOT*KVDIM];
__device__ __half g_v[MTOT*KVDIM];
__device__ __half g_ao[MTOT*QDIM];
__device__ __half g_wqkvT[QKVN*DIN];
__device__ __half g_woT[DOUT*QDIM];
__device__ float2 g_rope[SS*32];

// ---------------- helpers ----------------------------------------------------
__device__ __forceinline__ uint32_t smem_u32(const void* p) {
    uint32_t a;
    asm("{ .reg .u64 t; cvta.to.shared.u64 t, %1; cvt.u32.u64 %0, t; }" : "=r"(a) : "l"(p));
    return a;
}

#define LDSM4(r, addr)                                                           \
    asm volatile("ldmatrix.sync.aligned.m8n8.x4.shared.b16 {%0,%1,%2,%3}, [%4];" \
        : "=r"((r)[0]), "=r"((r)[1]), "=r"((r)[2]), "=r"((r)[3]) : "r"(addr))

#define LDSM4T(r, addr)                                                          \
    asm volatile("ldmatrix.sync.aligned.m8n8.x4.trans.shared.b16 {%0,%1,%2,%3}, [%4];" \
        : "=r"((r)[0]), "=r"((r)[1]), "=r"((r)[2]), "=r"((r)[3]) : "r"(addr))

#define MMA_F16(d, a, b0, b1)                                                    \
    asm volatile("mma.sync.aligned.m16n8k16.row.col.f32.f16.f16.f32 "            \
        "{%0,%1,%2,%3}, {%4,%5,%6,%7}, {%8,%9}, {%0,%1,%2,%3};"                  \
        : "+f"((d)[0]), "+f"((d)[1]), "+f"((d)[2]), "+f"((d)[3])                 \
        : "r"((a)[0]), "r"((a)[1]), "r"((a)[2]), "r"((a)[3]), "r"(b0), "r"(b1))

#define CP_ASYNC16(dst, src)                                                     \
    asm volatile("cp.async.cg.shared.global [%0], [%1], 16;" :: "r"(dst), "l"(src) : "memory")
#define CP_COMMIT()  asm volatile("cp.async.commit_group;" ::: "memory")
#define CP_WAIT1()   asm volatile("cp.async.wait_group 1;" ::: "memory")
#define CP_WAIT0()   asm volatile("cp.async.wait_group 0;" ::: "memory")

__device__ __forceinline__ uint32_t pack_f16(float lo, float hi) {
    uint32_t r;
    asm("cvt.rn.f16x2.f32 %0, %1, %2;" : "=r"(r) : "f"(hi), "f"(lo));
    return r;
}

__device__ __forceinline__ float fast_exp(float x) {
    float t = fmaxf(x * 1.4426950408889634f, -126.0f);
    float fi = floorf(t);
    float f = t - fi;
    float p = 1.54035304e-4f;
    p = fmaf(p, f, 1.33335581e-3f);
    p = fmaf(p, f, 9.61812911e-3f);
    p = fmaf(p, f, 5.55041087e-2f);
    p = fmaf(p, f, 2.40226507e-1f);
    p = fmaf(p, f, 6.93147181e-1f);
    p = fmaf(p, f, 1.0f);
    return p * __uint_as_float(((uint32_t)((int)fi + 127)) << 23);
}

// ---------------- unified prep kernel (grid-sectioned) -------------------------
#define PREP_A 16384
#define PREP_B 12288
#define PREP_C 4096
#define PREP_D 256

__global__ void prep_all(const float* __restrict__ hs,
                         const float* __restrict__ Wq, const float* __restrict__ Wk,
                         const float* __restrict__ Wv, const float* __restrict__ Wo,
                         __half* __restrict__ hsh, __half* __restrict__ wqkvT,
                         __half* __restrict__ woT, float2* __restrict__ rope)
{
    __shared__ float t[32][33];
    int bid = blockIdx.x;
    int tid = threadIdx.x;

    if (bid < PREP_A) {
        int i = bid * 256 + tid;
        float4 v = ((const float4*)hs)[i];
        __half hh[4];
        hh[0] = __float2half_rn(v.x); hh[1] = __float2half_rn(v.y);
        hh[2] = __float2half_rn(v.z); hh[3] = __float2half_rn(v.w);
        ((uint2*)hsh)[i] = *(uint2*)hh;
        return;
    }
    if (bid >= PREP_A + PREP_B + PREP_C) {
        int idx = (bid - PREP_A - PREP_B - PREP_C) * 256 + tid;
        int p  = idx >> 5;
        int jp = idx & 31;
        float inv = exp2f(-(float)jp * (13.287712379549449f / 32.0f));
        float s, c;
        sincosf((float)p * inv, &s, &c);
        rope[idx] = make_float2(c, s);
        return;
    }

    int x = tid & 31, y = tid >> 5;
    if (bid < PREP_A + PREP_B) {
        int b2 = bid - PREP_A;
        int n0 = (b2 % (QKVN / 32)) * 32;
        int k0 = (b2 / (QKVN / 32)) * 32;
        const float* W; int srcN, sn0;
        if (n0 < QDIM)              { W = Wq; srcN = QDIM;  sn0 = n0; }
        else if (n0 < QDIM + KVDIM) { W = Wk; srcN = KVDIM; sn0 = n0 - QDIM; }
        else                        { W = Wv; srcN = KVDIM; sn0 = n0 - QDIM - KVDIM; }
        #pragma unroll
        for (int i = 0; i < 32; i += 8)
            t[y + i][x] = W[(size_t)(k0 + y + i) * srcN + sn0 + x];
        __syncthreads();
        #pragma unroll
        for (int i = 0; i < 32; i += 8)
            wqkvT[(size_t)(n0 + y + i) * DIN + k0 + x] = __float2half_rn(t[x][y + i]);
    } else {
        int b3 = bid - PREP_A - PREP_B;
        int n0 = (b3 % (DOUT / 32)) * 32;
        int k0 = (b3 / (DOUT / 32)) * 32;
        #pragma unroll
        for (int i = 0; i < 32; i += 8)
            t[y + i][x] = Wo[(size_t)(k0 + y + i) * DOUT + n0 + x];
        __syncthreads();
        #pragma unroll
        for (int i = 0; i < 32; i += 8)
            woT[(size_t)(n0 + y + i) * QDIM + k0 + x] = __float2half_rn(t[x][y + i]);
    }
}

// ---------------- 1-term fp16 HMMA GEMM core (3-stage, 2 CTAs/SM) --------------
#define AST 40
#define TILE_E (128*AST)
#define STAGE_E (2*TILE_E)
#define NSTAGE 3
#define GEMM_SMEM (NSTAGE * STAGE_E * 2)

__device__ __forceinline__ void load_stage(
    uint32_t sbase_bytes, int tid, int bm, int bn, int k0, int K,
    const __half* __restrict__ A, const __half* __restrict__ B)
{
    #pragma unroll
    for (int i = 0; i < 4; i++) {
        int cid = tid + i * 256;
        int arr = cid >> 9;
        int rem = cid & 511;
        int row = rem >> 2;
        int c16 = rem & 3;
        const __half* g = (arr == 0)
            ? A + (size_t)(bm + row) * K + k0 + c16 * 8
            : B + (size_t)(bn + row) * K + k0 + c16 * 8;
        uint32_t d = sbase_bytes + (uint32_t)(arr * TILE_E + row * AST + c16 * 8) * 2;
        CP_ASYNC16(d, g);
    }
    CP_COMMIT();
}

__device__ __forceinline__ void gemm_mainloop(
    float acc[2][8][4], uint32_t smb, int tid, int bm, int bn, int K,
    const __half* __restrict__ A, const __half* __restrict__ B)
{
    const int wid = tid >> 5;
    const int lane = tid & 31;
    const int wm = (wid & 3) * 32;
    const int wn = (wid >> 2) * 64;
    const int nch = K >> 5;

    load_stage(smb, tid, bm, bn, 0, K, A, B);
    load_stage(smb + STAGE_E * 2, tid, bm, bn, 32, K, A, B);

    int st = 0, pst = 2;
    for (int c = 0; c < nch; c++) {
        CP_WAIT1();
        __syncthreads();

        if (c + 2 < nch)
            load_stage(smb + (uint32_t)pst * STAGE_E * 2, tid, bm, bn,
                       (c + 2) << 5, K, A, B);

        uint32_t Ab = smb + (uint32_t)st * STAGE_E * 2;
        uint32_t Bb = Ab + TILE_E * 2;

        #pragma unroll
        for (int ks = 0; ks < 2; ks++) {
            uint32_t ah[2][4], bf[4][4];
            #pragma unroll
            for (int mt = 0; mt < 2; mt++) {
                int row = wm + mt * 16 + (lane & 15);
                int col = ks * 16 + ((lane >> 4) << 3);
                LDSM4(ah[mt], Ab + (uint32_t)(row * AST + col) * 2);
            }
            #pragma unroll
            for (int p = 0; p < 4; p++) {
                int row = wn + p * 16 + (lane & 7) + ((lane >> 4) << 3);
                int col = ks * 16 + (((lane >> 3) & 1) << 3);
                LDSM4(bf[p], Bb + (uint32_t)(row * AST + col) * 2);
            }
            #pragma unroll
            for (int mt = 0; mt < 2; mt++) {
                #pragma unroll
                for (int nt = 0; nt < 8; nt++) {
                    uint32_t b0 = bf[nt >> 1][(nt & 1) * 2];
                    uint32_t b1 = bf[nt >> 1][(nt & 1) * 2 + 1];
                    MMA_F16(acc[mt][nt], ah[mt], b0, b1);
                }
            }
        }
        st = (st == 2) ? 0 : st + 1;
        pst = (pst == 2) ? 0 : pst + 1;
    }
}

// O projection: fp32 C output (2 CTAs/SM)
__global__ __launch_bounds__(256, 2)
void hmma_gemm_c(const __half* __restrict__ A, const __half* __restrict__ B,
                 float* __restrict__ C, int M, int N, int K)
{
    extern __shared__ __half sm[];
    const int tid = threadIdx.x;
    const int wid = tid >> 5, lane = tid & 31;
    const int bm = blockIdx.y * 128, bn = blockIdx.x * 128;
    const int wm = (wid & 3) * 32, wn = (wid >> 2) * 64;

    float acc[2][8][4];
    #pragma unroll
    for (int mt = 0; mt < 2; mt++)
        #pragma unroll
        for (int nt = 0; nt < 8; nt++)
            #pragma unroll
            for (int j = 0; j < 4; j++) acc[mt][nt][j] = 0.f;

    gemm_mainloop(acc, smem_u32(sm), tid, bm, bn, K, A, B);

    #pragma unroll
    for (int mt = 0; mt < 2; mt++)
        #pragma unroll
        for (int nt = 0; nt < 8; nt++) {
            int r0  = bm + wm + mt * 16 + (lane >> 2);
            int col = bn + wn + nt * 8 + (lane & 3) * 2;
            *(float2*)&C[(size_t)r0 * N + col] = make_float2(acc[mt][nt][0], acc[mt][nt][1]);
            *(float2*)&C[(size_t)(r0 + 8) * N + col] = make_float2(acc[mt][nt][2], acc[mt][nt][3]);
        }
}

// QKV GEMM with fused RoPE epilogue (table-based; 2 CTAs/SM)
__global__ __launch_bounds__(256, 2)
void hmma_gemm_qkv(const __half* __restrict__ A, const __half* __restrict__ B,
                   const int* __restrict__ pos, const float2* __restrict__ rope,
                   __half* __restrict__ q, __half* __restrict__ k,
                   __half* __restrict__ v)
{
    extern __shared__ __half sm[];
    const int tid = threadIdx.x;
    const int wid = tid >> 5, lane = tid & 31;
    const int bm = blockIdx.y * 128, bn = blockIdx.x * 128;
    const int wm = (wid & 3) * 32, wn = (wid >> 2) * 64;

    float acc[2][8][4];
    #pragma unroll
    for (int mt = 0; mt < 2; mt++)
        #pragma unroll
        for (int nt = 0; nt < 8; nt++)
            #pragma unroll
            for (int j = 0; j < 4; j++) acc[mt][nt][j] = 0.f;

    gemm_mainloop(acc, smem_u32(sm), tid, bm, bn, DIN, A, B);

    const int ncol0 = bn + wn;
    if (ncol0 >= QDIM + KVDIM) {
        int colb = ncol0 - (QDIM + KVDIM) + (lane & 3) * 2;
        #pragma unroll
        for (int mt = 0; mt < 2; mt++)
            #pragma unroll
            for (int nt = 0; nt < 8; nt++)
                #pragma unroll
                for (int rs = 0; rs < 2; rs++) {
                    int m = bm + wm + mt * 16 + (lane >> 2) + rs * 8;
                    size_t o = (size_t)m * KVDIM + colb + nt * 8;
                    *(uint32_t*)&v[o] = pack_f16(acc[mt][nt][rs * 2], acc[mt][nt][rs * 2 + 1]);
                }
    } else {
        const int isQ = ncol0 < QDIM;
        const float scale = isQ ? 0.125f : 1.0f;
        __half* dst = isQ ? q : k;
        const int stride = isQ ? QDIM : KVDIM;
        const int colbase = isQ ? ncol0 : ncol0 - QDIM;
        #pragma unroll
        for (int mt = 0; mt < 2; mt++)
            #pragma unroll
            for (int rs = 0; rs < 2; rs++) {
                int m = bm + wm + mt * 16 + (lane >> 2) + rs * 8;
                const float2* rrow = rope + (size_t)pos[m] * 32;
                #pragma unroll
                for (int nt = 0; nt < 4; nt++) {
                    int jp0 = nt * 8 + (lane & 3) * 2;
                    float4 cs2 = *(const float4*)&rrow[jp0];
                    float y1[2], y2[2];
                    {
                        float v1 = acc[mt][nt][rs * 2], v2 = acc[mt][nt + 4][rs * 2];
                        y1[0] = (v1 * cs2.x - v2 * cs2.y) * scale;
                        y2[0] = (v2 * cs2.x + v1 * cs2.y) * scale;
                    }
                    {
                        float v1 = acc[mt][nt][rs * 2 + 1], v2 = acc[mt][nt + 4][rs * 2 + 1];
                        y1[1] = (v1 * cs2.z - v2 * cs2.w) * scale;
                        y2[1] = (v2 * cs2.z + v1 * cs2.w) * scale;
                    }
                    size_t o = (size_t)m * stride + colbase + jp0;
                    *(uint32_t*)&dst[o]      = pack_f16(y1[0], y1[1]);
                    *(uint32_t*)&dst[o + 32] = pack_f16(y2[0], y2[1]);
                }
            }
    }
}

// ---------------- HMMA flash attention (M=128 tile, 2 CTAs/SM) -----------------
// CTA: (qt, head-pair, b). 128 rows = 2 q-heads x 64 tokens. 8 warps x 16 rows.
#define QST 72
#define ATT_Q_E  (128*QST)
#define ATT_KV_E (64*QST)
#define ATT_KV_STAGE (2*ATT_KV_E*2)       // K | V
#define ATT_QBYTES (ATT_Q_E*2)
#define ATT_SMEM (ATT_QBYTES + 3*ATT_KV_STAGE)   // 73728 B -> 2 CTAs/SM

__device__ __forceinline__ void attn_load_kv(
    uint32_t stage_base, int tid, int b, int kvh, int kt,
    const __half* __restrict__ k, const __half* __restrict__ v)
{
    #pragma unroll
    for (int it = 0; it < 4; it++) {
        int cid = tid + it * 256;
        int arr = cid >> 9;
        int rem = cid & 511;
        int row = rem >> 3;
        int c   = rem & 7;
        const __half* base = (arr == 0) ? k : v;
        const __half* src = base + (size_t)(b * SS + kt * 64 + row) * KVDIM + kvh * 64 + c * 8;
        CP_ASYNC16(stage_base + (uint32_t)arr * ATT_KV_E * 2 + (uint32_t)(row * QST + c * 8) * 2, src);
    }
    CP_COMMIT();
}

__global__ __launch_bounds__(256, 2)
void attn_hmma(const __half* __restrict__ q, const __half* __restrict__ k,
               const __half* __restrict__ v, __half* __restrict__ ao)
{
    extern __shared__ __half smatt[];
    const int qt    = gridDim.x - 1 - blockIdx.x;
    const int hp    = blockIdx.y;        // 0..15: head-pair
    const int kvh   = hp >> 1;
    const int hpair = hp & 1;
    const int b     = blockIdx.z;
    const int tid = threadIdx.x, wid = tid >> 5, lane = tid & 31;

    const uint32_t smb = smem_u32(smatt);
    const uint32_t Q_o = smb;

    // Q tile load: 128 rows x 64 cols = 1024 x 16B chunks
    #pragma unroll
    for (int it = 0; it < 4; it++) {
        int cid = tid + it * 256;
        int row = cid >> 3;                 // 0..127
        int c   = cid & 7;
        const __half* src = q
            + (size_t)(b * SS + qt * 64 + (row & 63)) * QDIM
            + (kvh * 4 + hpair * 2 + (row >> 6)) * 64 + c * 8;
        CP_ASYNC16(Q_o + (uint32_t)(row * QST + c * 8) * 2, src);
    }
    CP_COMMIT();

    attn_load_kv(smb + ATT_QBYTES, tid, b, kvh, 0, k, v);
    if (qt >= 1)
        attn_load_kv(smb + ATT_QBYTES + ATT_KV_STAGE, tid, b, kvh, 1, k, v);

    float m_r[2], l_r[2], oacc[8][4];
    m_r[0] = -1e30f; m_r[1] = -1e30f;
    l_r[0] = 0.f;    l_r[1] = 0.f;
    #pragma unroll
    for (int nt = 0; nt < 8; nt++)
        #pragma unroll
        for (int j = 0; j < 4; j++) oacc[nt][j] = 0.f;

    const int wrow  = wid * 16;        // 8 warps x 16 rows = 128
    const int hloc  = wid >> 2;        // q head within pair (0-1)
    const int rtile = (wid & 3) * 16;  // token row base in 64-tile

    int st = 0;
    for (int kt = 0; kt <= qt; kt++) {
        if (kt < qt) CP_WAIT1(); else CP_WAIT0();
        __syncthreads();

        if (kt + 2 <= qt)
            attn_load_kv(smb + ATT_QBYTES + (uint32_t)((kt + 2) % 3) * ATT_KV_STAGE,
                         tid, b, kvh, kt + 2, k, v);

        const uint32_t stg = smb + ATT_QBYTES + (uint32_t)st * ATT_KV_STAGE;
        const uint32_t K_o = stg;
        const uint32_t V_o = stg + ATT_KV_E * 2;

        // ---- S = Q K^T (1-term)
        float sacc[8][4];
        #pragma unroll
        for (int nt = 0; nt < 8; nt++)
            #pragma unroll
            for (int j = 0; j < 4; j++) sacc[nt][j] = 0.f;

        #pragma unroll
        for (int ks = 0; ks < 4; ks++) {
            uint32_t qa[4], kb[4][4];
            {
                int row = wrow + (lane & 15);
                int col = ks * 16 + ((lane >> 4) << 3);
                LDSM4(qa, Q_o + (uint32_t)(row * QST + col) * 2);
            }
            #pragma unroll
            for (int p = 0; p < 4; p++) {
                int row = p * 16 + (lane & 7) + ((lane >> 4) << 3);
                int col = ks * 16 + (((lane >> 3) & 1) << 3);
                LDSM4(kb[p], K_o + (uint32_t)(row * QST + col) * 2);
            }
            #pragma unroll
            for (int nt = 0; nt < 8; nt++) {
                uint32_t b0 = kb[nt >> 1][(nt & 1) * 2];
                uint32_t b1 = kb[nt >> 1][(nt & 1) * 2 + 1];
                MMA_F16(sacc[nt], qa, b0, b1);
            }
        }

        if (kt == qt) {
            #pragma unroll
            for (int nt = 0; nt < 8; nt++)
                #pragma unroll
                for (int cc = 0; cc < 4; cc++) {
                    int rloc = rtile + (lane >> 2) + ((cc >= 2) ? 8 : 0);
                    int cloc = nt * 8 + (lane & 3) * 2 + (cc & 1);
                    if (cloc > rloc) sacc[nt][cc] = -1e30f;
                }
        }

        // ---- online softmax
        {
            float mx0 = -1e30f, mx1 = -1e30f;
            #pragma unroll
            for (int nt = 0; nt < 8; nt++) {
                mx0 = fmaxf(mx0, fmaxf(sacc[nt][0], sacc[nt][1]));
                mx1 = fmaxf(mx1, fmaxf(sacc[nt][2], sacc[nt][3]));
            }
            mx0 = fmaxf(mx0, __shfl_xor_sync(0xffffffffu, mx0, 1));
            mx0 = fmaxf(mx0, __shfl_xor_sync(0xffffffffu, mx0, 2));
            mx1 = fmaxf(mx1, __shfl_xor_sync(0xffffffffu, mx1, 1));
            mx1 = fmaxf(mx1, __shfl_xor_sync(0xffffffffu, mx1, 2));
            float mn0 = fmaxf(m_r[0], mx0);
            float mn1 = fmaxf(m_r[1], mx1);
            float sc0 = fast_exp(m_r[0] - mn0);
            float sc1 = fast_exp(m_r[1] - mn1);
            m_r[0] = mn0; m_r[1] = mn1;
            float sum0 = 0.f, sum1 = 0.f;
            #pragma unroll
            for (int nt = 0; nt < 8; nt++) {
                float p0 = fast_exp(sacc[nt][0] - mn0);
                float p1 = fast_exp(sacc[nt][1] - mn0);
                float p2 = fast_exp(sacc[nt][2] - mn1);
                float p3 = fast_exp(sacc[nt][3] - mn1);
                sacc[nt][0] = p0; sacc[nt][1] = p1;
                sacc[nt][2] = p2; sacc[nt][3] = p3;
                sum0 += p0 + p1; sum1 += p2 + p3;
                oacc[nt][0] *= sc0; oacc[nt][1] *= sc0;
                oacc[nt][2] *= sc1; oacc[nt][3] *= sc1;
            }
            l_r[0] = l_r[0] * sc0 + sum0;
            l_r[1] = l_r[1] * sc1 + sum1;
        }

        // ---- O += P V (1-term)
        #pragma unroll
        for (int j = 0; j < 4; j++) {
            uint32_t vb[4][4];
            int tok_off = (lane & 7) + (((lane >> 3) & 1) << 3);
            int d_off   = ((lane >> 4) & 1) << 3;
            #pragma unroll
            for (int p = 0; p < 4; p++) {
                uint32_t off = (uint32_t)((j * 16 + tok_off) * QST + p * 16 + d_off) * 2;
                LDSM4T(vb[p], V_o + off);
            }
            uint32_t ah[4];
            #pragma unroll
            for (int qd = 0; qd < 4; qd++) {
                int nt = 2 * j + (qd >> 1);
                ah[qd] = pack_f16(sacc[nt][(qd & 1) * 2], sacc[nt][(qd & 1) * 2 + 1]);
            }
            #pragma unroll
            for (int nt = 0; nt < 8; nt++) {
                uint32_t b0 = vb[nt >> 1][(nt & 1) * 2];
                uint32_t b1 = vb[nt >> 1][(nt & 1) * 2 + 1];
                MMA_F16(oacc[nt], ah, b0, b1);
            }
        }
        st = (st == 2) ? 0 : st + 1;
    }

    // ---- epilogue
    l_r[0] += __shfl_xor_sync(0xffffffffu, l_r[0], 1);
    l_r[0] += __shfl_xor_sync(0xffffffffu, l_r[0], 2);
    l_r[1] += __shfl_xor_sync(0xffffffffu, l_r[1], 1);
    l_r[1] += __shfl_xor_sync(0xffffffffu, l_r[1], 2);
    float inv0 = 1.0f / l_r[0];
    float inv1 = 1.0f / l_r[1];
    int tok = qt * 64 + rtile + (lane >> 2);
    int colb = (kvh * 4 + hpair * 2 + hloc) * 64 + (lane & 3) * 2;
    #pragma unroll
    for (int nt = 0; nt < 8; nt++) {
        size_t o0 = (size_t)(b * SS + tok) * QDIM + colb + nt * 8;
        size_t o1 = o0 + (size_t)8 * QDIM;
        *(uint32_t*)&ao[o0] = pack_f16(oacc[nt][0] * inv0, oacc[nt][1] * inv0);
        *(uint32_t*)&ao[o1] = pack_f16(oacc[nt][2] * inv1, oacc[nt][3] * inv1);
    }
}

// ---------------------------------------------------------------------------
extern "C" void kernel_launch(void* const* d_in, const int* in_sizes, int n_in,
                              void* d_out, int out_size)
{
    (void)in_sizes; (void)n_in; (void)out_size;
    const float* hs  = (const float*)d_in[0];
    const int*   pos = (const int*)d_in[2];
    const float* Wq  = (const float*)d_in[3];
    const float* Wk  = (const float*)d_in[4];
    const float* Wv  = (const float*)d_in[5];
    const float* Wo  = (const float*)d_in[6];
    float* out = (float*)d_out;

    __half *hsb, *q, *k, *v, *ao, *w, *wo;
    float2* rope;
    cudaGetSymbolAddress((void**)&hsb, g_hs);
    cudaGetSymbolAddress((void**)&q,  g_q);
    cudaGetSymbolAddress((void**)&k,  g_k);
    cudaGetSymbolAddress((void**)&v,  g_v);
    cudaGetSymbolAddress((void**)&ao, g_ao);
    cudaGetSymbolAddress((void**)&w,  g_wqkvT);
    cudaGetSymbolAddress((void**)&wo, g_woT);
    cudaGetSymbolAddress((void**)&rope, g_rope);

    const int M = MTOT;
    cudaFuncSetAttribute(hmma_gemm_c,   cudaFuncAttributeMaxDynamicSharedMemorySize, GEMM_SMEM);
    cudaFuncSetAttribute(hmma_gemm_qkv, cudaFuncAttributeMaxDynamicSharedMemorySize, GEMM_SMEM);
    cudaFuncSetAttribute(attn_hmma,     cudaFuncAttributeMaxDynamicSharedMemorySize, ATT_SMEM);

    prep_all<<<PREP_A + PREP_B + PREP_C + PREP_D, 256>>>(hs, Wq, Wk, Wv, Wo, hsb, w, wo, rope); // 1
    hmma_gemm_qkv<<<dim3(QKVN / 128, M / 128), 256, GEMM_SMEM>>>(hsb, w, pos, rope, q, k, v);   // 2
    attn_hmma<<<dim3(SS / 64, 2 * NKV, BB), 256, ATT_SMEM>>>(q, k, v, ao);                      // 3
    hmma_gemm_c<<<dim3(DOUT / 128, M / 128), 256, GEMM_SMEM>>>(ao, wo, out, M, DOUT, QDIM);     // 4
}

// round 15
// speedup vs baseline: 2.8106x; 1.0063x over previous
#include <cuda_runtime.h>
#include <cuda_fp16.h>
#include <math.h>
#include <stdint.h>

#define BB 2
#define SS 2048
#define DIN 4096
#define NH 32
#define NKV 8
#define HD 64
#define QDIM 2048
#define KVDIM 512
#define QKVN 3072
#define DOUT 2048
#define MTOT 4096

// ---------------- scratch (__device__ globals) ------------------------------
__device__ __half g_hs[MTOT*DIN];
__device__ __half g_q[MTOT*QDIM];            // roped Q, pre-scaled by 0.125*log2(e)
__device__ __half g_k[MTOT*KVDIM];
__device__ __half g_v[MTOT*KVDIM];
__device__ __half g_ao[MTOT*QDIM];
__device__ __half g_wqkvT[QKVN*DIN];
__device__ __half g_woT[DOUT*QDIM];
__device__ float2 g_rope[SS*32];

// ---------------- helpers ----------------------------------------------------
__device__ __forceinline__ uint32_t smem_u32(const void* p) {
    uint32_t a;
    asm("{ .reg .u64 t; cvta.to.shared.u64 t, %1; cvt.u32.u64 %0, t; }" : "=r"(a) : "l"(p));
    return a;
}

#define LDSM4(r, addr)                                                           \
    asm volatile("ldmatrix.sync.aligned.m8n8.x4.shared.b16 {%0,%1,%2,%3}, [%4];" \
        : "=r"((r)[0]), "=r"((r)[1]), "=r"((r)[2]), "=r"((r)[3]) : "r"(addr))

#define LDSM4T(r, addr)                                                          \
    asm volatile("ldmatrix.sync.aligned.m8n8.x4.trans.shared.b16 {%0,%1,%2,%3}, [%4];" \
        : "=r"((r)[0]), "=r"((r)[1]), "=r"((r)[2]), "=r"((r)[3]) : "r"(addr))

#define MMA_F16(d, a, b0, b1)                                                    \
    asm volatile("mma.sync.aligned.m16n8k16.row.col.f32.f16.f16.f32 "            \
        "{%0,%1,%2,%3}, {%4,%5,%6,%7}, {%8,%9}, {%0,%1,%2,%3};"                  \
        : "+f"((d)[0]), "+f"((d)[1]), "+f"((d)[2]), "+f"((d)[3])                 \
        : "r"((a)[0]), "r"((a)[1]), "r"((a)[2]), "r"((a)[3]), "r"(b0), "r"(b1))

#define CP_ASYNC16(dst, src)                                                     \
    asm volatile("cp.async.cg.shared.global [%0], [%1], 16;" :: "r"(dst), "l"(src) : "memory")
#define CP_COMMIT()  asm volatile("cp.async.commit_group;" ::: "memory")
#define CP_WAIT1()   asm volatile("cp.async.wait_group 1;" ::: "memory")
#define CP_WAIT0()   asm volatile("cp.async.wait_group 0;" ::: "memory")

__device__ __forceinline__ uint32_t pack_f16(float lo, float hi) {
    uint32_t r;
    asm("cvt.rn.f16x2.f32 %0, %1, %2;" : "=r"(r) : "f"(hi), "f"(lo));
    return r;
}

// 2^x for x <= 0 (scores are pre-scaled by log2(e); base change is exact for softmax)
__device__ __forceinline__ float fast_exp2(float x) {
    float t = fmaxf(x, -126.0f);
    float fi = floorf(t);
    float f = t - fi;
    float p = 1.54035304e-4f;
    p = fmaf(p, f, 1.33335581e-3f);
    p = fmaf(p, f, 9.61812911e-3f);
    p = fmaf(p, f, 5.55041087e-2f);
    p = fmaf(p, f, 2.40226507e-1f);
    p = fmaf(p, f, 6.93147181e-1f);
    p = fmaf(p, f, 1.0f);
    return p * __uint_as_float(((uint32_t)((int)fi + 127)) << 23);
}

// ---------------- unified prep kernel (grid-sectioned) -------------------------
#define PREP_A 16384
#define PREP_B 12288
#define PREP_C 4096
#define PREP_D 256

__global__ void prep_all(const float* __restrict__ hs,
                         const float* __restrict__ Wq, const float* __restrict__ Wk,
                         const float* __restrict__ Wv, const float* __restrict__ Wo,
                         __half* __restrict__ hsh, __half* __restrict__ wqkvT,
                         __half* __restrict__ woT, float2* __restrict__ rope)
{
    __shared__ float t[32][33];
    int bid = blockIdx.x;
    int tid = threadIdx.x;

    if (bid < PREP_A) {
        int i = bid * 256 + tid;
        float4 v = ((const float4*)hs)[i];
        __half hh[4];
        hh[0] = __float2half_rn(v.x); hh[1] = __float2half_rn(v.y);
        hh[2] = __float2half_rn(v.z); hh[3] = __float2half_rn(v.w);
        ((uint2*)hsh)[i] = *(uint2*)hh;
        return;
    }
    if (bid >= PREP_A + PREP_B + PREP_C) {
        int idx = (bid - PREP_A - PREP_B - PREP_C) * 256 + tid;
        int p  = idx >> 5;
        int jp = idx & 31;
        float inv = exp2f(-(float)jp * (13.287712379549449f / 32.0f));
        float s, c;
        sincosf((float)p * inv, &s, &c);
        rope[idx] = make_float2(c, s);
        return;
    }

    int x = tid & 31, y = tid >> 5;
    if (bid < PREP_A + PREP_B) {
        int b2 = bid - PREP_A;
        int n0 = (b2 % (QKVN / 32)) * 32;
        int k0 = (b2 / (QKVN / 32)) * 32;
        const float* W; int srcN, sn0;
        if (n0 < QDIM)              { W = Wq; srcN = QDIM;  sn0 = n0; }
        else if (n0 < QDIM + KVDIM) { W = Wk; srcN = KVDIM; sn0 = n0 - QDIM; }
        else                        { W = Wv; srcN = KVDIM; sn0 = n0 - QDIM - KVDIM; }
        #pragma unroll
        for (int i = 0; i < 32; i += 8)
            t[y + i][x] = W[(size_t)(k0 + y + i) * srcN + sn0 + x];
        __syncthreads();
        #pragma unroll
        for (int i = 0; i < 32; i += 8)
            wqkvT[(size_t)(n0 + y + i) * DIN + k0 + x] = __float2half_rn(t[x][y + i]);
    } else {
        int b3 = bid - PREP_A - PREP_B;
        int n0 = (b3 % (DOUT / 32)) * 32;
        int k0 = (b3 / (DOUT / 32)) * 32;
        #pragma unroll
        for (int i = 0; i < 32; i += 8)
            t[y + i][x] = Wo[(size_t)(k0 + y + i) * DOUT + n0 + x];
        __syncthreads();
        #pragma unroll
        for (int i = 0; i < 32; i += 8)
            woT[(size_t)(n0 + y + i) * QDIM + k0 + x] = __float2half_rn(t[x][y + i]);
    }
}

// ---------------- 1-term fp16 HMMA GEMM core (3-stage, 2 CTAs/SM) --------------
#define AST 40
#define TILE_E (128*AST)
#define STAGE_E (2*TILE_E)
#define NSTAGE 3
#define GEMM_SMEM (NSTAGE * STAGE_E * 2)

__device__ __forceinline__ void load_stage(
    uint32_t sbase_bytes, int tid, int bm, int bn, int k0, int K,
    const __half* __restrict__ A, const __half* __restrict__ B)
{
    #pragma unroll
    for (int i = 0; i < 4; i++) {
        int cid = tid + i * 256;
        int arr = cid >> 9;
        int rem = cid & 511;
        int row = rem >> 2;
        int c16 = rem & 3;
        const __half* g = (arr == 0)
            ? A + (size_t)(bm + row) * K + k0 + c16 * 8
            : B + (size_t)(bn + row) * K + k0 + c16 * 8;
        uint32_t d = sbase_bytes + (uint32_t)(arr * TILE_E + row * AST + c16 * 8) * 2;
        CP_ASYNC16(d, g);
    }
    CP_COMMIT();
}

__device__ __forceinline__ void gemm_mainloop(
    float acc[2][8][4], uint32_t smb, int tid, int bm, int bn, int K,
    const __half* __restrict__ A, const __half* __restrict__ B)
{
    const int wid = tid >> 5;
    const int lane = tid & 31;
    const int wm = (wid & 3) * 32;
    const int wn = (wid >> 2) * 64;
    const int nch = K >> 5;

    load_stage(smb, tid, bm, bn, 0, K, A, B);
    load_stage(smb + STAGE_E * 2, tid, bm, bn, 32, K, A, B);

    int st = 0, pst = 2;
    for (int c = 0; c < nch; c++) {
        CP_WAIT1();
        __syncthreads();

        if (c + 2 < nch)
            load_stage(smb + (uint32_t)pst * STAGE_E * 2, tid, bm, bn,
                       (c + 2) << 5, K, A, B);

        uint32_t Ab = smb + (uint32_t)st * STAGE_E * 2;
        uint32_t Bb = Ab + TILE_E * 2;

        #pragma unroll
        for (int ks = 0; ks < 2; ks++) {
            uint32_t ah[2][4], bf[4][4];
            #pragma unroll
            for (int mt = 0; mt < 2; mt++) {
                int row = wm + mt * 16 + (lane & 15);
                int col = ks * 16 + ((lane >> 4) << 3);
                LDSM4(ah[mt], Ab + (uint32_t)(row * AST + col) * 2);
            }
            #pragma unroll
            for (int p = 0; p < 4; p++) {
                int row = wn + p * 16 + (lane & 7) + ((lane >> 4) << 3);
                int col = ks * 16 + (((lane >> 3) & 1) << 3);
                LDSM4(bf[p], Bb + (uint32_t)(row * AST + col) * 2);
            }
            #pragma unroll
            for (int mt = 0; mt < 2; mt++) {
                #pragma unroll
                for (int nt = 0; nt < 8; nt++) {
                    uint32_t b0 = bf[nt >> 1][(nt & 1) * 2];
                    uint32_t b1 = bf[nt >> 1][(nt & 1) * 2 + 1];
                    MMA_F16(acc[mt][nt], ah[mt], b0, b1);
                }
            }
        }
        st = (st == 2) ? 0 : st + 1;
        pst = (pst == 2) ? 0 : pst + 1;
    }
}

// O projection: fp32 C output (2 CTAs/SM)
__global__ __launch_bounds__(256, 2)
void hmma_gemm_c(const __half* __restrict__ A, const __half* __restrict__ B,
                 float* __restrict__ C, int M, int N, int K)
{
    extern __shared__ __half sm[];
    const int tid = threadIdx.x;
    const int wid = tid >> 5, lane = tid & 31;
    const int bm = blockIdx.y * 128, bn = blockIdx.x * 128;
    const int wm = (wid & 3) * 32, wn = (wid >> 2) * 64;

    float acc[2][8][4];
    #pragma unroll
    for (int mt = 0; mt < 2; mt++)
        #pragma unroll
        for (int nt = 0; nt < 8; nt++)
            #pragma unroll
            for (int j = 0; j < 4; j++) acc[mt][nt][j] = 0.f;

    gemm_mainloop(acc, smem_u32(sm), tid, bm, bn, K, A, B);

    #pragma unroll
    for (int mt = 0; mt < 2; mt++)
        #pragma unroll
        for (int nt = 0; nt < 8; nt++) {
            int r0  = bm + wm + mt * 16 + (lane >> 2);
            int col = bn + wn + nt * 8 + (lane & 3) * 2;
            *(float2*)&C[(size_t)r0 * N + col] = make_float2(acc[mt][nt][0], acc[mt][nt][1]);
            *(float2*)&C[(size_t)(r0 + 8) * N + col] = make_float2(acc[mt][nt][2], acc[mt][nt][3]);
        }
}

// QKV GEMM with fused RoPE epilogue (table-based; 2 CTAs/SM)
// Q pre-scale folds in log2(e) so attention softmax can use exp2.
__global__ __launch_bounds__(256, 2)
void hmma_gemm_qkv(const __half* __restrict__ A, const __half* __restrict__ B,
                   const int* __restrict__ pos, const float2* __restrict__ rope,
                   __half* __restrict__ q, __half* __restrict__ k,
                   __half* __restrict__ v)
{
    extern __shared__ __half sm[];
    const int tid = threadIdx.x;
    const int wid = tid >> 5, lane = tid & 31;
    const int bm = blockIdx.y * 128, bn = blockIdx.x * 128;
    const int wm = (wid & 3) * 32, wn = (wid >> 2) * 64;

    float acc[2][8][4];
    #pragma unroll
    for (int mt = 0; mt < 2; mt++)
        #pragma unroll
        for (int nt = 0; nt < 8; nt++)
            #pragma unroll
            for (int j = 0; j < 4; j++) acc[mt][nt][j] = 0.f;

    gemm_mainloop(acc, smem_u32(sm), tid, bm, bn, DIN, A, B);

    const int ncol0 = bn + wn;
    if (ncol0 >= QDIM + KVDIM) {
        int colb = ncol0 - (QDIM + KVDIM) + (lane & 3) * 2;
        #pragma unroll
        for (int mt = 0; mt < 2; mt++)
            #pragma unroll
            for (int nt = 0; nt < 8; nt++)
                #pragma unroll
                for (int rs = 0; rs < 2; rs++) {
                    int m = bm + wm + mt * 16 + (lane >> 2) + rs * 8;
                    size_t o = (size_t)m * KVDIM + colb + nt * 8;
                    *(uint32_t*)&v[o] = pack_f16(acc[mt][nt][rs * 2], acc[mt][nt][rs * 2 + 1]);
                }
    } else {
        const int isQ = ncol0 < QDIM;
        const float scale = isQ ? 0.18033688011112042f : 1.0f;  // 0.125 * log2(e)
        __half* dst = isQ ? q : k;
        const int stride = isQ ? QDIM : KVDIM;
        const int colbase = isQ ? ncol0 : ncol0 - QDIM;
        #pragma unroll
        for (int mt = 0; mt < 2; mt++)
            #pragma unroll
            for (int rs = 0; rs < 2; rs++) {
                int m = bm + wm + mt * 16 + (lane >> 2) + rs * 8;
                const float2* rrow = rope + (size_t)pos[m] * 32;
                #pragma unroll
                for (int nt = 0; nt < 4; nt++) {
                    int jp0 = nt * 8 + (lane & 3) * 2;
                    float4 cs2 = *(const float4*)&rrow[jp0];
                    float y1[2], y2[2];
                    {
                        float v1 = acc[mt][nt][rs * 2], v2 = acc[mt][nt + 4][rs * 2];
                        y1[0] = (v1 * cs2.x - v2 * cs2.y) * scale;
                        y2[0] = (v2 * cs2.x + v1 * cs2.y) * scale;
                    }
                    {
                        float v1 = acc[mt][nt][rs * 2 + 1], v2 = acc[mt][nt + 4][rs * 2 + 1];
                        y1[1] = (v1 * cs2.z - v2 * cs2.w) * scale;
                        y2[1] = (v2 * cs2.z + v1 * cs2.w) * scale;
                    }
                    size_t o = (size_t)m * stride + colbase + jp0;
                    *(uint32_t*)&dst[o]      = pack_f16(y1[0], y1[1]);
                    *(uint32_t*)&dst[o + 32] = pack_f16(y2[0], y2[1]);
                }
            }
    }
}

// ---------------- HMMA flash attention (M=128 tile, 2 CTAs/SM) -----------------
#define QST 72
#define ATT_Q_E  (128*QST)
#define ATT_KV_E (64*QST)
#define ATT_KV_STAGE (2*ATT_KV_E*2)
#define ATT_QBYTES (ATT_Q_E*2)
#define ATT_SMEM (ATT_QBYTES + 3*ATT_KV_STAGE)   // 73728 B -> 2 CTAs/SM

__device__ __forceinline__ void attn_load_kv(
    uint32_t stage_base, int tid, int b, int kvh, int kt,
    const __half* __restrict__ k, const __half* __restrict__ v)
{
    #pragma unroll
    for (int it = 0; it < 4; it++) {
        int cid = tid + it * 256;
        int arr = cid >> 9;
        int rem = cid & 511;
        int row = rem >> 3;
        int c   = rem & 7;
        const __half* base = (arr == 0) ? k : v;
        const __half* src = base + (size_t)(b * SS + kt * 64 + row) * KVDIM + kvh * 64 + c * 8;
        CP_ASYNC16(stage_base + (uint32_t)arr * ATT_KV_E * 2 + (uint32_t)(row * QST + c * 8) * 2, src);
    }
    CP_COMMIT();
}

__global__ __launch_bounds__(256, 2)
void attn_hmma(const __half* __restrict__ q, const __half* __restrict__ k,
               const __half* __restrict__ v, __half* __restrict__ ao)
{
    extern __shared__ __half smatt[];
    const int qt    = gridDim.x - 1 - blockIdx.x;
    const int hp    = blockIdx.y;
    const int kvh   = hp >> 1;
    const int hpair = hp & 1;
    const int b     = blockIdx.z;
    const int tid = threadIdx.x, wid = tid >> 5, lane = tid & 31;

    const uint32_t smb = smem_u32(smatt);
    const uint32_t Q_o = smb;

    // Q tile load: 128 rows x 64 cols
    #pragma unroll
    for (int it = 0; it < 4; it++) {
        int cid = tid + it * 256;
        int row = cid >> 3;
        int c   = cid & 7;
        const __half* src = q
            + (size_t)(b * SS + qt * 64 + (row & 63)) * QDIM
            + (kvh * 4 + hpair * 2 + (row >> 6)) * 64 + c * 8;
        CP_ASYNC16(Q_o + (uint32_t)(row * QST + c * 8) * 2, src);
    }
    CP_COMMIT();

    attn_load_kv(smb + ATT_QBYTES, tid, b, kvh, 0, k, v);
    if (qt >= 1)
        attn_load_kv(smb + ATT_QBYTES + ATT_KV_STAGE, tid, b, kvh, 1, k, v);

    float m_r[2], l_r[2], oacc[8][4];
    m_r[0] = -1e30f; m_r[1] = -1e30f;
    l_r[0] = 0.f;    l_r[1] = 0.f;
    #pragma unroll
    for (int nt = 0; nt < 8; nt++)
        #pragma unroll
        for (int j = 0; j < 4; j++) oacc[nt][j] = 0.f;

    const int wrow  = wid * 16;
    const int hloc  = wid >> 2;
    const int rtile = (wid & 3) * 16;

    uint32_t qa_reg[4][4];   // Q fragments, loop-invariant: loaded once at kt=0

    int st = 0;
    for (int kt = 0; kt <= qt; kt++) {
        if (kt < qt) CP_WAIT1(); else CP_WAIT0();
        __syncthreads();

        if (kt == 0) {
            #pragma unroll
            for (int ks = 0; ks < 4; ks++) {
                int row = wrow + (lane & 15);
                int col = ks * 16 + ((lane >> 4) << 3);
                LDSM4(qa_reg[ks], Q_o + (uint32_t)(row * QST + col) * 2);
            }
        }

        if (kt + 2 <= qt)
            attn_load_kv(smb + ATT_QBYTES + (uint32_t)((kt + 2) % 3) * ATT_KV_STAGE,
                         tid, b, kvh, kt + 2, k, v);

        const uint32_t stg = smb + ATT_QBYTES + (uint32_t)st * ATT_KV_STAGE;
        const uint32_t K_o = stg;
        const uint32_t V_o = stg + ATT_KV_E * 2;

        // ---- S = Q K^T (1-term; Q frags from registers)
        float sacc[8][4];
        #pragma unroll
        for (int nt = 0; nt < 8; nt++)
            #pragma unroll
            for (int j = 0; j < 4; j++) sacc[nt][j] = 0.f;

        #pragma unroll
        for (int ks = 0; ks < 4; ks++) {
            uint32_t kb[4][4];
            #pragma unroll
            for (int p = 0; p < 4; p++) {
                int row = p * 16 + (lane & 7) + ((lane >> 4) << 3);
                int col = ks * 16 + (((lane >> 3) & 1) << 3);
                LDSM4(kb[p], K_o + (uint32_t)(row * QST + col) * 2);
            }
            #pragma unroll
            for (int nt = 0; nt < 8; nt++) {
                uint32_t b0 = kb[nt >> 1][(nt & 1) * 2];
                uint32_t b1 = kb[nt >> 1][(nt & 1) * 2 + 1];
                MMA_F16(sacc[nt], qa_reg[ks], b0, b1);
            }
        }

        if (kt == qt) {
            #pragma unroll
            for (int nt = 0; nt < 8; nt++)
                #pragma unroll
                for (int cc = 0; cc < 4; cc++) {
                    int rloc = rtile + (lane >> 2) + ((cc >= 2) ? 8 : 0);
                    int cloc = nt * 8 + (lane & 3) * 2 + (cc & 1);
                    if (cloc > rloc) sacc[nt][cc] = -1e30f;
                }
        }

        // ---- online softmax (base-2 domain)
        {
            float mx0 = -1e30f, mx1 = -1e30f;
            #pragma unroll
            for (int nt = 0; nt < 8; nt++) {
                mx0 = fmaxf(mx0, fmaxf(sacc[nt][0], sacc[nt][1]));
                mx1 = fmaxf(mx1, fmaxf(sacc[nt][2], sacc[nt][3]));
            }
            mx0 = fmaxf(mx0, __shfl_xor_sync(0xffffffffu, mx0, 1));
            mx0 = fmaxf(mx0, __shfl_xor_sync(0xffffffffu, mx0, 2));
            mx1 = fmaxf(mx1, __shfl_xor_sync(0xffffffffu, mx1, 1));
            mx1 = fmaxf(mx1, __shfl_xor_sync(0xffffffffu, mx1, 2));
            float mn0 = fmaxf(m_r[0], mx0);
            float mn1 = fmaxf(m_r[1], mx1);
            float sc0 = fast_exp2(m_r[0] - mn0);
            float sc1 = fast_exp2(m_r[1] - mn1);
            m_r[0] = mn0; m_r[1] = mn1;
            float sum0 = 0.f, sum1 = 0.f;
            #pragma unroll
            for (int nt = 0; nt < 8; nt++) {
                float p0 = fast_exp2(sacc[nt][0] - mn0);
                float p1 = fast_exp2(sacc[nt][1] - mn0);
                float p2 = fast_exp2(sacc[nt][2] - mn1);
                float p3 = fast_exp2(sacc[nt][3] - mn1);
                sacc[nt][0] = p0; sacc[nt][1] = p1;
                sacc[nt][2] = p2; sacc[nt][3] = p3;
                sum0 += p0 + p1; sum1 += p2 + p3;
                oacc[nt][0] *= sc0; oacc[nt][1] *= sc0;
                oacc[nt][2] *= sc1; oacc[nt][3] *= sc1;
            }
            l_r[0] = l_r[0] * sc0 + sum0;
            l_r[1] = l_r[1] * sc1 + sum1;
        }

        // ---- O += P V (1-term)
        #pragma unroll
        for (int j = 0; j < 4; j++) {
            uint32_t vb[4][4];
            int tok_off = (lane & 7) + (((lane >> 3) & 1) << 3);
            int d_off   = ((lane >> 4) & 1) << 3;
            #pragma unroll
            for (int p = 0; p < 4; p++) {
                uint32_t off = (uint32_t)((j * 16 + tok_off) * QST + p * 16 + d_off) * 2;
                LDSM4T(vb[p], V_o + off);
            }
            uint32_t ah[4];
            #pragma unroll
            for (int qd = 0; qd < 4; qd++) {
                int nt = 2 * j + (qd >> 1);
                ah[qd] = pack_f16(sacc[nt][(qd & 1) * 2], sacc[nt][(qd & 1) * 2 + 1]);
            }
            #pragma unroll
            for (int nt = 0; nt < 8; nt++) {
                uint32_t b0 = vb[nt >> 1][(nt & 1) * 2];
                uint32_t b1 = vb[nt >> 1][(nt & 1) * 2 + 1];
                MMA_F16(oacc[nt], ah, b0, b1);
            }
        }
        st = (st == 2) ? 0 : st + 1;
    }

    // ---- epilogue
    l_r[0] += __shfl_xor_sync(0xffffffffu, l_r[0], 1);
    l_r[0] += __shfl_xor_sync(0xffffffffu, l_r[0], 2);
    l_r[1] += __shfl_xor_sync(0xffffffffu, l_r[1], 1);
    l_r[1] += __shfl_xor_sync(0xffffffffu, l_r[1], 2);
    float inv0 = 1.0f / l_r[0];
    float inv1 = 1.0f / l_r[1];
    int tok = qt * 64 + rtile + (lane >> 2);
    int colb = (kvh * 4 + hpair * 2 + hloc) * 64 + (lane & 3) * 2;
    #pragma unroll
    for (int nt = 0; nt < 8; nt++) {
        size_t o0 = (size_t)(b * SS + tok) * QDIM + colb + nt * 8;
        size_t o1 = o0 + (size_t)8 * QDIM;
        *(uint32_t*)&ao[o0] = pack_f16(oacc[nt][0] * inv0, oacc[nt][1] * inv0);
        *(uint32_t*)&ao[o1] = pack_f16(oacc[nt][2] * inv1, oacc[nt][3] * inv1);
    }
}

// ---------------------------------------------------------------------------
extern "C" void kernel_launch(void* const* d_in, const int* in_sizes, int n_in,
                              void* d_out, int out_size)
{
    (void)in_sizes; (void)n_in; (void)out_size;
    const float* hs  = (const float*)d_in[0];
    const int*   pos = (const int*)d_in[2];
    const float* Wq  = (const float*)d_in[3];
    const float* Wk  = (const float*)d_in[4];
    const float* Wv  = (const float*)d_in[5];
    const float* Wo  = (const float*)d_in[6];
    float* out = (float*)d_out;

    __half *hsb, *q, *k, *v, *ao, *w, *wo;
    float2* rope;
    cudaGetSymbolAddress((void**)&hsb, g_hs);
    cudaGetSymbolAddress((void**)&q,  g_q);
    cudaGetSymbolAddress((void**)&k,  g_k);
    cudaGetSymbolAddress((void**)&v,  g_v);
    cudaGetSymbolAddress((void**)&ao, g_ao);
    cudaGetSymbolAddress((void**)&w,  g_wqkvT);
    cudaGetSymbolAddress((void**)&wo, g_woT);
    cudaGetSymbolAddress((void**)&rope, g_rope);

    const int M = MTOT;
    cudaFuncSetAttribute(hmma_gemm_c,   cudaFuncAttributeMaxDynamicSharedMemorySize, GEMM_SMEM);
    cudaFuncSetAttribute(hmma_gemm_qkv, cudaFuncAttributeMaxDynamicSharedMemorySize, GEMM_SMEM);
    cudaFuncSetAttribute(attn_hmma,     cudaFuncAttributeMaxDynamicSharedMemorySize, ATT_SMEM);

    prep_all<<<PREP_A + PREP_B + PREP_C + PREP_D, 256>>>(hs, Wq, Wk, Wv, Wo, hsb, w, wo, rope); // 1
    hmma_gemm_qkv<<<dim3(QKVN / 128, M / 128), 256, GEMM_SMEM>>>(hsb, w, pos, rope, q, k, v);   // 2
    attn_hmma<<<dim3(SS / 64, 2 * NKV, BB), 256, ATT_SMEM>>>(q, k, v, ao);                      // 3
    hmma_gemm_c<<<dim3(DOUT / 128, M / 128), 256, GEMM_SMEM>>>(ao, wo, out, M, DOUT, QDIM);     // 4
}

// round 16
// speedup vs baseline: 3.0516x; 1.0858x over previous
#include <cuda_runtime.h>
#include <cuda_fp16.h>
#include <math.h>
#include <stdint.h>

#define BB 2
#define SS 2048
#define DIN 4096
#define NH 32
#define NKV 8
#define HD 64
#define QDIM 2048
#define KVDIM 512
#define QKVN 3072
#define DOUT 2048
#define MTOT 4096

// ---------------- scratch (__device__ globals) ------------------------------
__device__ __half g_hs[MTOT*DIN];
__device__ __half g_q[MTOT*QDIM];            // roped Q, pre-scaled by 0.125*log2(e)
__device__ __half g_k[MTOT*KVDIM];
__device__ __half g_v[MTOT*KVDIM];
__device__ __half g_ao[MTOT*QDIM];
__device__ __half g_wqkvT[QKVN*DIN];
__device__ __half g_woT[DOUT*QDIM];
__device__ float2 g_rope[SS*32];

// ---------------- helpers ----------------------------------------------------
__device__ __forceinline__ uint32_t smem_u32(const void* p) {
    uint32_t a;
    asm("{ .reg .u64 t; cvta.to.shared.u64 t, %1; cvt.u32.u64 %0, t; }" : "=r"(a) : "l"(p));
    return a;
}

#define LDSM4(r, addr)                                                           \
    asm volatile("ldmatrix.sync.aligned.m8n8.x4.shared.b16 {%0,%1,%2,%3}, [%4];" \
        : "=r"((r)[0]), "=r"((r)[1]), "=r"((r)[2]), "=r"((r)[3]) : "r"(addr))

#define LDSM4T(r, addr)                                                          \
    asm volatile("ldmatrix.sync.aligned.m8n8.x4.trans.shared.b16 {%0,%1,%2,%3}, [%4];" \
        : "=r"((r)[0]), "=r"((r)[1]), "=r"((r)[2]), "=r"((r)[3]) : "r"(addr))

#define MMA_F16(d, a, b0, b1)                                                    \
    asm volatile("mma.sync.aligned.m16n8k16.row.col.f32.f16.f16.f32 "            \
        "{%0,%1,%2,%3}, {%4,%5,%6,%7}, {%8,%9}, {%0,%1,%2,%3};"                  \
        : "+f"((d)[0]), "+f"((d)[1]), "+f"((d)[2]), "+f"((d)[3])                 \
        : "r"((a)[0]), "r"((a)[1]), "r"((a)[2]), "r"((a)[3]), "r"(b0), "r"(b1))

#define CP_ASYNC16(dst, src)                                                     \
    asm volatile("cp.async.cg.shared.global [%0], [%1], 16;" :: "r"(dst), "l"(src) : "memory")
#define CP_COMMIT()  asm volatile("cp.async.commit_group;" ::: "memory")
#define CP_WAIT1()   asm volatile("cp.async.wait_group 1;" ::: "memory")
#define CP_WAIT0()   asm volatile("cp.async.wait_group 0;" ::: "memory")

__device__ __forceinline__ uint32_t pack_f16(float lo, float hi) {
    uint32_t r;
    asm("cvt.rn.f16x2.f32 %0, %1, %2;" : "=r"(r) : "f"(hi), "f"(lo));
    return r;
}

// 2^x for x <= 0 (scores pre-scaled by log2(e); base change exact for softmax)
__device__ __forceinline__ float fast_exp2(float x) {
    float t = fmaxf(x, -126.0f);
    float fi = floorf(t);
    float f = t - fi;
    float p = 1.54035304e-4f;
    p = fmaf(p, f, 1.33335581e-3f);
    p = fmaf(p, f, 9.61812911e-3f);
    p = fmaf(p, f, 5.55041087e-2f);
    p = fmaf(p, f, 2.40226507e-1f);
    p = fmaf(p, f, 6.93147181e-1f);
    p = fmaf(p, f, 1.0f);
    return p * __uint_as_float(((uint32_t)((int)fi + 127)) << 23);
}

// ---------------- unified prep kernel (grid-sectioned) -------------------------
#define PREP_A 16384
#define PREP_B 12288
#define PREP_C 4096
#define PREP_D 256

__global__ void prep_all(const float* __restrict__ hs,
                         const float* __restrict__ Wq, const float* __restrict__ Wk,
                         const float* __restrict__ Wv, const float* __restrict__ Wo,
                         __half* __restrict__ hsh, __half* __restrict__ wqkvT,
                         __half* __restrict__ woT, float2* __restrict__ rope)
{
    __shared__ float t[32][33];
    int bid = blockIdx.x;
    int tid = threadIdx.x;

    if (bid < PREP_A) {
        int i = bid * 256 + tid;
        float4 v = ((const float4*)hs)[i];
        __half hh[4];
        hh[0] = __float2half_rn(v.x); hh[1] = __float2half_rn(v.y);
        hh[2] = __float2half_rn(v.z); hh[3] = __float2half_rn(v.w);
        ((uint2*)hsh)[i] = *(uint2*)hh;
        return;
    }
    if (bid >= PREP_A + PREP_B + PREP_C) {
        int idx = (bid - PREP_A - PREP_B - PREP_C) * 256 + tid;
        int p  = idx >> 5;
        int jp = idx & 31;
        float inv = exp2f(-(float)jp * (13.287712379549449f / 32.0f));
        float s, c;
        sincosf((float)p * inv, &s, &c);
        rope[idx] = make_float2(c, s);
        return;
    }

    int x = tid & 31, y = tid >> 5;
    if (bid < PREP_A + PREP_B) {
        int b2 = bid - PREP_A;
        int n0 = (b2 % (QKVN / 32)) * 32;
        int k0 = (b2 / (QKVN / 32)) * 32;
        const float* W; int srcN, sn0;
        if (n0 < QDIM)              { W = Wq; srcN = QDIM;  sn0 = n0; }
        else if (n0 < QDIM + KVDIM) { W = Wk; srcN = KVDIM; sn0 = n0 - QDIM; }
        else                        { W = Wv; srcN = KVDIM; sn0 = n0 - QDIM - KVDIM; }
        #pragma unroll
        for (int i = 0; i < 32; i += 8)
            t[y + i][x] = W[(size_t)(k0 + y + i) * srcN + sn0 + x];
        __syncthreads();
        #pragma unroll
        for (int i = 0; i < 32; i += 8)
            wqkvT[(size_t)(n0 + y + i) * DIN + k0 + x] = __float2half_rn(t[x][y + i]);
    } else {
        int b3 = bid - PREP_A - PREP_B;
        int n0 = (b3 % (DOUT / 32)) * 32;
        int k0 = (b3 / (DOUT / 32)) * 32;
        #pragma unroll
        for (int i = 0; i < 32; i += 8)
            t[y + i][x] = Wo[(size_t)(k0 + y + i) * DOUT + n0 + x];
        __syncthreads();
        #pragma unroll
        for (int i = 0; i < 32; i += 8)
            woT[(size_t)(n0 + y + i) * QDIM + k0 + x] = __float2half_rn(t[x][y + i]);
    }
}

// ---------------- 1-term fp16 HMMA GEMM core (K-chunk 64, 2-stage, 2 CTAs/SM) --
#define AST 72                     // 64 cols + 8 pad (halfs)
#define TILE_E (128*AST)           // per array per stage
#define STAGE_E (2*TILE_E)         // A | B
#define GEMM_SMEM (2 * STAGE_E * 2)   // 73728 B -> 2 CTAs/SM

__device__ __forceinline__ void load_stage(
    uint32_t sbase_bytes, int tid, int bm, int bn, int k0, int K,
    const __half* __restrict__ A, const __half* __restrict__ B)
{
    #pragma unroll
    for (int i = 0; i < 8; i++) {
        int cid = tid + i * 256;       // 0..2047
        int arr = cid >> 10;           // 0:A 1:B
        int rem = cid & 1023;
        int row = rem >> 3;            // 0..127
        int c16 = rem & 7;             // 16B chunk within 64-col row
        const __half* g = (arr == 0)
            ? A + (size_t)(bm + row) * K + k0 + c16 * 8
            : B + (size_t)(bn + row) * K + k0 + c16 * 8;
        uint32_t d = sbase_bytes + (uint32_t)(arr * TILE_E + row * AST + c16 * 8) * 2;
        CP_ASYNC16(d, g);
    }
    CP_COMMIT();
}

__device__ __forceinline__ void gemm_mainloop(
    float acc[2][8][4], uint32_t smb, int tid, int bm, int bn, int K,
    const __half* __restrict__ A, const __half* __restrict__ B)
{
    const int wid = tid >> 5;
    const int lane = tid & 31;
    const int wm = (wid & 3) * 32;
    const int wn = (wid >> 2) * 64;
    const int nch = K >> 6;

    load_stage(smb, tid, bm, bn, 0, K, A, B);

    for (int c = 0; c < nch; c++) {
        int buf = c & 1;
        CP_WAIT0();          // chunk c resident
        __syncthreads();     // all warps done with buf^1 (chunk c-1)

        if (c + 1 < nch)
            load_stage(smb + (uint32_t)(buf ^ 1) * STAGE_E * 2, tid, bm, bn,
                       (c + 1) << 6, K, A, B);

        uint32_t Ab = smb + (uint32_t)buf * STAGE_E * 2;
        uint32_t Bb = Ab + TILE_E * 2;

        #pragma unroll
        for (int ks = 0; ks < 4; ks++) {
            uint32_t ah[2][4], bf[4][4];
            #pragma unroll
            for (int mt = 0; mt < 2; mt++) {
                int row = wm + mt * 16 + (lane & 15);
                int col = ks * 16 + ((lane >> 4) << 3);
                LDSM4(ah[mt], Ab + (uint32_t)(row * AST + col) * 2);
            }
            #pragma unroll
            for (int p = 0; p < 4; p++) {
                int row = wn + p * 16 + (lane & 7) + ((lane >> 4) << 3);
                int col = ks * 16 + (((lane >> 3) & 1) << 3);
                LDSM4(bf[p], Bb + (uint32_t)(row * AST + col) * 2);
            }
            #pragma unroll
            for (int mt = 0; mt < 2; mt++) {
                #pragma unroll
                for (int nt = 0; nt < 8; nt++) {
                    uint32_t b0 = bf[nt >> 1][(nt & 1) * 2];
                    uint32_t b1 = bf[nt >> 1][(nt & 1) * 2 + 1];
                    MMA_F16(acc[mt][nt], ah[mt], b0, b1);
                }
            }
        }
    }
}

// O projection: fp32 C output (2 CTAs/SM)
__global__ __launch_bounds__(256, 2)
void hmma_gemm_c(const __half* __restrict__ A, const __half* __restrict__ B,
                 float* __restrict__ C, int M, int N, int K)
{
    extern __shared__ __half sm[];
    const int tid = threadIdx.x;
    const int wid = tid >> 5, lane = tid & 31;
    const int bm = blockIdx.y * 128, bn = blockIdx.x * 128;
    const int wm = (wid & 3) * 32, wn = (wid >> 2) * 64;

    float acc[2][8][4];
    #pragma unroll
    for (int mt = 0; mt < 2; mt++)
        #pragma unroll
        for (int nt = 0; nt < 8; nt++)
            #pragma unroll
            for (int j = 0; j < 4; j++) acc[mt][nt][j] = 0.f;

    gemm_mainloop(acc, smem_u32(sm), tid, bm, bn, K, A, B);

    #pragma unroll
    for (int mt = 0; mt < 2; mt++)
        #pragma unroll
        for (int nt = 0; nt < 8; nt++) {
            int r0  = bm + wm + mt * 16 + (lane >> 2);
            int col = bn + wn + nt * 8 + (lane & 3) * 2;
            *(float2*)&C[(size_t)r0 * N + col] = make_float2(acc[mt][nt][0], acc[mt][nt][1]);
            *(float2*)&C[(size_t)(r0 + 8) * N + col] = make_float2(acc[mt][nt][2], acc[mt][nt][3]);
        }
}

// QKV GEMM with fused RoPE epilogue (table-based; 2 CTAs/SM)
__global__ __launch_bounds__(256, 2)
void hmma_gemm_qkv(const __half* __restrict__ A, const __half* __restrict__ B,
                   const int* __restrict__ pos, const float2* __restrict__ rope,
                   __half* __restrict__ q, __half* __restrict__ k,
                   __half* __restrict__ v)
{
    extern __shared__ __half sm[];
    const int tid = threadIdx.x;
    const int wid = tid >> 5, lane = tid & 31;
    const int bm = blockIdx.y * 128, bn = blockIdx.x * 128;
    const int wm = (wid & 3) * 32, wn = (wid >> 2) * 64;

    float acc[2][8][4];
    #pragma unroll
    for (int mt = 0; mt < 2; mt++)
        #pragma unroll
        for (int nt = 0; nt < 8; nt++)
            #pragma unroll
            for (int j = 0; j < 4; j++) acc[mt][nt][j] = 0.f;

    gemm_mainloop(acc, smem_u32(sm), tid, bm, bn, DIN, A, B);

    const int ncol0 = bn + wn;
    if (ncol0 >= QDIM + KVDIM) {
        int colb = ncol0 - (QDIM + KVDIM) + (lane & 3) * 2;
        #pragma unroll
        for (int mt = 0; mt < 2; mt++)
            #pragma unroll
            for (int nt = 0; nt < 8; nt++)
                #pragma unroll
                for (int rs = 0; rs < 2; rs++) {
                    int m = bm + wm + mt * 16 + (lane >> 2) + rs * 8;
                    size_t o = (size_t)m * KVDIM + colb + nt * 8;
                    *(uint32_t*)&v[o] = pack_f16(acc[mt][nt][rs * 2], acc[mt][nt][rs * 2 + 1]);
                }
    } else {
        const int isQ = ncol0 < QDIM;
        const float scale = isQ ? 0.18033688011112042f : 1.0f;  // 0.125 * log2(e)
        __half* dst = isQ ? q : k;
        const int stride = isQ ? QDIM : KVDIM;
        const int colbase = isQ ? ncol0 : ncol0 - QDIM;
        #pragma unroll
        for (int mt = 0; mt < 2; mt++)
            #pragma unroll
            for (int rs = 0; rs < 2; rs++) {
                int m = bm + wm + mt * 16 + (lane >> 2) + rs * 8;
                const float2* rrow = rope + (size_t)pos[m] * 32;
                #pragma unroll
                for (int nt = 0; nt < 4; nt++) {
                    int jp0 = nt * 8 + (lane & 3) * 2;
                    float4 cs2 = *(const float4*)&rrow[jp0];
                    float y1[2], y2[2];
                    {
                        float v1 = acc[mt][nt][rs * 2], v2 = acc[mt][nt + 4][rs * 2];
                        y1[0] = (v1 * cs2.x - v2 * cs2.y) * scale;
                        y2[0] = (v2 * cs2.x + v1 * cs2.y) * scale;
                    }
                    {
                        float v1 = acc[mt][nt][rs * 2 + 1], v2 = acc[mt][nt + 4][rs * 2 + 1];
                        y1[1] = (v1 * cs2.z - v2 * cs2.w) * scale;
                        y2[1] = (v2 * cs2.z + v1 * cs2.w) * scale;
                    }
                    size_t o = (size_t)m * stride + colbase + jp0;
                    *(uint32_t*)&dst[o]      = pack_f16(y1[0], y1[1]);
                    *(uint32_t*)&dst[o + 32] = pack_f16(y2[0], y2[1]);
                }
            }
    }
}

// ---------------- HMMA flash attention (M=128 tile, 2 CTAs/SM) -----------------
#define QST 72
#define ATT_Q_E  (128*QST)
#define ATT_KV_E (64*QST)
#define ATT_KV_STAGE (2*ATT_KV_E*2)
#define ATT_QBYTES (ATT_Q_E*2)
#define ATT_SMEM (ATT_QBYTES + 3*ATT_KV_STAGE)   // 73728 B -> 2 CTAs/SM

__device__ __forceinline__ void attn_load_kv(
    uint32_t stage_base, int tid, int b, int kvh, int kt,
    const __half* __restrict__ k, const __half* __restrict__ v)
{
    #pragma unroll
    for (int it = 0; it < 4; it++) {
        int cid = tid + it * 256;
        int arr = cid >> 9;
        int rem = cid & 511;
        int row = rem >> 3;
        int c   = rem & 7;
        const __half* base = (arr == 0) ? k : v;
        const __half* src = base + (size_t)(b * SS + kt * 64 + row) * KVDIM + kvh * 64 + c * 8;
        CP_ASYNC16(stage_base + (uint32_t)arr * ATT_KV_E * 2 + (uint32_t)(row * QST + c * 8) * 2, src);
    }
    CP_COMMIT();
}

__global__ __launch_bounds__(256, 2)
void attn_hmma(const __half* __restrict__ q, const __half* __restrict__ k,
               const __half* __restrict__ v, __half* __restrict__ ao)
{
    extern __shared__ __half smatt[];
    const int qt    = gridDim.x - 1 - blockIdx.x;
    const int hp    = blockIdx.y;
    const int kvh   = hp >> 1;
    const int hpair = hp & 1;
    const int b     = blockIdx.z;
    const int tid = threadIdx.x, wid = tid >> 5, lane = tid & 31;

    const uint32_t smb = smem_u32(smatt);
    const uint32_t Q_o = smb;

    #pragma unroll
    for (int it = 0; it < 4; it++) {
        int cid = tid + it * 256;
        int row = cid >> 3;
        int c   = cid & 7;
        const __half* src = q
            + (size_t)(b * SS + qt * 64 + (row & 63)) * QDIM
            + (kvh * 4 + hpair * 2 + (row >> 6)) * 64 + c * 8;
        CP_ASYNC16(Q_o + (uint32_t)(row * QST + c * 8) * 2, src);
    }
    CP_COMMIT();

    attn_load_kv(smb + ATT_QBYTES, tid, b, kvh, 0, k, v);
    if (qt >= 1)
        attn_load_kv(smb + ATT_QBYTES + ATT_KV_STAGE, tid, b, kvh, 1, k, v);

    float m_r[2], l_r[2], oacc[8][4];
    m_r[0] = -1e30f; m_r[1] = -1e30f;
    l_r[0] = 0.f;    l_r[1] = 0.f;
    #pragma unroll
    for (int nt = 0; nt < 8; nt++)
        #pragma unroll
        for (int j = 0; j < 4; j++) oacc[nt][j] = 0.f;

    const int wrow  = wid * 16;
    const int hloc  = wid >> 2;
    const int rtile = (wid & 3) * 16;

    uint32_t qa_reg[4][4];

    int st = 0;
    for (int kt = 0; kt <= qt; kt++) {
        if (kt < qt) CP_WAIT1(); else CP_WAIT0();
        __syncthreads();

        if (kt == 0) {
            #pragma unroll
            for (int ks = 0; ks < 4; ks++) {
                int row = wrow + (lane & 15);
                int col = ks * 16 + ((lane >> 4) << 3);
                LDSM4(qa_reg[ks], Q_o + (uint32_t)(row * QST + col) * 2);
            }
        }

        if (kt + 2 <= qt)
            attn_load_kv(smb + ATT_QBYTES + (uint32_t)((kt + 2) % 3) * ATT_KV_STAGE,
                         tid, b, kvh, kt + 2, k, v);

        const uint32_t stg = smb + ATT_QBYTES + (uint32_t)st * ATT_KV_STAGE;
        const uint32_t K_o = stg;
        const uint32_t V_o = stg + ATT_KV_E * 2;

        float sacc[8][4];
        #pragma unroll
        for (int nt = 0; nt < 8; nt++)
            #pragma unroll
            for (int j = 0; j < 4; j++) sacc[nt][j] = 0.f;

        #pragma unroll
        for (int ks = 0; ks < 4; ks++) {
            uint32_t kb[4][4];
            #pragma unroll
            for (int p = 0; p < 4; p++) {
                int row = p * 16 + (lane & 7) + ((lane >> 4) << 3);
                int col = ks * 16 + (((lane >> 3) & 1) << 3);
                LDSM4(kb[p], K_o + (uint32_t)(row * QST + col) * 2);
            }
            #pragma unroll
            for (int nt = 0; nt < 8; nt++) {
                uint32_t b0 = kb[nt >> 1][(nt & 1) * 2];
                uint32_t b1 = kb[nt >> 1][(nt & 1) * 2 + 1];
                MMA_F16(sacc[nt], qa_reg[ks], b0, b1);
            }
        }

        if (kt == qt) {
            #pragma unroll
            for (int nt = 0; nt < 8; nt++)
                #pragma unroll
                for (int cc = 0; cc < 4; cc++) {
                    int rloc = rtile + (lane >> 2) + ((cc >= 2) ? 8 : 0);
                    int cloc = nt * 8 + (lane & 3) * 2 + (cc & 1);
                    if (cloc > rloc) sacc[nt][cc] = -1e30f;
                }
        }

        {
            float mx0 = -1e30f, mx1 = -1e30f;
            #pragma unroll
            for (int nt = 0; nt < 8; nt++) {
                mx0 = fmaxf(mx0, fmaxf(sacc[nt][0], sacc[nt][1]));
                mx1 = fmaxf(mx1, fmaxf(sacc[nt][2], sacc[nt][3]));
            }
            mx0 = fmaxf(mx0, __shfl_xor_sync(0xffffffffu, mx0, 1));
            mx0 = fmaxf(mx0, __shfl_xor_sync(0xffffffffu, mx0, 2));
            mx1 = fmaxf(mx1, __shfl_xor_sync(0xffffffffu, mx1, 1));
            mx1 = fmaxf(mx1, __shfl_xor_sync(0xffffffffu, mx1, 2));
            float mn0 = fmaxf(m_r[0], mx0);
            float mn1 = fmaxf(m_r[1], mx1);
            float sc0 = fast_exp2(m_r[0] - mn0);
            float sc1 = fast_exp2(m_r[1] - mn1);
            m_r[0] = mn0; m_r[1] = mn1;
            float sum0 = 0.f, sum1 = 0.f;
            #pragma unroll
            for (int nt = 0; nt < 8; nt++) {
                float p0 = fast_exp2(sacc[nt][0] - mn0);
                float p1 = fast_exp2(sacc[nt][1] - mn0);
                float p2 = fast_exp2(sacc[nt][2] - mn1);
                float p3 = fast_exp2(sacc[nt][3] - mn1);
                sacc[nt][0] = p0; sacc[nt][1] = p1;
                sacc[nt][2] = p2; sacc[nt][3] = p3;
                sum0 += p0 + p1; sum1 += p2 + p3;
                oacc[nt][0] *= sc0; oacc[nt][1] *= sc0;
                oacc[nt][2] *= sc1; oacc[nt][3] *= sc1;
            }
            l_r[0] = l_r[0] * sc0 + sum0;
            l_r[1] = l_r[1] * sc1 + sum1;
        }

        #pragma unroll
        for (int j = 0; j < 4; j++) {
            uint32_t vb[4][4];
            int tok_off = (lane & 7) + (((lane >> 3) & 1) << 3);
            int d_off   = ((lane >> 4) & 1) << 3;
            #pragma unroll
            for (int p = 0; p < 4; p++) {
                uint32_t off = (uint32_t)((j * 16 + tok_off) * QST + p * 16 + d_off) * 2;
                LDSM4T(vb[p], V_o + off);
            }
            uint32_t ah[4];
            #pragma unroll
            for (int qd = 0; qd < 4; qd++) {
                int nt = 2 * j + (qd >> 1);
                ah[qd] = pack_f16(sacc[nt][(qd & 1) * 2], sacc[nt][(qd & 1) * 2 + 1]);
            }
            #pragma unroll
            for (int nt = 0; nt < 8; nt++) {
                uint32_t b0 = vb[nt >> 1][(nt & 1) * 2];
                uint32_t b1 = vb[nt >> 1][(nt & 1) * 2 + 1];
                MMA_F16(oacc[nt], ah, b0, b1);
            }
        }
        st = (st == 2) ? 0 : st + 1;
    }

    l_r[0] += __shfl_xor_sync(0xffffffffu, l_r[0], 1);
    l_r[0] += __shfl_xor_sync(0xffffffffu, l_r[0], 2);
    l_r[1] += __shfl_xor_sync(0xffffffffu, l_r[1], 1);
    l_r[1] += __shfl_xor_sync(0xffffffffu, l_r[1], 2);
    float inv0 = 1.0f / l_r[0];
    float inv1 = 1.0f / l_r[1];
    int tok = qt * 64 + rtile + (lane >> 2);
    int colb = (kvh * 4 + hpair * 2 + hloc) * 64 + (lane & 3) * 2;
    #pragma unroll
    for (int nt = 0; nt < 8; nt++) {
        size_t o0 = (size_t)(b * SS + tok) * QDIM + colb + nt * 8;
        size_t o1 = o0 + (size_t)8 * QDIM;
        *(uint32_t*)&ao[o0] = pack_f16(oacc[nt][0] * inv0, oacc[nt][1] * inv0);
        *(uint32_t*)&ao[o1] = pack_f16(oacc[nt][2] * inv1, oacc[nt][3] * inv1);
    }
}

// ---------------------------------------------------------------------------
extern "C" void kernel_launch(void* const* d_in, const int* in_sizes, int n_in,
                              void* d_out, int out_size)
{
    (void)in_sizes; (void)n_in; (void)out_size;
    const float* hs  = (const float*)d_in[0];
    const int*   pos = (const int*)d_in[2];
    const float* Wq  = (const float*)d_in[3];
    const float* Wk  = (const float*)d_in[4];
    const float* Wv  = (const float*)d_in[5];
    const float* Wo  = (const float*)d_in[6];
    float* out = (float*)d_out;

    __half *hsb, *q, *k, *v, *ao, *w, *wo;
    float2* rope;
    cudaGetSymbolAddress((void**)&hsb, g_hs);
    cudaGetSymbolAddress((void**)&q,  g_q);
    cudaGetSymbolAddress((void**)&k,  g_k);
    cudaGetSymbolAddress((void**)&v,  g_v);
    cudaGetSymbolAddress((void**)&ao, g_ao);
    cudaGetSymbolAddress((void**)&w,  g_wqkvT);
    cudaGetSymbolAddress((void**)&wo, g_woT);
    cudaGetSymbolAddress((void**)&rope, g_rope);

    const int M = MTOT;
    cudaFuncSetAttribute(hmma_gemm_c,   cudaFuncAttributeMaxDynamicSharedMemorySize, GEMM_SMEM);
    cudaFuncSetAttribute(hmma_gemm_qkv, cudaFuncAttributeMaxDynamicSharedMemorySize, GEMM_SMEM);
    cudaFuncSetAttribute(attn_hmma,     cudaFuncAttributeMaxDynamicSharedMemorySize, ATT_SMEM);

    prep_all<<<PREP_A + PREP_B + PREP_C + PREP_D, 256>>>(hs, Wq, Wk, Wv, Wo, hsb, w, wo, rope); // 1
    hmma_gemm_qkv<<<dim3(QKVN / 128, M / 128), 256, GEMM_SMEM>>>(hsb, w, pos, rope, q, k, v);   // 2
    attn_hmma<<<dim3(SS / 64, 2 * NKV, BB), 256, ATT_SMEM>>>(q, k, v, ao);                      // 3
    hmma_gemm_c<<<dim3(DOUT / 128, M / 128), 256, GEMM_SMEM>>>(ao, wo, out, M, DOUT, QDIM);     // 4
}